// round 4
// baseline (speedup 1.0000x reference)
#include <cuda_runtime.h>
#include <math.h>

#define NN   32768
#define TT   20
#define EMBD 64
#define HD   128
#define NE   1048576   // NN * 32

// ---------------- scratch (static device globals; no allocations) ----------------
__device__ float g_u   [NN * HD];
__device__ float g_c   [NN * HD];
__device__ float g_u2  [NN * HD];
__device__ float g_c2  [NN * HD];
__device__ float g_aggc[NN * HD];
__device__ float g_aggu[NN * HD];
__device__ float g_cntd[NN];
__device__ float g_cnts[NN];

__device__ __forceinline__ float sigmoidf_(float x) { return 1.0f / (1.0f + expf(-x)); }

#define DOT4(acc, A, B) (acc) += (A).x*(B).x + (A).y*(B).y + (A).z*(B).z + (A).w*(B).w

// ---------------- zeroing ----------------
__global__ void zero_aggs_kernel(int also_counts) {
    int i = blockIdx.x * blockDim.x + threadIdx.x;
    int stride = gridDim.x * blockDim.x;
    for (int k = i; k < NN * HD; k += stride) { g_aggc[k] = 0.f; g_aggu[k] = 0.f; }
    if (also_counts) {
        for (int k = i; k < NN; k += stride) { g_cntd[k] = 0.f; g_cnts[k] = 0.f; }
    }
}

// ---------------- edge degree counts ----------------
__global__ void count_kernel(const int* __restrict__ src, const int* __restrict__ dst) {
    int e = blockIdx.x * blockDim.x + threadIdx.x;
    if (e < NE) {
        atomicAdd(&g_cntd[dst[e]], 1.0f);
        atomicAdd(&g_cnts[src[e]], 1.0f);
    }
}

// ---------------- LSTM: one block = 32 users, 256 threads ----------------
// thread t: user u = t/8, slot s = t%8, owns hidden indices m = s + 8*i (i<16).
__global__ __launch_bounds__(256) void lstm_kernel(
    const float* __restrict__ x_user,
    const float* __restrict__ W_ih, const float* __restrict__ W_hh,
    const float* __restrict__ b_ih, const float* __restrict__ b_hh)
{
    __shared__ float h_sh[32 * 132];   // row stride 132 floats (33 float4) -> bank-safe
    __shared__ float x_sh[32 * 68];    // row stride 68 floats  (17 float4)
    __shared__ float bsum[512];

    int tid = threadIdx.x;
    int u   = tid >> 3;
    int s   = tid & 7;
    int u0  = blockIdx.x * 32;

    bsum[tid]       = b_ih[tid]       + b_hh[tid];
    bsum[tid + 256] = b_ih[tid + 256] + b_hh[tid + 256];
    for (int i = tid; i < 32 * 132; i += 256) h_sh[i] = 0.f;

    float c_reg[16];
#pragma unroll
    for (int i = 0; i < 16; i++) c_reg[i] = 0.f;

    const float4* Wih4 = (const float4*)W_ih;   // [512][16]
    const float4* Whh4 = (const float4*)W_hh;   // [512][32]
    const float4* xg4  = (const float4*)x_user; // [(n*T+t)][16]
    float4*       xs4  = (float4*)x_sh;
    const float4* hs4  = (const float4*)h_sh;

    for (int t = 0; t < TT; t++) {
        // stage x_t for 32 users (512 float4, 2 per thread)
        {
            int i0 = tid * 2;
#pragma unroll
            for (int r = 0; r < 2; r++) {
                int idx = i0 + r;
                int uu = idx >> 4, k4 = idx & 15;
                xs4[uu * 17 + k4] = xg4[((u0 + uu) * TT + t) * 16 + k4];
            }
        }
        __syncthreads();  // x ready; previous step's h writes visible

        float acc_i[16], acc_f[16], acc_g[16], acc_o[16];
#pragma unroll
        for (int i = 0; i < 16; i++) {
            int m = s + 8 * i;
            acc_i[i] = bsum[m];
            acc_f[i] = bsum[128 + m];
            acc_g[i] = bsum[256 + m];
            acc_o[i] = bsum[384 + m];
        }

        // input contribution: k over EMB (16 float4)
#pragma unroll 1
        for (int k4 = 0; k4 < 16; k4++) {
            float4 xv = xs4[u * 17 + k4];
#pragma unroll
            for (int i = 0; i < 16; i++) {
                int m = s + 8 * i;
                float4 wv;
                wv = Wih4[(m)       * 16 + k4]; DOT4(acc_i[i], wv, xv);
                wv = Wih4[(128 + m) * 16 + k4]; DOT4(acc_f[i], wv, xv);
                wv = Wih4[(256 + m) * 16 + k4]; DOT4(acc_g[i], wv, xv);
                wv = Wih4[(384 + m) * 16 + k4]; DOT4(acc_o[i], wv, xv);
            }
        }
        // recurrent contribution: k over H (32 float4)
#pragma unroll 1
        for (int k4 = 0; k4 < 32; k4++) {
            float4 hv = hs4[u * 33 + k4];
#pragma unroll
            for (int i = 0; i < 16; i++) {
                int m = s + 8 * i;
                float4 wv;
                wv = Whh4[(m)       * 32 + k4]; DOT4(acc_i[i], wv, hv);
                wv = Whh4[(128 + m) * 32 + k4]; DOT4(acc_f[i], wv, hv);
                wv = Whh4[(256 + m) * 32 + k4]; DOT4(acc_g[i], wv, hv);
                wv = Whh4[(384 + m) * 32 + k4]; DOT4(acc_o[i], wv, hv);
            }
        }
        __syncthreads();  // all reads of h_sh / x_sh complete

#pragma unroll
        for (int i = 0; i < 16; i++) {
            int m = s + 8 * i;
            float ig = sigmoidf_(acc_i[i]);
            float fg = sigmoidf_(acc_f[i]);
            float gg = tanhf(acc_g[i]);
            float og = sigmoidf_(acc_o[i]);
            float cc = fg * c_reg[i] + ig * gg;
            c_reg[i] = cc;
            h_sh[u * 132 + m] = og * tanhf(cc);
        }
    }
    __syncthreads();
#pragma unroll
    for (int i = 0; i < 16; i++) {
        int m = s + 8 * i;
        g_u[(u0 + u) * HD + m] = h_sh[u * 132 + m];
    }
}

// ---------------- content linear: c = x_content @ Wc^T + bc ----------------
__global__ __launch_bounds__(256) void content_kernel(
    const float* __restrict__ xc, const float* __restrict__ Wc, const float* __restrict__ bc)
{
    __shared__ float4 Wc4s[128 * 17];  // 128 rows x 16 f4 (pad 17)
    __shared__ float4 xs[32 * 17];
    int tid = threadIdx.x;
    int n0 = blockIdx.x * 32;

    for (int idx = tid; idx < 128 * 16; idx += 256) {
        int r = idx >> 4, col = idx & 15;
        Wc4s[r * 17 + col] = ((const float4*)Wc)[idx];
    }
    for (int idx = tid; idx < 32 * 16; idx += 256) {
        int n = idx >> 4, k4 = idx & 15;
        xs[n * 17 + k4] = ((const float4*)xc)[(n0 + n) * 16 + k4];
    }
    __syncthreads();

    int n = tid >> 3, q = tid & 7;
    float acc[16];
#pragma unroll
    for (int i = 0; i < 16; i++) acc[i] = bc[q + 8 * i];
#pragma unroll 1
    for (int k4 = 0; k4 < 16; k4++) {
        float4 xv = xs[n * 17 + k4];
#pragma unroll
        for (int i = 0; i < 16; i++) {
            float4 wv = Wc4s[(q + 8 * i) * 17 + k4];
            DOT4(acc[i], wv, xv);
        }
    }
#pragma unroll
    for (int i = 0; i < 16; i++)
        g_c[(n0 + n) * HD + q + 8 * i] = acc[i];  // no activation
}

// ---------------- edge scatter: one warp per edge ----------------
// layer==0: messages from (g_u, g_c);  layer==1: from (g_u2, g_c2)
__global__ __launch_bounds__(256) void scatter_kernel(
    const int* __restrict__ src, const int* __restrict__ dst, int layer)
{
    int e = blockIdx.x * 8 + (threadIdx.x >> 5);
    int lane = threadIdx.x & 31;
    if (e >= NE) return;
    const float* u = (layer == 0) ? g_u : g_u2;
    const float* c = (layer == 0) ? g_c : g_c2;
    int sidx = src[e], didx = dst[e];
    float4 uv = ((const float4*)u)[sidx * 32 + lane];
    float4 cv = ((const float4*)c)[didx * 32 + lane];
    float* ac = g_aggc + didx * HD + lane * 4;
    atomicAdd(ac + 0, uv.x); atomicAdd(ac + 1, uv.y);
    atomicAdd(ac + 2, uv.z); atomicAdd(ac + 3, uv.w);
    float* au = g_aggu + sidx * HD + lane * 4;
    atomicAdd(au + 0, cv.x); atomicAdd(au + 1, cv.y);
    atomicAdd(au + 2, cv.z); atomicAdd(au + 3, cv.w);
}

// ---------------- SAGE combine: out = relu(mean @ Wl^T + bl + self @ Wr^T) ----------------
// mode 0: aggc/cntd, self=g_c  -> g_c2     mode 1: aggu/cnts, self=g_u  -> g_u2
// mode 2: aggc/cntd, self=g_c2 -> g_c      mode 3: aggu/cnts, self=g_u2 -> g_u
#define COMBINE_SMEM ((2 * 128 * 33 + 2 * 32 * 33) * 16)
__global__ __launch_bounds__(256) void combine_kernel(
    const float* __restrict__ Wl, const float* __restrict__ bl,
    const float* __restrict__ Wr, int mode)
{
    extern __shared__ float sm[];
    float4* Wl4 = (float4*)sm;           // 128 x 33
    float4* Wr4 = Wl4 + 128 * 33;
    float4* xm4 = Wr4 + 128 * 33;        // 32 x 33
    float4* xs4 = xm4 + 32 * 33;

    const float* agg; const float* cnt; const float* selfx; float* outp;
    if      (mode == 0) { agg = g_aggc; cnt = g_cntd; selfx = g_c;  outp = g_c2; }
    else if (mode == 1) { agg = g_aggu; cnt = g_cnts; selfx = g_u;  outp = g_u2; }
    else if (mode == 2) { agg = g_aggc; cnt = g_cntd; selfx = g_c2; outp = g_c;  }
    else                { agg = g_aggu; cnt = g_cnts; selfx = g_u2; outp = g_u;  }

    int tid = threadIdx.x;
    int n0 = blockIdx.x * 32;

    for (int idx = tid; idx < 128 * 32; idx += 256) {
        int r = idx >> 5, col = idx & 31;
        Wl4[r * 33 + col] = ((const float4*)Wl)[idx];
        Wr4[r * 33 + col] = ((const float4*)Wr)[idx];
    }
    for (int idx = tid; idx < 32 * 32; idx += 256) {
        int n = idx >> 5, k4 = idx & 31;
        float inv = 1.0f / fmaxf(cnt[n0 + n], 1.0f);
        float4 a = ((const float4*)agg)[(n0 + n) * 32 + k4];
        a.x *= inv; a.y *= inv; a.z *= inv; a.w *= inv;
        xm4[n * 33 + k4] = a;
        xs4[n * 33 + k4] = ((const float4*)selfx)[(n0 + n) * 32 + k4];
    }
    __syncthreads();

    int n = tid >> 3, q = tid & 7;
    float acc[16];
#pragma unroll
    for (int i = 0; i < 16; i++) acc[i] = bl[q + 8 * i];
#pragma unroll 1
    for (int k4 = 0; k4 < 32; k4++) {
        float4 xm = xm4[n * 33 + k4];
        float4 xv = xs4[n * 33 + k4];
#pragma unroll
        for (int i = 0; i < 16; i++) {
            int j = q + 8 * i;
            float4 wlv = Wl4[j * 33 + k4];
            float4 wrv = Wr4[j * 33 + k4];
            DOT4(acc[i], wlv, xm);
            DOT4(acc[i], wrv, xv);
        }
    }
#pragma unroll
    for (int i = 0; i < 16; i++)
        outp[(n0 + n) * HD + q + 8 * i] = fmaxf(acc[i], 0.f);
}

// ---------------- classifier: sigmoid(relu([u,c] @ W1^T + b1) @ W2^T + b2) ----------------
#define CLS_SMEM ((128 * 65 + 32 * 65) * 16 + 512)
__global__ __launch_bounds__(256) void classifier_kernel(
    const float* __restrict__ W1, const float* __restrict__ b1,
    const float* __restrict__ W2, const float* __restrict__ b2,
    float* __restrict__ out)
{
    extern __shared__ float sm[];
    float4* W14 = (float4*)sm;        // 128 rows x 65 (64 f4 data + pad)
    float4* xc4 = W14 + 128 * 65;     // 32 nodes x 65
    float*  W2s = (float*)(xc4 + 32 * 65);

    int tid = threadIdx.x;
    int n0 = blockIdx.x * 32;

    for (int idx = tid; idx < 128 * 64; idx += 256) {
        int r = idx >> 6, col = idx & 63;
        W14[r * 65 + col] = ((const float4*)W1)[idx];
    }
    for (int idx = tid; idx < 32 * 64; idx += 256) {
        int n = idx >> 6, k4 = idx & 63;
        float4 v = (k4 < 32) ? ((const float4*)g_u)[(n0 + n) * 32 + k4]
                             : ((const float4*)g_c)[(n0 + n) * 32 + (k4 - 32)];
        xc4[n * 65 + k4] = v;
    }
    if (tid < 128) W2s[tid] = W2[tid];
    __syncthreads();

    int n = tid >> 3, q = tid & 7;
    float acc[16];
#pragma unroll
    for (int i = 0; i < 16; i++) acc[i] = b1[q + 8 * i];
#pragma unroll 1
    for (int k4 = 0; k4 < 64; k4++) {
        float4 xv = xc4[n * 65 + k4];
#pragma unroll
        for (int i = 0; i < 16; i++) {
            float4 wv = W14[(q + 8 * i) * 65 + k4];
            DOT4(acc[i], wv, xv);
        }
    }
    float p = 0.f;
#pragma unroll
    for (int i = 0; i < 16; i++) {
        float h = fmaxf(acc[i], 0.f);
        p += h * W2s[q + 8 * i];
    }
    p += __shfl_xor_sync(0xffffffffu, p, 1);
    p += __shfl_xor_sync(0xffffffffu, p, 2);
    p += __shfl_xor_sync(0xffffffffu, p, 4);
    if (q == 0) out[n0 + n] = sigmoidf_(p + b2[0]);
}

// ---------------- launch ----------------
extern "C" void kernel_launch(void* const* d_in, const int* in_sizes, int n_in,
                              void* d_out, int out_size)
{
    const float* x_user    = (const float*)d_in[0];
    const float* x_content = (const float*)d_in[1];
    const int*   edge      = (const int*)  d_in[2];
    const float* W_ih      = (const float*)d_in[3];
    const float* W_hh      = (const float*)d_in[4];
    const float* b_ih      = (const float*)d_in[5];
    const float* b_hh      = (const float*)d_in[6];
    const float* Wc        = (const float*)d_in[7];
    const float* bc        = (const float*)d_in[8];
    const float* Wl0       = (const float*)d_in[9];
    const float* bl0       = (const float*)d_in[10];
    const float* Wr0       = (const float*)d_in[11];
    const float* Wl1       = (const float*)d_in[12];
    const float* bl1       = (const float*)d_in[13];
    const float* Wr1       = (const float*)d_in[14];
    const float* W1        = (const float*)d_in[15];
    const float* b1        = (const float*)d_in[16];
    const float* W2        = (const float*)d_in[17];
    const float* b2        = (const float*)d_in[18];
    float* out = (float*)d_out;

    const int* src = edge;
    const int* dst = edge + NE;

    cudaFuncSetAttribute(combine_kernel,    cudaFuncAttributeMaxDynamicSharedMemorySize, COMBINE_SMEM);
    cudaFuncSetAttribute(classifier_kernel, cudaFuncAttributeMaxDynamicSharedMemorySize, CLS_SMEM);

    // zero aggregation buffers + counts
    zero_aggs_kernel<<<4096, 256>>>(1);
    count_kernel<<<NE / 256, 256>>>(src, dst);

    // node features
    lstm_kernel<<<NN / 32, 256>>>(x_user, W_ih, W_hh, b_ih, b_hh);      // -> g_u
    content_kernel<<<NN / 32, 256>>>(x_content, Wc, bc);                // -> g_c

    // SAGE layer 0
    scatter_kernel<<<NE / 8, 256>>>(src, dst, 0);                       // aggc += u[src]@dst, aggu += c[dst]@src
    combine_kernel<<<NN / 32, 256, COMBINE_SMEM>>>(Wl0, bl0, Wr0, 0);   // -> g_c2
    combine_kernel<<<NN / 32, 256, COMBINE_SMEM>>>(Wl0, bl0, Wr0, 1);   // -> g_u2

    // SAGE layer 1
    zero_aggs_kernel<<<4096, 256>>>(0);
    scatter_kernel<<<NE / 8, 256>>>(src, dst, 1);
    combine_kernel<<<NN / 32, 256, COMBINE_SMEM>>>(Wl1, bl1, Wr1, 2);   // -> g_c
    combine_kernel<<<NN / 32, 256, COMBINE_SMEM>>>(Wl1, bl1, Wr1, 3);   // -> g_u

    // classifier
    classifier_kernel<<<NN / 32, 256, CLS_SMEM>>>(W1, b1, W2, b2, out);
}

// round 7
// speedup vs baseline: 8.2056x; 8.2056x over previous
#include <cuda_runtime.h>
#include <math.h>

#define NN   32768
#define TT   20
#define EMBD 64
#define HD   128
#define NE   1048576   // NN * 32

// ---------------- scratch (static device globals; no allocations) ----------------
__device__ float g_u   [NN * HD];
__device__ float g_c   [NN * HD];
__device__ float g_u2  [NN * HD];
__device__ float g_c2  [NN * HD];
__device__ float g_aggc[NN * HD];
__device__ float g_aggu[NN * HD];
__device__ float g_cntd[NN];
__device__ float g_cnts[NN];

__device__ __forceinline__ float sigmoidf_(float x) { return 1.0f / (1.0f + expf(-x)); }

#define DOT4(acc, A, B) (acc) += (A).x*(B).x + (A).y*(B).y + (A).z*(B).z + (A).w*(B).w

// ---------------- zeroing ----------------
__global__ void zero_aggs_kernel(int also_counts) {
    int i = blockIdx.x * blockDim.x + threadIdx.x;
    int stride = gridDim.x * blockDim.x;
    for (int k = i; k < NN * HD; k += stride) { g_aggc[k] = 0.f; g_aggu[k] = 0.f; }
    if (also_counts) {
        for (int k = i; k < NN; k += stride) { g_cntd[k] = 0.f; g_cnts[k] = 0.f; }
    }
}

// ---------------- edge degree counts ----------------
__global__ void count_kernel(const int* __restrict__ src, const int* __restrict__ dst) {
    int e = blockIdx.x * blockDim.x + threadIdx.x;
    if (e < NE) {
        atomicAdd(&g_cntd[dst[e]], 1.0f);
        atomicAdd(&g_cnts[src[e]], 1.0f);
    }
}

// =====================================================================
// LSTM: smem-tiled register-blocked GEMM, software-pipelined weights.
//  Block: 512 threads, 64 users. Thread: 8 gate-rows x 8 users.
//  gg = tid & 63 -> gate rows gg + 64*j (j=0..7); ug = tid>>6 -> users ug*8..+7.
//  Thread owns full (i,f,g,o) for hidden units m = gg and m = gg+64.
//  Weight k-tiles (512x16) double-buffered in smem, prefetched one tile
//  ahead across the 12-tile ring (weights time-invariant -> tile 0 of
//  step t+1 is fetched during tile 11 of step t).
// =====================================================================
#define LSTM_SMEM ((2*512*17 + 64*68 + 64*129 + 512) * 4)

template<int XSTR>
__device__ __forceinline__ void lstm_gemm_tile(
    const float* __restrict__ xp,   // thread's user block base (+kbase)
    const float* __restrict__ wp,   // Wsh[cur] + gg*17
    float acc[8][8])
{
#pragma unroll
    for (int kk = 0; kk < 16; kk++) {
        float xv[8];
#pragma unroll
        for (int r = 0; r < 8; r++) xv[r] = xp[r * XSTR + kk];   // warp-broadcast
#pragma unroll
        for (int j = 0; j < 8; j++) {
            float wv = wp[j * 64 * 17 + kk];                     // conflict-free (stride 17)
#pragma unroll
            for (int r = 0; r < 8; r++) acc[j][r] = fmaf(wv, xv[r], acc[j][r]);
        }
    }
}

__global__ __launch_bounds__(512, 1) void lstm_kernel(
    const float* __restrict__ x_user,
    const float* __restrict__ W_ih, const float* __restrict__ W_hh,
    const float* __restrict__ b_ih, const float* __restrict__ b_hh)
{
    extern __shared__ float sm[];
    float* Wsh  = sm;                   // [2][512][17]
    float* xs   = Wsh + 2 * 512 * 17;   // [64][68]  (x_t staged, float4-aligned rows)
    float* h_sh = xs + 64 * 68;         // [64][129]
    float* bsum = h_sh + 64 * 129;      // [512]

    int tid = threadIdx.x;
    int gg  = tid & 63;
    int ug  = tid >> 6;
    int u0  = blockIdx.x * 64;

    bsum[tid] = b_ih[tid] + b_hh[tid];
    for (int i = tid; i < 64 * 129; i += 512) h_sh[i] = 0.f;

    float c0[8], c1[8];
#pragma unroll
    for (int r = 0; r < 8; r++) { c0[r] = 0.f; c1[r] = 0.f; }

    // ---- prologue: stage xs for t=0, weight tile 0 into buffer 0 ----
#pragma unroll
    for (int i = 0; i < 2; i++) {
        int idx = tid + i * 512;
        int u = idx >> 4, c = idx & 15;
        float4 v = ((const float4*)x_user)[((u0 + u) * TT + 0) * 16 + c];
        *(float4*)(xs + u * 68 + c * 4) = v;
    }
    {
        const float4* wsrc = (const float4*)(W_ih + tid * 64);   // tile 0: k0 = 0
        float* Wn = Wsh + tid * 17;
#pragma unroll
        for (int c = 0; c < 4; c++) {
            float4 w = wsrc[c];
            Wn[c * 4 + 0] = w.x; Wn[c * 4 + 1] = w.y;
            Wn[c * 4 + 2] = w.z; Wn[c * 4 + 3] = w.w;
        }
    }
    __syncthreads();

    float acc[8][8];
    for (int t = 0; t < TT; t++) {
        // init accumulators with fused bias
#pragma unroll
        for (int j = 0; j < 8; j++) {
            float b = bsum[gg + 64 * j];
#pragma unroll
            for (int r = 0; r < 8; r++) acc[j][r] = b;
        }

#pragma unroll 1
        for (int tile = 0; tile < 12; tile++) {
            int cur = tile & 1;
            bool last    = (t == TT - 1) && (tile == 11);
            bool stage_x = (tile == 11) && (t < TT - 1);

            // prefetch next weight tile into registers (ring: 11 -> 0)
            float4 wreg[4];
            if (!last) {
                int nt = (tile + 1) % 12;
                const float* wsrc = (nt < 4) ? (W_ih + tid * 64 + nt * 16)
                                             : (W_hh + tid * 128 + nt * 16 - 64);
#pragma unroll
                for (int c = 0; c < 4; c++) wreg[c] = ((const float4*)wsrc)[c];
            }
            // prefetch next step's x
            float4 xreg[2];
            if (stage_x) {
#pragma unroll
                for (int i = 0; i < 2; i++) {
                    int idx = tid + i * 512;
                    int u = idx >> 4, c = idx & 15;
                    xreg[i] = ((const float4*)x_user)[((u0 + u) * TT + t + 1) * 16 + c];
                }
            }

            // compute current tile
            const float* wp = Wsh + cur * 512 * 17 + gg * 17;
            if (tile < 4) {
                const float* xp = xs + (ug * 8) * 68 + tile * 16;
                lstm_gemm_tile<68>(xp, wp, acc);
            } else {
                const float* xp = h_sh + (ug * 8) * 129 + tile * 16 - 64;
                lstm_gemm_tile<129>(xp, wp, acc);
            }

            // drain prefetches into the other buffer / xs
            if (!last) {
                float* Wn = Wsh + (cur ^ 1) * 512 * 17 + tid * 17;
#pragma unroll
                for (int c = 0; c < 4; c++) {
                    Wn[c * 4 + 0] = wreg[c].x; Wn[c * 4 + 1] = wreg[c].y;
                    Wn[c * 4 + 2] = wreg[c].z; Wn[c * 4 + 3] = wreg[c].w;
                }
            }
            if (stage_x) {
#pragma unroll
                for (int i = 0; i < 2; i++) {
                    int idx = tid + i * 512;
                    int u = idx >> 4, c = idx & 15;
                    *(float4*)(xs + u * 68 + c * 4) = xreg[i];
                }
            }
            __syncthreads();
        }

        // cell update: thread owns (i,f,g,o) for m = gg (j even base) and m = gg+64
        bool final_t = (t == TT - 1);
#pragma unroll
        for (int r = 0; r < 8; r++) {
            int u = ug * 8 + r;
            {
                float ig = sigmoidf_(acc[0][r]);
                float fg = sigmoidf_(acc[2][r]);
                float g_ = tanhf(acc[4][r]);
                float og = sigmoidf_(acc[6][r]);
                float cc = fg * c0[r] + ig * g_;
                c0[r] = cc;
                float hv = og * tanhf(cc);
                h_sh[u * 129 + gg] = hv;
                if (final_t) g_u[(u0 + u) * HD + gg] = hv;
            }
            {
                float ig = sigmoidf_(acc[1][r]);
                float fg = sigmoidf_(acc[3][r]);
                float g_ = tanhf(acc[5][r]);
                float og = sigmoidf_(acc[7][r]);
                float cc = fg * c1[r] + ig * g_;
                c1[r] = cc;
                float hv = og * tanhf(cc);
                h_sh[u * 129 + gg + 64] = hv;
                if (final_t) g_u[(u0 + u) * HD + gg + 64] = hv;
            }
        }
    }
}

// ---------------- content linear: c = x_content @ Wc^T + bc ----------------
__global__ __launch_bounds__(256) void content_kernel(
    const float* __restrict__ xc, const float* __restrict__ Wc, const float* __restrict__ bc)
{
    __shared__ float4 Wc4s[128 * 17];  // 128 rows x 16 f4 (pad 17)
    __shared__ float4 xs[32 * 17];
    int tid = threadIdx.x;
    int n0 = blockIdx.x * 32;

    for (int idx = tid; idx < 128 * 16; idx += 256) {
        int r = idx >> 4, col = idx & 15;
        Wc4s[r * 17 + col] = ((const float4*)Wc)[idx];
    }
    for (int idx = tid; idx < 32 * 16; idx += 256) {
        int n = idx >> 4, k4 = idx & 15;
        xs[n * 17 + k4] = ((const float4*)xc)[(n0 + n) * 16 + k4];
    }
    __syncthreads();

    int n = tid >> 3, q = tid & 7;
    float acc[16];
#pragma unroll
    for (int i = 0; i < 16; i++) acc[i] = bc[q + 8 * i];
#pragma unroll 1
    for (int k4 = 0; k4 < 16; k4++) {
        float4 xv = xs[n * 17 + k4];
#pragma unroll
        for (int i = 0; i < 16; i++) {
            float4 wv = Wc4s[(q + 8 * i) * 17 + k4];
            DOT4(acc[i], wv, xv);
        }
    }
#pragma unroll
    for (int i = 0; i < 16; i++)
        g_c[(n0 + n) * HD + q + 8 * i] = acc[i];  // no activation
}

// ---------------- edge scatter: one warp per edge ----------------
__global__ __launch_bounds__(256) void scatter_kernel(
    const int* __restrict__ src, const int* __restrict__ dst, int layer)
{
    int e = blockIdx.x * 8 + (threadIdx.x >> 5);
    int lane = threadIdx.x & 31;
    if (e >= NE) return;
    const float* u = (layer == 0) ? g_u : g_u2;
    const float* c = (layer == 0) ? g_c : g_c2;
    int sidx = src[e], didx = dst[e];
    float4 uv = ((const float4*)u)[sidx * 32 + lane];
    float4 cv = ((const float4*)c)[didx * 32 + lane];
    float* ac = g_aggc + didx * HD + lane * 4;
    atomicAdd(ac + 0, uv.x); atomicAdd(ac + 1, uv.y);
    atomicAdd(ac + 2, uv.z); atomicAdd(ac + 3, uv.w);
    float* au = g_aggu + sidx * HD + lane * 4;
    atomicAdd(au + 0, cv.x); atomicAdd(au + 1, cv.y);
    atomicAdd(au + 2, cv.z); atomicAdd(au + 3, cv.w);
}

// ---------------- SAGE combine: out = relu(mean @ Wl^T + bl + self @ Wr^T) ----------------
#define COMBINE_SMEM ((2 * 128 * 33 + 2 * 32 * 33) * 16)
__global__ __launch_bounds__(256) void combine_kernel(
    const float* __restrict__ Wl, const float* __restrict__ bl,
    const float* __restrict__ Wr, int mode)
{
    extern __shared__ float smc[];
    float4* Wl4 = (float4*)smc;          // 128 x 33
    float4* Wr4 = Wl4 + 128 * 33;
    float4* xm4 = Wr4 + 128 * 33;        // 32 x 33
    float4* xs4 = xm4 + 32 * 33;

    const float* agg; const float* cnt; const float* selfx; float* outp;
    if      (mode == 0) { agg = g_aggc; cnt = g_cntd; selfx = g_c;  outp = g_c2; }
    else if (mode == 1) { agg = g_aggu; cnt = g_cnts; selfx = g_u;  outp = g_u2; }
    else if (mode == 2) { agg = g_aggc; cnt = g_cntd; selfx = g_c2; outp = g_c;  }
    else                { agg = g_aggu; cnt = g_cnts; selfx = g_u2; outp = g_u;  }

    int tid = threadIdx.x;
    int n0 = blockIdx.x * 32;

    for (int idx = tid; idx < 128 * 32; idx += 256) {
        int r = idx >> 5, col = idx & 31;
        Wl4[r * 33 + col] = ((const float4*)Wl)[idx];
        Wr4[r * 33 + col] = ((const float4*)Wr)[idx];
    }
    for (int idx = tid; idx < 32 * 32; idx += 256) {
        int n = idx >> 5, k4 = idx & 31;
        float inv = 1.0f / fmaxf(cnt[n0 + n], 1.0f);
        float4 a = ((const float4*)agg)[(n0 + n) * 32 + k4];
        a.x *= inv; a.y *= inv; a.z *= inv; a.w *= inv;
        xm4[n * 33 + k4] = a;
        xs4[n * 33 + k4] = ((const float4*)selfx)[(n0 + n) * 32 + k4];
    }
    __syncthreads();

    int n = tid >> 3, q = tid & 7;
    float acc[16];
#pragma unroll
    for (int i = 0; i < 16; i++) acc[i] = bl[q + 8 * i];
#pragma unroll 1
    for (int k4 = 0; k4 < 32; k4++) {
        float4 xm = xm4[n * 33 + k4];
        float4 xv = xs4[n * 33 + k4];
#pragma unroll
        for (int i = 0; i < 16; i++) {
            int j = q + 8 * i;
            float4 wlv = Wl4[j * 33 + k4];
            float4 wrv = Wr4[j * 33 + k4];
            DOT4(acc[i], wlv, xm);
            DOT4(acc[i], wrv, xv);
        }
    }
#pragma unroll
    for (int i = 0; i < 16; i++)
        outp[(n0 + n) * HD + q + 8 * i] = fmaxf(acc[i], 0.f);
}

// ---------------- classifier: sigmoid(relu([u,c] @ W1^T + b1) @ W2^T + b2) ----------------
#define CLS_SMEM ((128 * 65 + 32 * 65) * 16 + 512)
__global__ __launch_bounds__(256) void classifier_kernel(
    const float* __restrict__ W1, const float* __restrict__ b1,
    const float* __restrict__ W2, const float* __restrict__ b2,
    float* __restrict__ out)
{
    extern __shared__ float smk[];
    float4* W14 = (float4*)smk;       // 128 rows x 65 (64 f4 data + pad)
    float4* xc4 = W14 + 128 * 65;     // 32 nodes x 65
    float*  W2s = (float*)(xc4 + 32 * 65);

    int tid = threadIdx.x;
    int n0 = blockIdx.x * 32;

    for (int idx = tid; idx < 128 * 64; idx += 256) {
        int r = idx >> 6, col = idx & 63;
        W14[r * 65 + col] = ((const float4*)W1)[idx];
    }
    for (int idx = tid; idx < 32 * 64; idx += 256) {
        int n = idx >> 6, k4 = idx & 63;
        float4 v = (k4 < 32) ? ((const float4*)g_u)[(n0 + n) * 32 + k4]
                             : ((const float4*)g_c)[(n0 + n) * 32 + (k4 - 32)];
        xc4[n * 65 + k4] = v;
    }
    if (tid < 128) W2s[tid] = W2[tid];
    __syncthreads();

    int n = tid >> 3, q = tid & 7;
    float acc[16];
#pragma unroll
    for (int i = 0; i < 16; i++) acc[i] = b1[q + 8 * i];
#pragma unroll 1
    for (int k4 = 0; k4 < 64; k4++) {
        float4 xv = xc4[n * 65 + k4];
#pragma unroll
        for (int i = 0; i < 16; i++) {
            float4 wv = W14[(q + 8 * i) * 65 + k4];
            DOT4(acc[i], wv, xv);
        }
    }
    float p = 0.f;
#pragma unroll
    for (int i = 0; i < 16; i++) {
        float h = fmaxf(acc[i], 0.f);
        p += h * W2s[q + 8 * i];
    }
    p += __shfl_xor_sync(0xffffffffu, p, 1);
    p += __shfl_xor_sync(0xffffffffu, p, 2);
    p += __shfl_xor_sync(0xffffffffu, p, 4);
    if (q == 0) out[n0 + n] = sigmoidf_(p + b2[0]);
}

// ---------------- launch ----------------
extern "C" void kernel_launch(void* const* d_in, const int* in_sizes, int n_in,
                              void* d_out, int out_size)
{
    const float* x_user    = (const float*)d_in[0];
    const float* x_content = (const float*)d_in[1];
    const int*   edge      = (const int*)  d_in[2];
    const float* W_ih      = (const float*)d_in[3];
    const float* W_hh      = (const float*)d_in[4];
    const float* b_ih      = (const float*)d_in[5];
    const float* b_hh      = (const float*)d_in[6];
    const float* Wc        = (const float*)d_in[7];
    const float* bc        = (const float*)d_in[8];
    const float* Wl0       = (const float*)d_in[9];
    const float* bl0       = (const float*)d_in[10];
    const float* Wr0       = (const float*)d_in[11];
    const float* Wl1       = (const float*)d_in[12];
    const float* bl1       = (const float*)d_in[13];
    const float* Wr1       = (const float*)d_in[14];
    const float* W1        = (const float*)d_in[15];
    const float* b1        = (const float*)d_in[16];
    const float* W2        = (const float*)d_in[17];
    const float* b2        = (const float*)d_in[18];
    float* out = (float*)d_out;

    const int* src = edge;
    const int* dst = edge + NE;

    cudaFuncSetAttribute(lstm_kernel,       cudaFuncAttributeMaxDynamicSharedMemorySize, LSTM_SMEM);
    cudaFuncSetAttribute(combine_kernel,    cudaFuncAttributeMaxDynamicSharedMemorySize, COMBINE_SMEM);
    cudaFuncSetAttribute(classifier_kernel, cudaFuncAttributeMaxDynamicSharedMemorySize, CLS_SMEM);

    // zero aggregation buffers + counts
    zero_aggs_kernel<<<4096, 256>>>(1);
    count_kernel<<<NE / 256, 256>>>(src, dst);

    // node features
    lstm_kernel<<<NN / 64, 512, LSTM_SMEM>>>(x_user, W_ih, W_hh, b_ih, b_hh);  // -> g_u
    content_kernel<<<NN / 32, 256>>>(x_content, Wc, bc);                       // -> g_c

    // SAGE layer 0
    scatter_kernel<<<NE / 8, 256>>>(src, dst, 0);
    combine_kernel<<<NN / 32, 256, COMBINE_SMEM>>>(Wl0, bl0, Wr0, 0);   // -> g_c2
    combine_kernel<<<NN / 32, 256, COMBINE_SMEM>>>(Wl0, bl0, Wr0, 1);   // -> g_u2

    // SAGE layer 1
    zero_aggs_kernel<<<4096, 256>>>(0);
    scatter_kernel<<<NE / 8, 256>>>(src, dst, 1);
    combine_kernel<<<NN / 32, 256, COMBINE_SMEM>>>(Wl1, bl1, Wr1, 2);   // -> g_c
    combine_kernel<<<NN / 32, 256, COMBINE_SMEM>>>(Wl1, bl1, Wr1, 3);   // -> g_u

    // classifier
    classifier_kernel<<<NN / 32, 256, CLS_SMEM>>>(W1, b1, W2, b2, out);
}

// round 8
// speedup vs baseline: 10.1601x; 1.2382x over previous
#include <cuda_runtime.h>
#include <math.h>

#define NN   32768
#define TT   20
#define EMBD 64
#define HD   128
#define NE   1048576   // NN * 32

// ---------------- scratch (static device globals; no allocations) ----------------
__device__ float g_u   [NN * HD];
__device__ float g_c   [NN * HD];
__device__ float g_u2  [NN * HD];
__device__ float g_c2  [NN * HD];
__device__ float g_aggc[NN * HD];
__device__ float g_aggu[NN * HD];
__device__ float g_cntd[NN];
__device__ float g_cnts[NN];

__device__ __forceinline__ float sigmoidf_(float x) { return 1.0f / (1.0f + expf(-x)); }

#define DOT4(acc, A, B) (acc) += (A).x*(B).x + (A).y*(B).y + (A).z*(B).z + (A).w*(B).w

// ---- packed f32x2 helpers (sm_103a FFMA2 path; bit-exact fp32) ----
__device__ __forceinline__ unsigned long long pack2(float a, float b) {
    unsigned long long r;
    asm("mov.b64 %0, {%1, %2};" : "=l"(r) : "f"(a), "f"(b));
    return r;
}
__device__ __forceinline__ void unpack2(unsigned long long v, float& a, float& b) {
    asm("mov.b64 {%0, %1}, %2;" : "=f"(a), "=f"(b) : "l"(v));
}
__device__ __forceinline__ void fma2(unsigned long long& d, unsigned long long a, unsigned long long b) {
    asm("fma.rn.f32x2 %0, %1, %2, %0;" : "+l"(d) : "l"(a), "l"(b));
}

// ---------------- zeroing ----------------
__global__ void zero_aggs_kernel(int also_counts) {
    int i = blockIdx.x * blockDim.x + threadIdx.x;
    int stride = gridDim.x * blockDim.x;
    for (int k = i; k < NN * HD; k += stride) { g_aggc[k] = 0.f; g_aggu[k] = 0.f; }
    if (also_counts) {
        for (int k = i; k < NN; k += stride) { g_cntd[k] = 0.f; g_cnts[k] = 0.f; }
    }
}

// ---------------- edge degree counts ----------------
__global__ void count_kernel(const int* __restrict__ src, const int* __restrict__ dst) {
    int e = blockIdx.x * blockDim.x + threadIdx.x;
    if (e < NE) {
        atomicAdd(&g_cntd[dst[e]], 1.0f);
        atomicAdd(&g_cnts[src[e]], 1.0f);
    }
}

// =====================================================================
// LSTM: smem-tiled register-blocked GEMM on the packed f32x2 FMA pipe.
//  Block: 512 threads, 64 users. Thread: 8 gate-rows x 8 users (4 pairs).
//  gg = tid & 63 -> gate rows gg + 64*j (j=0..7); ug = tid>>6 -> users ug*8..+7.
//  x_t / h_t stored k-major transposed ([k][64 users], stride 66) so a
//  user-pair is one aligned LDS.64; weights broadcast-packed (mov.b64 {w,w}).
//  Weight k-tiles (512x16) double-buffered, prefetched around the 12-tile ring.
// =====================================================================
#define LSTM_SMEM ((2*512*17 + 64*66 + 128*66 + 512) * 4)

template<int NROWS_UNUSED>
struct dummy_ {};

__device__ __forceinline__ void lstm_tile2(
    const float* __restrict__ xt,   // &layer[k0*66 + ucol0]
    const float* __restrict__ wp,   // Wsh[cur] + gg*17
    unsigned long long acc[8][4])
{
#pragma unroll
    for (int kk = 0; kk < 16; kk++) {
        unsigned long long xv[4];
#pragma unroll
        for (int p = 0; p < 4; p++)
            xv[p] = *(const unsigned long long*)(xt + kk * 66 + 2 * p);  // warp-broadcast LDS.64
#pragma unroll
        for (int j = 0; j < 8; j++) {
            float w = wp[j * 64 * 17 + kk];              // conflict-free (stride 17)
            unsigned long long wv = pack2(w, w);
#pragma unroll
            for (int p = 0; p < 4; p++) fma2(acc[j][p], wv, xv[p]);
        }
    }
}

__global__ __launch_bounds__(512, 1) void lstm_kernel(
    const float* __restrict__ x_user,
    const float* __restrict__ W_ih, const float* __restrict__ W_hh,
    const float* __restrict__ b_ih, const float* __restrict__ b_hh)
{
    extern __shared__ float sm[];
    float* Wsh  = sm;                   // [2][512][17]
    float* x_t  = Wsh + 2 * 512 * 17;   // [64][66]   k-major: x_t[k][user]
    float* h_t  = x_t + 64 * 66;        // [128][66]  k-major: h_t[k][user]
    float* bsum = h_t + 128 * 66;       // [512]

    int tid   = threadIdx.x;
    int gg    = tid & 63;
    int ug    = tid >> 6;
    int ucol0 = ug * 8;
    int u0    = blockIdx.x * 64;

    bsum[tid] = b_ih[tid] + b_hh[tid];
    for (int i = tid; i < 128 * 66; i += 512) h_t[i] = 0.f;

    float c0[8], c1[8];
#pragma unroll
    for (int r = 0; r < 8; r++) { c0[r] = 0.f; c1[r] = 0.f; }

    // ---- prologue: stage x_t for t=0 (transposed), weight tile 0 into buffer 0 ----
#pragma unroll
    for (int i = 0; i < 2; i++) {
        int idx = tid + i * 512;
        int u = idx >> 4, c = idx & 15;
        float4 v = ((const float4*)x_user)[((u0 + u) * TT + 0) * 16 + c];
        x_t[(4 * c + 0) * 66 + u] = v.x;
        x_t[(4 * c + 1) * 66 + u] = v.y;
        x_t[(4 * c + 2) * 66 + u] = v.z;
        x_t[(4 * c + 3) * 66 + u] = v.w;
    }
    {
        const float4* wsrc = (const float4*)(W_ih + tid * 64);   // tile 0: k0 = 0
        float* Wn = Wsh + tid * 17;
#pragma unroll
        for (int c = 0; c < 4; c++) {
            float4 w = wsrc[c];
            Wn[c * 4 + 0] = w.x; Wn[c * 4 + 1] = w.y;
            Wn[c * 4 + 2] = w.z; Wn[c * 4 + 3] = w.w;
        }
    }
    __syncthreads();

    unsigned long long acc[8][4];
    for (int t = 0; t < TT; t++) {
        // init accumulators with fused bias
#pragma unroll
        for (int j = 0; j < 8; j++) {
            unsigned long long b2v = pack2(bsum[gg + 64 * j], bsum[gg + 64 * j]);
#pragma unroll
            for (int p = 0; p < 4; p++) acc[j][p] = b2v;
        }

#pragma unroll 1
        for (int tile = 0; tile < 12; tile++) {
            int cur = tile & 1;
            bool last    = (t == TT - 1) && (tile == 11);
            bool stage_x = (tile == 11) && (t < TT - 1);

            // prefetch next weight tile into registers (ring: 11 -> 0)
            float4 wreg[4];
            if (!last) {
                int nt = (tile + 1) % 12;
                const float* wsrc = (nt < 4) ? (W_ih + tid * 64 + nt * 16)
                                             : (W_hh + tid * 128 + nt * 16 - 64);
#pragma unroll
                for (int c = 0; c < 4; c++) wreg[c] = ((const float4*)wsrc)[c];
            }
            // prefetch next step's x
            float4 xreg[2];
            if (stage_x) {
#pragma unroll
                for (int i = 0; i < 2; i++) {
                    int idx = tid + i * 512;
                    int u = idx >> 4, c = idx & 15;
                    xreg[i] = ((const float4*)x_user)[((u0 + u) * TT + t + 1) * 16 + c];
                }
            }

            // compute current tile (packed FFMA2)
            const float* wp = Wsh + cur * 512 * 17 + gg * 17;
            if (tile < 4) {
                lstm_tile2(x_t + (tile * 16) * 66 + ucol0, wp, acc);
            } else {
                lstm_tile2(h_t + (tile * 16 - 64) * 66 + ucol0, wp, acc);
            }

            // drain prefetches into the other buffer / x_t
            if (!last) {
                float* Wn = Wsh + (cur ^ 1) * 512 * 17 + tid * 17;
#pragma unroll
                for (int c = 0; c < 4; c++) {
                    Wn[c * 4 + 0] = wreg[c].x; Wn[c * 4 + 1] = wreg[c].y;
                    Wn[c * 4 + 2] = wreg[c].z; Wn[c * 4 + 3] = wreg[c].w;
                }
            }
            if (stage_x) {
#pragma unroll
                for (int i = 0; i < 2; i++) {
                    int idx = tid + i * 512;
                    int u = idx >> 4, c = idx & 15;
                    x_t[(4 * c + 0) * 66 + u] = xreg[i].x;
                    x_t[(4 * c + 1) * 66 + u] = xreg[i].y;
                    x_t[(4 * c + 2) * 66 + u] = xreg[i].z;
                    x_t[(4 * c + 3) * 66 + u] = xreg[i].w;
                }
            }
            __syncthreads();
        }

        // cell update: thread owns (i,f,g,o) for hidden m = gg and m = gg+64,
        // users ucol0 + 2p, +1 (pairs).
        bool final_t = (t == TT - 1);
#pragma unroll
        for (int p = 0; p < 4; p++) {
            float ia, ib, fa, fb, ga, gb, oa, ob;
            // hidden gg  (gates at j = 0,2,4,6)
            unpack2(acc[0][p], ia, ib);
            unpack2(acc[2][p], fa, fb);
            unpack2(acc[4][p], ga, gb);
            unpack2(acc[6][p], oa, ob);
            {
                float cA = sigmoidf_(fa) * c0[2*p]   + sigmoidf_(ia) * tanhf(ga);
                float cB = sigmoidf_(fb) * c0[2*p+1] + sigmoidf_(ib) * tanhf(gb);
                c0[2*p] = cA; c0[2*p+1] = cB;
                float hA = sigmoidf_(oa) * tanhf(cA);
                float hB = sigmoidf_(ob) * tanhf(cB);
                *(float2*)(h_t + gg * 66 + ucol0 + 2 * p) = make_float2(hA, hB);
                if (final_t) {
                    g_u[(u0 + ucol0 + 2*p)     * HD + gg] = hA;
                    g_u[(u0 + ucol0 + 2*p + 1) * HD + gg] = hB;
                }
            }
            // hidden gg+64 (gates at j = 1,3,5,7)
            unpack2(acc[1][p], ia, ib);
            unpack2(acc[3][p], fa, fb);
            unpack2(acc[5][p], ga, gb);
            unpack2(acc[7][p], oa, ob);
            {
                float cA = sigmoidf_(fa) * c1[2*p]   + sigmoidf_(ia) * tanhf(ga);
                float cB = sigmoidf_(fb) * c1[2*p+1] + sigmoidf_(ib) * tanhf(gb);
                c1[2*p] = cA; c1[2*p+1] = cB;
                float hA = sigmoidf_(oa) * tanhf(cA);
                float hB = sigmoidf_(ob) * tanhf(cB);
                *(float2*)(h_t + (gg + 64) * 66 + ucol0 + 2 * p) = make_float2(hA, hB);
                if (final_t) {
                    g_u[(u0 + ucol0 + 2*p)     * HD + gg + 64] = hA;
                    g_u[(u0 + ucol0 + 2*p + 1) * HD + gg + 64] = hB;
                }
            }
        }
    }
}

// ---------------- content linear: c = x_content @ Wc^T + bc ----------------
__global__ __launch_bounds__(256) void content_kernel(
    const float* __restrict__ xc, const float* __restrict__ Wc, const float* __restrict__ bc)
{
    __shared__ float4 Wc4s[128 * 17];  // 128 rows x 16 f4 (pad 17)
    __shared__ float4 xs[32 * 17];
    int tid = threadIdx.x;
    int n0 = blockIdx.x * 32;

    for (int idx = tid; idx < 128 * 16; idx += 256) {
        int r = idx >> 4, col = idx & 15;
        Wc4s[r * 17 + col] = ((const float4*)Wc)[idx];
    }
    for (int idx = tid; idx < 32 * 16; idx += 256) {
        int n = idx >> 4, k4 = idx & 15;
        xs[n * 17 + k4] = ((const float4*)xc)[(n0 + n) * 16 + k4];
    }
    __syncthreads();

    int n = tid >> 3, q = tid & 7;
    float acc[16];
#pragma unroll
    for (int i = 0; i < 16; i++) acc[i] = bc[q + 8 * i];
#pragma unroll 1
    for (int k4 = 0; k4 < 16; k4++) {
        float4 xv = xs[n * 17 + k4];
#pragma unroll
        for (int i = 0; i < 16; i++) {
            float4 wv = Wc4s[(q + 8 * i) * 17 + k4];
            DOT4(acc[i], wv, xv);
        }
    }
#pragma unroll
    for (int i = 0; i < 16; i++)
        g_c[(n0 + n) * HD + q + 8 * i] = acc[i];  // no activation
}

// ---------------- edge scatter: one warp per edge, vector reductions ----------------
__global__ __launch_bounds__(256) void scatter_kernel(
    const int* __restrict__ src, const int* __restrict__ dst, int layer)
{
    int e = blockIdx.x * 8 + (threadIdx.x >> 5);
    int lane = threadIdx.x & 31;
    if (e >= NE) return;
    const float* u = (layer == 0) ? g_u : g_u2;
    const float* c = (layer == 0) ? g_c : g_c2;
    int sidx = src[e], didx = dst[e];
    float4 uv = ((const float4*)u)[sidx * 32 + lane];
    float4 cv = ((const float4*)c)[didx * 32 + lane];
    float* ac = g_aggc + didx * HD + lane * 4;
    asm volatile("red.global.add.v4.f32 [%0], {%1, %2, %3, %4};"
                 :: "l"(ac), "f"(uv.x), "f"(uv.y), "f"(uv.z), "f"(uv.w) : "memory");
    float* au = g_aggu + sidx * HD + lane * 4;
    asm volatile("red.global.add.v4.f32 [%0], {%1, %2, %3, %4};"
                 :: "l"(au), "f"(cv.x), "f"(cv.y), "f"(cv.z), "f"(cv.w) : "memory");
}

// ---------------- SAGE combine: out = relu(mean @ Wl^T + bl + self @ Wr^T) ----------------
#define COMBINE_SMEM ((2 * 128 * 33 + 2 * 32 * 33) * 16)
__global__ __launch_bounds__(256) void combine_kernel(
    const float* __restrict__ Wl, const float* __restrict__ bl,
    const float* __restrict__ Wr, int mode)
{
    extern __shared__ float smc[];
    float4* Wl4 = (float4*)smc;          // 128 x 33
    float4* Wr4 = Wl4 + 128 * 33;
    float4* xm4 = Wr4 + 128 * 33;        // 32 x 33
    float4* xs4 = xm4 + 32 * 33;

    const float* agg; const float* cnt; const float* selfx; float* outp;
    if      (mode == 0) { agg = g_aggc; cnt = g_cntd; selfx = g_c;  outp = g_c2; }
    else if (mode == 1) { agg = g_aggu; cnt = g_cnts; selfx = g_u;  outp = g_u2; }
    else if (mode == 2) { agg = g_aggc; cnt = g_cntd; selfx = g_c2; outp = g_c;  }
    else                { agg = g_aggu; cnt = g_cnts; selfx = g_u2; outp = g_u;  }

    int tid = threadIdx.x;
    int n0 = blockIdx.x * 32;

    for (int idx = tid; idx < 128 * 32; idx += 256) {
        int r = idx >> 5, col = idx & 31;
        Wl4[r * 33 + col] = ((const float4*)Wl)[idx];
        Wr4[r * 33 + col] = ((const float4*)Wr)[idx];
    }
    for (int idx = tid; idx < 32 * 32; idx += 256) {
        int n = idx >> 5, k4 = idx & 31;
        float inv = 1.0f / fmaxf(cnt[n0 + n], 1.0f);
        float4 a = ((const float4*)agg)[(n0 + n) * 32 + k4];
        a.x *= inv; a.y *= inv; a.z *= inv; a.w *= inv;
        xm4[n * 33 + k4] = a;
        xs4[n * 33 + k4] = ((const float4*)selfx)[(n0 + n) * 32 + k4];
    }
    __syncthreads();

    int n = tid >> 3, q = tid & 7;
    float acc[16];
#pragma unroll
    for (int i = 0; i < 16; i++) acc[i] = bl[q + 8 * i];
#pragma unroll 1
    for (int k4 = 0; k4 < 32; k4++) {
        float4 xm = xm4[n * 33 + k4];
        float4 xv = xs4[n * 33 + k4];
#pragma unroll
        for (int i = 0; i < 16; i++) {
            int j = q + 8 * i;
            float4 wlv = Wl4[j * 33 + k4];
            float4 wrv = Wr4[j * 33 + k4];
            DOT4(acc[i], wlv, xm);
            DOT4(acc[i], wrv, xv);
        }
    }
#pragma unroll
    for (int i = 0; i < 16; i++)
        outp[(n0 + n) * HD + q + 8 * i] = fmaxf(acc[i], 0.f);
}

// ---------------- classifier: sigmoid(relu([u,c] @ W1^T + b1) @ W2^T + b2) ----------------
#define CLS_SMEM ((128 * 65 + 32 * 65) * 16 + 512)
__global__ __launch_bounds__(256) void classifier_kernel(
    const float* __restrict__ W1, const float* __restrict__ b1,
    const float* __restrict__ W2, const float* __restrict__ b2,
    float* __restrict__ out)
{
    extern __shared__ float smk[];
    float4* W14 = (float4*)smk;       // 128 rows x 65 (64 f4 data + pad)
    float4* xc4 = W14 + 128 * 65;     // 32 nodes x 65
    float*  W2s = (float*)(xc4 + 32 * 65);

    int tid = threadIdx.x;
    int n0 = blockIdx.x * 32;

    for (int idx = tid; idx < 128 * 64; idx += 256) {
        int r = idx >> 6, col = idx & 63;
        W14[r * 65 + col] = ((const float4*)W1)[idx];
    }
    for (int idx = tid; idx < 32 * 64; idx += 256) {
        int n = idx >> 6, k4 = idx & 63;
        float4 v = (k4 < 32) ? ((const float4*)g_u)[(n0 + n) * 32 + k4]
                             : ((const float4*)g_c)[(n0 + n) * 32 + (k4 - 32)];
        xc4[n * 65 + k4] = v;
    }
    if (tid < 128) W2s[tid] = W2[tid];
    __syncthreads();

    int n = tid >> 3, q = tid & 7;
    float acc[16];
#pragma unroll
    for (int i = 0; i < 16; i++) acc[i] = b1[q + 8 * i];
#pragma unroll 1
    for (int k4 = 0; k4 < 64; k4++) {
        float4 xv = xc4[n * 65 + k4];
#pragma unroll
        for (int i = 0; i < 16; i++) {
            float4 wv = W14[(q + 8 * i) * 65 + k4];
            DOT4(acc[i], wv, xv);
        }
    }
    float p = 0.f;
#pragma unroll
    for (int i = 0; i < 16; i++) {
        float h = fmaxf(acc[i], 0.f);
        p += h * W2s[q + 8 * i];
    }
    p += __shfl_xor_sync(0xffffffffu, p, 1);
    p += __shfl_xor_sync(0xffffffffu, p, 2);
    p += __shfl_xor_sync(0xffffffffu, p, 4);
    if (q == 0) out[n0 + n] = sigmoidf_(p + b2[0]);
}

// ---------------- launch ----------------
extern "C" void kernel_launch(void* const* d_in, const int* in_sizes, int n_in,
                              void* d_out, int out_size)
{
    const float* x_user    = (const float*)d_in[0];
    const float* x_content = (const float*)d_in[1];
    const int*   edge      = (const int*)  d_in[2];
    const float* W_ih      = (const float*)d_in[3];
    const float* W_hh      = (const float*)d_in[4];
    const float* b_ih      = (const float*)d_in[5];
    const float* b_hh      = (const float*)d_in[6];
    const float* Wc        = (const float*)d_in[7];
    const float* bc        = (const float*)d_in[8];
    const float* Wl0       = (const float*)d_in[9];
    const float* bl0       = (const float*)d_in[10];
    const float* Wr0       = (const float*)d_in[11];
    const float* Wl1       = (const float*)d_in[12];
    const float* bl1       = (const float*)d_in[13];
    const float* Wr1       = (const float*)d_in[14];
    const float* W1        = (const float*)d_in[15];
    const float* b1        = (const float*)d_in[16];
    const float* W2        = (const float*)d_in[17];
    const float* b2        = (const float*)d_in[18];
    float* out = (float*)d_out;

    const int* src = edge;
    const int* dst = edge + NE;

    cudaFuncSetAttribute(lstm_kernel,       cudaFuncAttributeMaxDynamicSharedMemorySize, LSTM_SMEM);
    cudaFuncSetAttribute(combine_kernel,    cudaFuncAttributeMaxDynamicSharedMemorySize, COMBINE_SMEM);
    cudaFuncSetAttribute(classifier_kernel, cudaFuncAttributeMaxDynamicSharedMemorySize, CLS_SMEM);

    // zero aggregation buffers + counts
    zero_aggs_kernel<<<4096, 256>>>(1);
    count_kernel<<<NE / 256, 256>>>(src, dst);

    // node features
    lstm_kernel<<<NN / 64, 512, LSTM_SMEM>>>(x_user, W_ih, W_hh, b_ih, b_hh);  // -> g_u
    content_kernel<<<NN / 32, 256>>>(x_content, Wc, bc);                       // -> g_c

    // SAGE layer 0
    scatter_kernel<<<NE / 8, 256>>>(src, dst, 0);
    combine_kernel<<<NN / 32, 256, COMBINE_SMEM>>>(Wl0, bl0, Wr0, 0);   // -> g_c2
    combine_kernel<<<NN / 32, 256, COMBINE_SMEM>>>(Wl0, bl0, Wr0, 1);   // -> g_u2

    // SAGE layer 1
    zero_aggs_kernel<<<4096, 256>>>(0);
    scatter_kernel<<<NE / 8, 256>>>(src, dst, 1);
    combine_kernel<<<NN / 32, 256, COMBINE_SMEM>>>(Wl1, bl1, Wr1, 2);   // -> g_c
    combine_kernel<<<NN / 32, 256, COMBINE_SMEM>>>(Wl1, bl1, Wr1, 3);   // -> g_u

    // classifier
    classifier_kernel<<<NN / 32, 256, CLS_SMEM>>>(W1, b1, W2, b2, out);
}

// round 10
// speedup vs baseline: 10.4132x; 1.0249x over previous
#include <cuda_runtime.h>
#include <math.h>

#define NN   32768
#define TT   20
#define EMBD 64
#define HD   128
#define NE   1048576   // NN * 32

// ---------------- scratch (static device globals; no allocations) ----------------
__device__ float g_u   [NN * HD];
__device__ float g_c   [NN * HD];
__device__ float g_u2  [NN * HD];
__device__ float g_c2  [NN * HD];
__device__ float g_aggc[NN * HD];   // holds MEAN directly
__device__ float g_aggu[NN * HD];   // holds MEAN directly

// CSR scratch
__device__ int g_deg_d[NN];
__device__ int g_deg_s[NN];
__device__ int g_off_d[NN + 1];
__device__ int g_off_s[NN + 1];
__device__ int g_cur_d[NN];
__device__ int g_cur_s[NN];
__device__ int g_eid_d[NE];   // grouped by dst, stores src (user) ids
__device__ int g_eid_s[NE];   // grouped by src, stores dst (content) ids

__device__ __forceinline__ float sigmoidf_(float x) { return 1.0f / (1.0f + expf(-x)); }

#define DOT4(acc, A, B) (acc) += (A).x*(B).x + (A).y*(B).y + (A).z*(B).z + (A).w*(B).w

// ---- packed f32x2 helpers (sm_103a FFMA2 path; bit-exact fp32) ----
__device__ __forceinline__ unsigned long long pack2(float a, float b) {
    unsigned long long r;
    asm("mov.b64 %0, {%1, %2};" : "=l"(r) : "f"(a), "f"(b));
    return r;
}
__device__ __forceinline__ void unpack2(unsigned long long v, float& a, float& b) {
    asm("mov.b64 {%0, %1}, %2;" : "=f"(a), "=f"(b) : "l"(v));
}
__device__ __forceinline__ void fma2(unsigned long long& d, unsigned long long a, unsigned long long b) {
    asm("fma.rn.f32x2 %0, %1, %2, %0;" : "+l"(d) : "l"(a), "l"(b));
}

// ================= CSR build =================
__global__ void zero_deg_kernel() {
    int i = blockIdx.x * blockDim.x + threadIdx.x;
    if (i < NN) { g_deg_d[i] = 0; g_deg_s[i] = 0; }
}

__global__ void count_kernel(const int* __restrict__ src, const int* __restrict__ dst) {
    int e = blockIdx.x * blockDim.x + threadIdx.x;
    if (e < NE) {
        atomicAdd(&g_deg_d[dst[e]], 1);
        atomicAdd(&g_deg_s[src[e]], 1);
    }
}

// grid = 2 blocks x 1024 threads; block 0 scans deg_d -> off_d/cur_d, block 1 deg_s
__global__ __launch_bounds__(1024) void scan_kernel() {
    const int* deg = (blockIdx.x == 0) ? g_deg_d : g_deg_s;
    int* off = (blockIdx.x == 0) ? g_off_d : g_off_s;
    int* cur = (blockIdx.x == 0) ? g_cur_d : g_cur_s;

    __shared__ int part[1024];
    int tid = threadIdx.x;
    int base = tid * 32;

    int s = 0;
#pragma unroll 4
    for (int k = 0; k < 32; k++) s += deg[base + k];
    part[tid] = s;
    __syncthreads();
    for (int d = 1; d < 1024; d <<= 1) {
        int v = (tid >= d) ? part[tid - d] : 0;
        __syncthreads();
        if (tid >= d) part[tid] += v;
        __syncthreads();
    }
    int run = (tid == 0) ? 0 : part[tid - 1];
#pragma unroll 4
    for (int k = 0; k < 32; k++) {
        off[base + k] = run;
        cur[base + k] = run;
        run += deg[base + k];
    }
    if (tid == 1023) off[NN] = run;
}

__global__ void fill_kernel(const int* __restrict__ src, const int* __restrict__ dst) {
    int e = blockIdx.x * blockDim.x + threadIdx.x;
    if (e < NE) {
        int s = src[e], d = dst[e];
        int p = atomicAdd(&g_cur_d[d], 1); g_eid_d[p] = s;
        int q = atomicAdd(&g_cur_s[s], 1); g_eid_s[q] = d;
    }
}

// ================= CSR mean-aggregate: one warp per node =================
// Pointers resolved in DEVICE code (never pass __device__ symbols from host!).
// mode 0: off_d/eid_d, feat=g_u  -> g_aggc     mode 1: off_s/eid_s, feat=g_c  -> g_aggu
// mode 2: off_d/eid_d, feat=g_u2 -> g_aggc     mode 3: off_s/eid_s, feat=g_c2 -> g_aggu
__global__ __launch_bounds__(256) void agg_kernel(int mode)
{
    const int* off; const int* eid; const float* feat; float* outp;
    if      (mode == 0) { off = g_off_d; eid = g_eid_d; feat = g_u;  outp = g_aggc; }
    else if (mode == 1) { off = g_off_s; eid = g_eid_s; feat = g_c;  outp = g_aggu; }
    else if (mode == 2) { off = g_off_d; eid = g_eid_d; feat = g_u2; outp = g_aggc; }
    else                { off = g_off_s; eid = g_eid_s; feat = g_c2; outp = g_aggu; }

    int n = blockIdx.x * 8 + (threadIdx.x >> 5);
    int lane = threadIdx.x & 31;
    int a = off[n], b = off[n + 1];

    float4 acc = make_float4(0.f, 0.f, 0.f, 0.f);
    const float4* f4 = (const float4*)feat;

    int i = a;
    for (; i + 4 <= b; i += 4) {
        int e0 = __ldg(&eid[i]),     e1 = __ldg(&eid[i + 1]);
        int e2 = __ldg(&eid[i + 2]), e3 = __ldg(&eid[i + 3]);
        float4 v0 = f4[e0 * 32 + lane];
        float4 v1 = f4[e1 * 32 + lane];
        float4 v2 = f4[e2 * 32 + lane];
        float4 v3 = f4[e3 * 32 + lane];
        acc.x += v0.x + v1.x + v2.x + v3.x;
        acc.y += v0.y + v1.y + v2.y + v3.y;
        acc.z += v0.z + v1.z + v2.z + v3.z;
        acc.w += v0.w + v1.w + v2.w + v3.w;
    }
    for (; i < b; i++) {
        int e0 = __ldg(&eid[i]);
        float4 v0 = f4[e0 * 32 + lane];
        acc.x += v0.x; acc.y += v0.y; acc.z += v0.z; acc.w += v0.w;
    }
    float inv = (b > a) ? 1.0f / (float)(b - a) : 1.0f;   // mean / max(cnt,1)
    acc.x *= inv; acc.y *= inv; acc.z *= inv; acc.w *= inv;
    ((float4*)outp)[n * 32 + lane] = acc;
}

// =====================================================================
// LSTM: smem-tiled register-blocked GEMM on the packed f32x2 FMA pipe.
// (unchanged from R8 — passed at rel_err 4.4e-8)
// =====================================================================
#define LSTM_SMEM ((2*512*17 + 64*66 + 128*66 + 512) * 4)

__device__ __forceinline__ void lstm_tile2(
    const float* __restrict__ xt,   // &layer[k0*66 + ucol0]
    const float* __restrict__ wp,   // Wsh[cur] + gg*17
    unsigned long long acc[8][4])
{
#pragma unroll
    for (int kk = 0; kk < 16; kk++) {
        unsigned long long xv[4];
#pragma unroll
        for (int p = 0; p < 4; p++)
            xv[p] = *(const unsigned long long*)(xt + kk * 66 + 2 * p);  // warp-broadcast LDS.64
#pragma unroll
        for (int j = 0; j < 8; j++) {
            float w = wp[j * 64 * 17 + kk];              // conflict-free (stride 17)
            unsigned long long wv = pack2(w, w);
#pragma unroll
            for (int p = 0; p < 4; p++) fma2(acc[j][p], wv, xv[p]);
        }
    }
}

__global__ __launch_bounds__(512, 1) void lstm_kernel(
    const float* __restrict__ x_user,
    const float* __restrict__ W_ih, const float* __restrict__ W_hh,
    const float* __restrict__ b_ih, const float* __restrict__ b_hh)
{
    extern __shared__ float sm[];
    float* Wsh  = sm;                   // [2][512][17]
    float* x_t  = Wsh + 2 * 512 * 17;   // [64][66]   k-major: x_t[k][user]
    float* h_t  = x_t + 64 * 66;        // [128][66]  k-major: h_t[k][user]
    float* bsum = h_t + 128 * 66;       // [512]

    int tid   = threadIdx.x;
    int gg    = tid & 63;
    int ug    = tid >> 6;
    int ucol0 = ug * 8;
    int u0    = blockIdx.x * 64;

    bsum[tid] = b_ih[tid] + b_hh[tid];
    for (int i = tid; i < 128 * 66; i += 512) h_t[i] = 0.f;

    float c0[8], c1[8];
#pragma unroll
    for (int r = 0; r < 8; r++) { c0[r] = 0.f; c1[r] = 0.f; }

    // ---- prologue: stage x_t for t=0 (transposed), weight tile 0 into buffer 0 ----
#pragma unroll
    for (int i = 0; i < 2; i++) {
        int idx = tid + i * 512;
        int u = idx >> 4, c = idx & 15;
        float4 v = ((const float4*)x_user)[((u0 + u) * TT + 0) * 16 + c];
        x_t[(4 * c + 0) * 66 + u] = v.x;
        x_t[(4 * c + 1) * 66 + u] = v.y;
        x_t[(4 * c + 2) * 66 + u] = v.z;
        x_t[(4 * c + 3) * 66 + u] = v.w;
    }
    {
        const float4* wsrc = (const float4*)(W_ih + tid * 64);   // tile 0: k0 = 0
        float* Wn = Wsh + tid * 17;
#pragma unroll
        for (int c = 0; c < 4; c++) {
            float4 w = wsrc[c];
            Wn[c * 4 + 0] = w.x; Wn[c * 4 + 1] = w.y;
            Wn[c * 4 + 2] = w.z; Wn[c * 4 + 3] = w.w;
        }
    }
    __syncthreads();

    unsigned long long acc[8][4];
    for (int t = 0; t < TT; t++) {
#pragma unroll
        for (int j = 0; j < 8; j++) {
            unsigned long long b2v = pack2(bsum[gg + 64 * j], bsum[gg + 64 * j]);
#pragma unroll
            for (int p = 0; p < 4; p++) acc[j][p] = b2v;
        }

#pragma unroll 1
        for (int tile = 0; tile < 12; tile++) {
            int cur = tile & 1;
            bool last    = (t == TT - 1) && (tile == 11);
            bool stage_x = (tile == 11) && (t < TT - 1);

            float4 wreg[4];
            if (!last) {
                int nt = (tile + 1) % 12;
                const float* wsrc = (nt < 4) ? (W_ih + tid * 64 + nt * 16)
                                             : (W_hh + tid * 128 + nt * 16 - 64);
#pragma unroll
                for (int c = 0; c < 4; c++) wreg[c] = ((const float4*)wsrc)[c];
            }
            float4 xreg[2];
            if (stage_x) {
#pragma unroll
                for (int i = 0; i < 2; i++) {
                    int idx = tid + i * 512;
                    int u = idx >> 4, c = idx & 15;
                    xreg[i] = ((const float4*)x_user)[((u0 + u) * TT + t + 1) * 16 + c];
                }
            }

            const float* wp = Wsh + cur * 512 * 17 + gg * 17;
            if (tile < 4) {
                lstm_tile2(x_t + (tile * 16) * 66 + ucol0, wp, acc);
            } else {
                lstm_tile2(h_t + (tile * 16 - 64) * 66 + ucol0, wp, acc);
            }

            if (!last) {
                float* Wn = Wsh + (cur ^ 1) * 512 * 17 + tid * 17;
#pragma unroll
                for (int c = 0; c < 4; c++) {
                    Wn[c * 4 + 0] = wreg[c].x; Wn[c * 4 + 1] = wreg[c].y;
                    Wn[c * 4 + 2] = wreg[c].z; Wn[c * 4 + 3] = wreg[c].w;
                }
            }
            if (stage_x) {
#pragma unroll
                for (int i = 0; i < 2; i++) {
                    int idx = tid + i * 512;
                    int u = idx >> 4, c = idx & 15;
                    x_t[(4 * c + 0) * 66 + u] = xreg[i].x;
                    x_t[(4 * c + 1) * 66 + u] = xreg[i].y;
                    x_t[(4 * c + 2) * 66 + u] = xreg[i].z;
                    x_t[(4 * c + 3) * 66 + u] = xreg[i].w;
                }
            }
            __syncthreads();
        }

        bool final_t = (t == TT - 1);
#pragma unroll
        for (int p = 0; p < 4; p++) {
            float ia, ib, fa, fb, ga, gb, oa, ob;
            unpack2(acc[0][p], ia, ib);
            unpack2(acc[2][p], fa, fb);
            unpack2(acc[4][p], ga, gb);
            unpack2(acc[6][p], oa, ob);
            {
                float cA = sigmoidf_(fa) * c0[2*p]   + sigmoidf_(ia) * tanhf(ga);
                float cB = sigmoidf_(fb) * c0[2*p+1] + sigmoidf_(ib) * tanhf(gb);
                c0[2*p] = cA; c0[2*p+1] = cB;
                float hA = sigmoidf_(oa) * tanhf(cA);
                float hB = sigmoidf_(ob) * tanhf(cB);
                *(float2*)(h_t + gg * 66 + ucol0 + 2 * p) = make_float2(hA, hB);
                if (final_t) {
                    g_u[(u0 + ucol0 + 2*p)     * HD + gg] = hA;
                    g_u[(u0 + ucol0 + 2*p + 1) * HD + gg] = hB;
                }
            }
            unpack2(acc[1][p], ia, ib);
            unpack2(acc[3][p], fa, fb);
            unpack2(acc[5][p], ga, gb);
            unpack2(acc[7][p], oa, ob);
            {
                float cA = sigmoidf_(fa) * c1[2*p]   + sigmoidf_(ia) * tanhf(ga);
                float cB = sigmoidf_(fb) * c1[2*p+1] + sigmoidf_(ib) * tanhf(gb);
                c1[2*p] = cA; c1[2*p+1] = cB;
                float hA = sigmoidf_(oa) * tanhf(cA);
                float hB = sigmoidf_(ob) * tanhf(cB);
                *(float2*)(h_t + (gg + 64) * 66 + ucol0 + 2 * p) = make_float2(hA, hB);
                if (final_t) {
                    g_u[(u0 + ucol0 + 2*p)     * HD + gg + 64] = hA;
                    g_u[(u0 + ucol0 + 2*p + 1) * HD + gg + 64] = hB;
                }
            }
        }
    }
}

// ---------------- content linear: c = x_content @ Wc^T + bc ----------------
__global__ __launch_bounds__(256) void content_kernel(
    const float* __restrict__ xc, const float* __restrict__ Wc, const float* __restrict__ bc)
{
    __shared__ float4 Wc4s[128 * 17];
    __shared__ float4 xs[32 * 17];
    int tid = threadIdx.x;
    int n0 = blockIdx.x * 32;

    for (int idx = tid; idx < 128 * 16; idx += 256) {
        int r = idx >> 4, col = idx & 15;
        Wc4s[r * 17 + col] = ((const float4*)Wc)[idx];
    }
    for (int idx = tid; idx < 32 * 16; idx += 256) {
        int n = idx >> 4, k4 = idx & 15;
        xs[n * 17 + k4] = ((const float4*)xc)[(n0 + n) * 16 + k4];
    }
    __syncthreads();

    int n = tid >> 3, q = tid & 7;
    float acc[16];
#pragma unroll
    for (int i = 0; i < 16; i++) acc[i] = bc[q + 8 * i];
#pragma unroll 1
    for (int k4 = 0; k4 < 16; k4++) {
        float4 xv = xs[n * 17 + k4];
#pragma unroll
        for (int i = 0; i < 16; i++) {
            float4 wv = Wc4s[(q + 8 * i) * 17 + k4];
            DOT4(acc[i], wv, xv);
        }
    }
#pragma unroll
    for (int i = 0; i < 16; i++)
        g_c[(n0 + n) * HD + q + 8 * i] = acc[i];
}

// ---------------- SAGE combine: out = relu(mean @ Wl^T + bl + self @ Wr^T) ----------------
// agg buffers already hold the MEAN (no division here).
#define COMBINE_SMEM ((2 * 128 * 33 + 2 * 32 * 33) * 16)
__global__ __launch_bounds__(256) void combine_kernel(
    const float* __restrict__ Wl, const float* __restrict__ bl,
    const float* __restrict__ Wr, int mode)
{
    extern __shared__ float smc[];
    float4* Wl4 = (float4*)smc;          // 128 x 33
    float4* Wr4 = Wl4 + 128 * 33;
    float4* xm4 = Wr4 + 128 * 33;        // 32 x 33
    float4* xs4 = xm4 + 32 * 33;

    const float* agg; const float* selfx; float* outp;
    if      (mode == 0) { agg = g_aggc; selfx = g_c;  outp = g_c2; }
    else if (mode == 1) { agg = g_aggu; selfx = g_u;  outp = g_u2; }
    else if (mode == 2) { agg = g_aggc; selfx = g_c2; outp = g_c;  }
    else                { agg = g_aggu; selfx = g_u2; outp = g_u;  }

    int tid = threadIdx.x;
    int n0 = blockIdx.x * 32;

    for (int idx = tid; idx < 128 * 32; idx += 256) {
        int r = idx >> 5, col = idx & 31;
        Wl4[r * 33 + col] = ((const float4*)Wl)[idx];
        Wr4[r * 33 + col] = ((const float4*)Wr)[idx];
    }
    for (int idx = tid; idx < 32 * 32; idx += 256) {
        int n = idx >> 5, k4 = idx & 31;
        xm4[n * 33 + k4] = ((const float4*)agg)[(n0 + n) * 32 + k4];
        xs4[n * 33 + k4] = ((const float4*)selfx)[(n0 + n) * 32 + k4];
    }
    __syncthreads();

    int n = tid >> 3, q = tid & 7;
    float acc[16];
#pragma unroll
    for (int i = 0; i < 16; i++) acc[i] = bl[q + 8 * i];
#pragma unroll 1
    for (int k4 = 0; k4 < 32; k4++) {
        float4 xm = xm4[n * 33 + k4];
        float4 xv = xs4[n * 33 + k4];
#pragma unroll
        for (int i = 0; i < 16; i++) {
            int j = q + 8 * i;
            float4 wlv = Wl4[j * 33 + k4];
            float4 wrv = Wr4[j * 33 + k4];
            DOT4(acc[i], wlv, xm);
            DOT4(acc[i], wrv, xv);
        }
    }
#pragma unroll
    for (int i = 0; i < 16; i++)
        outp[(n0 + n) * HD + q + 8 * i] = fmaxf(acc[i], 0.f);
}

// ---------------- classifier ----------------
#define CLS_SMEM ((128 * 65 + 32 * 65) * 16 + 512)
__global__ __launch_bounds__(256) void classifier_kernel(
    const float* __restrict__ W1, const float* __restrict__ b1,
    const float* __restrict__ W2, const float* __restrict__ b2,
    float* __restrict__ out)
{
    extern __shared__ float smk[];
    float4* W14 = (float4*)smk;
    float4* xc4 = W14 + 128 * 65;
    float*  W2s = (float*)(xc4 + 32 * 65);

    int tid = threadIdx.x;
    int n0 = blockIdx.x * 32;

    for (int idx = tid; idx < 128 * 64; idx += 256) {
        int r = idx >> 6, col = idx & 63;
        W14[r * 65 + col] = ((const float4*)W1)[idx];
    }
    for (int idx = tid; idx < 32 * 64; idx += 256) {
        int n = idx >> 6, k4 = idx & 63;
        float4 v = (k4 < 32) ? ((const float4*)g_u)[(n0 + n) * 32 + k4]
                             : ((const float4*)g_c)[(n0 + n) * 32 + (k4 - 32)];
        xc4[n * 65 + k4] = v;
    }
    if (tid < 128) W2s[tid] = W2[tid];
    __syncthreads();

    int n = tid >> 3, q = tid & 7;
    float acc[16];
#pragma unroll
    for (int i = 0; i < 16; i++) acc[i] = b1[q + 8 * i];
#pragma unroll 1
    for (int k4 = 0; k4 < 64; k4++) {
        float4 xv = xc4[n * 65 + k4];
#pragma unroll
        for (int i = 0; i < 16; i++) {
            float4 wv = W14[(q + 8 * i) * 65 + k4];
            DOT4(acc[i], wv, xv);
        }
    }
    float p = 0.f;
#pragma unroll
    for (int i = 0; i < 16; i++) {
        float h = fmaxf(acc[i], 0.f);
        p += h * W2s[q + 8 * i];
    }
    p += __shfl_xor_sync(0xffffffffu, p, 1);
    p += __shfl_xor_sync(0xffffffffu, p, 2);
    p += __shfl_xor_sync(0xffffffffu, p, 4);
    if (q == 0) out[n0 + n] = sigmoidf_(p + b2[0]);
}

// ---------------- launch ----------------
extern "C" void kernel_launch(void* const* d_in, const int* in_sizes, int n_in,
                              void* d_out, int out_size)
{
    const float* x_user    = (const float*)d_in[0];
    const float* x_content = (const float*)d_in[1];
    const int*   edge      = (const int*)  d_in[2];
    const float* W_ih      = (const float*)d_in[3];
    const float* W_hh      = (const float*)d_in[4];
    const float* b_ih      = (const float*)d_in[5];
    const float* b_hh      = (const float*)d_in[6];
    const float* Wc        = (const float*)d_in[7];
    const float* bc        = (const float*)d_in[8];
    const float* Wl0       = (const float*)d_in[9];
    const float* bl0       = (const float*)d_in[10];
    const float* Wr0       = (const float*)d_in[11];
    const float* Wl1       = (const float*)d_in[12];
    const float* bl1       = (const float*)d_in[13];
    const float* Wr1       = (const float*)d_in[14];
    const float* W1        = (const float*)d_in[15];
    const float* b1        = (const float*)d_in[16];
    const float* W2        = (const float*)d_in[17];
    const float* b2        = (const float*)d_in[18];
    float* out = (float*)d_out;

    const int* src = edge;
    const int* dst = edge + NE;

    cudaFuncSetAttribute(lstm_kernel,       cudaFuncAttributeMaxDynamicSharedMemorySize, LSTM_SMEM);
    cudaFuncSetAttribute(combine_kernel,    cudaFuncAttributeMaxDynamicSharedMemorySize, COMBINE_SMEM);
    cudaFuncSetAttribute(classifier_kernel, cudaFuncAttributeMaxDynamicSharedMemorySize, CLS_SMEM);

    // ---- CSR build (per call; deterministic; graph-capturable) ----
    zero_deg_kernel<<<NN / 256, 256>>>();
    count_kernel<<<NE / 256, 256>>>(src, dst);
    scan_kernel<<<2, 1024>>>();
    fill_kernel<<<NE / 256, 256>>>(src, dst);

    // ---- node features ----
    lstm_kernel<<<NN / 64, 512, LSTM_SMEM>>>(x_user, W_ih, W_hh, b_ih, b_hh);  // -> g_u
    content_kernel<<<NN / 32, 256>>>(x_content, Wc, bc);                       // -> g_c

    // ---- SAGE layer 0 ----
    agg_kernel<<<NN / 8, 256>>>(0);   // mean of u[src] per dst -> g_aggc
    agg_kernel<<<NN / 8, 256>>>(1);   // mean of c[dst] per src -> g_aggu
    combine_kernel<<<NN / 32, 256, COMBINE_SMEM>>>(Wl0, bl0, Wr0, 0);   // -> g_c2
    combine_kernel<<<NN / 32, 256, COMBINE_SMEM>>>(Wl0, bl0, Wr0, 1);   // -> g_u2

    // ---- SAGE layer 1 ----
    agg_kernel<<<NN / 8, 256>>>(2);   // mean of u2[src] per dst -> g_aggc
    agg_kernel<<<NN / 8, 256>>>(3);   // mean of c2[dst] per src -> g_aggu
    combine_kernel<<<NN / 32, 256, COMBINE_SMEM>>>(Wl1, bl1, Wr1, 2);   // -> g_c
    combine_kernel<<<NN / 32, 256, COMBINE_SMEM>>>(Wl1, bl1, Wr1, 3);   // -> g_u

    // ---- classifier ----
    classifier_kernel<<<NN / 32, 256, CLS_SMEM>>>(W1, b1, W2, b2, out);
}

// round 11
// speedup vs baseline: 20.3444x; 1.9537x over previous
#include <cuda_runtime.h>
#include <math.h>

#define NN   32768
#define TT   20
#define EMBD 64
#define HD   128
#define NE   1048576   // NN * 32

// ---------------- scratch (static device globals; no allocations) ----------------
__device__ float g_u   [NN * HD];
__device__ float g_c   [NN * HD];
__device__ float g_u2  [NN * HD];
__device__ float g_c2  [NN * HD];
__device__ float g_aggc[NN * HD];   // holds MEAN directly
__device__ float g_aggu[NN * HD];   // holds MEAN directly
__device__ float g_gates [NN * 512]; // LSTM gate preactivations (per step)
__device__ float g_cstate[NN * HD];  // LSTM cell state

// CSR scratch
__device__ int g_deg_d[NN];
__device__ int g_deg_s[NN];
__device__ int g_off_d[NN + 1];
__device__ int g_off_s[NN + 1];
__device__ int g_cur_d[NN];
__device__ int g_cur_s[NN];
__device__ int g_eid_d[NE];   // grouped by dst, stores src (user) ids
__device__ int g_eid_s[NE];   // grouped by src, stores dst (content) ids

__device__ __forceinline__ float sigmoidf_(float x) { return 1.0f / (1.0f + expf(-x)); }

#define DOT4(acc, A, B) (acc) += (A).x*(B).x + (A).y*(B).y + (A).z*(B).z + (A).w*(B).w

// ================= CSR build =================
__global__ void zero_deg_kernel() {
    int i = blockIdx.x * blockDim.x + threadIdx.x;
    if (i < NN) { g_deg_d[i] = 0; g_deg_s[i] = 0; }
}

__global__ void count_kernel(const int* __restrict__ src, const int* __restrict__ dst) {
    int e = blockIdx.x * blockDim.x + threadIdx.x;
    if (e < NE) {
        atomicAdd(&g_deg_d[dst[e]], 1);
        atomicAdd(&g_deg_s[src[e]], 1);
    }
}

// grid = 2 blocks x 1024 threads; block 0 scans deg_d -> off_d/cur_d, block 1 deg_s
__global__ __launch_bounds__(1024) void scan_kernel() {
    const int* deg = (blockIdx.x == 0) ? g_deg_d : g_deg_s;
    int* off = (blockIdx.x == 0) ? g_off_d : g_off_s;
    int* cur = (blockIdx.x == 0) ? g_cur_d : g_cur_s;

    __shared__ int part[1024];
    int tid = threadIdx.x;
    int base = tid * 32;

    int s = 0;
#pragma unroll 4
    for (int k = 0; k < 32; k++) s += deg[base + k];
    part[tid] = s;
    __syncthreads();
    for (int d = 1; d < 1024; d <<= 1) {
        int v = (tid >= d) ? part[tid - d] : 0;
        __syncthreads();
        if (tid >= d) part[tid] += v;
        __syncthreads();
    }
    int run = (tid == 0) ? 0 : part[tid - 1];
#pragma unroll 4
    for (int k = 0; k < 32; k++) {
        off[base + k] = run;
        cur[base + k] = run;
        run += deg[base + k];
    }
    if (tid == 1023) off[NN] = run;
}

__global__ void fill_kernel(const int* __restrict__ src, const int* __restrict__ dst) {
    int e = blockIdx.x * blockDim.x + threadIdx.x;
    if (e < NE) {
        int s = src[e], d = dst[e];
        int p = atomicAdd(&g_cur_d[d], 1); g_eid_d[p] = s;
        int q = atomicAdd(&g_cur_s[s], 1); g_eid_s[q] = d;
    }
}

// ================= CSR mean-aggregate: one warp per node =================
// Pointers resolved in DEVICE code (never pass __device__ symbols from host!).
__global__ __launch_bounds__(256) void agg_kernel(int mode)
{
    const int* off; const int* eid; const float* feat; float* outp;
    if      (mode == 0) { off = g_off_d; eid = g_eid_d; feat = g_u;  outp = g_aggc; }
    else if (mode == 1) { off = g_off_s; eid = g_eid_s; feat = g_c;  outp = g_aggu; }
    else if (mode == 2) { off = g_off_d; eid = g_eid_d; feat = g_u2; outp = g_aggc; }
    else                { off = g_off_s; eid = g_eid_s; feat = g_c2; outp = g_aggu; }

    int n = blockIdx.x * 8 + (threadIdx.x >> 5);
    int lane = threadIdx.x & 31;
    int a = off[n], b = off[n + 1];

    float4 acc = make_float4(0.f, 0.f, 0.f, 0.f);
    const float4* f4 = (const float4*)feat;

    int i = a;
    for (; i + 4 <= b; i += 4) {
        int e0 = __ldg(&eid[i]),     e1 = __ldg(&eid[i + 1]);
        int e2 = __ldg(&eid[i + 2]), e3 = __ldg(&eid[i + 3]);
        float4 v0 = f4[e0 * 32 + lane];
        float4 v1 = f4[e1 * 32 + lane];
        float4 v2 = f4[e2 * 32 + lane];
        float4 v3 = f4[e3 * 32 + lane];
        acc.x += v0.x + v1.x + v2.x + v3.x;
        acc.y += v0.y + v1.y + v2.y + v3.y;
        acc.z += v0.z + v1.z + v2.z + v3.z;
        acc.w += v0.w + v1.w + v2.w + v3.w;
    }
    for (; i < b; i++) {
        int e0 = __ldg(&eid[i]);
        float4 v0 = f4[e0 * 32 + lane];
        acc.x += v0.x; acc.y += v0.y; acc.z += v0.z; acc.w += v0.w;
    }
    float inv = (b > a) ? 1.0f / (float)(b - a) : 1.0f;   // mean / max(cnt,1)
    acc.x *= inv; acc.y *= inv; acc.z *= inv; acc.w *= inv;
    ((float4*)outp)[n * 32 + lane] = acc;
}

// =====================================================================
// LSTM via tf32 mma.sync: per step, gates = [x_t | h] @ [W_ih | W_hh]^T.
// Block 512 thr, tile M=128 x N=256, K=192 in 6 chunks of 32, cp.async
// double-buffered. Warp grid 4x4, warp tile 32x64 (m16n8k8 frags).
// Smem row stride 36 floats -> all fragment LDS conflict-free.
// =====================================================================
#define GEMM_SMEM ((2 * 128 * 36 + 2 * 256 * 36) * 4)

__global__ void zero_h_kernel() {
    int i = blockIdx.x * 256 + threadIdx.x;
    ((float4*)g_u)[i] = make_float4(0.f, 0.f, 0.f, 0.f);
}

__device__ __forceinline__ void mma_tf32(float d[4], const unsigned a[4], const unsigned b[2]) {
    asm volatile(
        "mma.sync.aligned.m16n8k8.row.col.f32.tf32.tf32.f32 "
        "{%0,%1,%2,%3}, {%4,%5,%6,%7}, {%8,%9}, {%0,%1,%2,%3};"
        : "+f"(d[0]), "+f"(d[1]), "+f"(d[2]), "+f"(d[3])
        : "r"(a[0]), "r"(a[1]), "r"(a[2]), "r"(a[3]), "r"(b[0]), "r"(b[1]));
}

__global__ __launch_bounds__(512, 1) void lstm_gemm_kernel(
    const float* __restrict__ x_user,
    const float* __restrict__ W_ih, const float* __restrict__ W_hh, int t)
{
    extern __shared__ float smg[];
    float* Abuf[2] = { smg, smg + 128 * 36 };
    float* Bbuf[2] = { smg + 2 * 128 * 36, smg + 2 * 128 * 36 + 256 * 36 };

    int tid = threadIdx.x;
    int u0 = blockIdx.x * 128;
    int n0 = blockIdx.y * 256;

    // stage tile kt into buffer buf via cp.async (16B chunks, no transpose)
    auto issue_tile = [&](int kt, int buf) {
        int kbase = kt * 32;
#pragma unroll
        for (int i = 0; i < 2; i++) {       // A: 1024 chunks
            int idx = tid + i * 512;
            int u = idx >> 3, k4 = idx & 7;
            int k = kbase + k4 * 4;
            const float* srcp = (k < 64)
                ? x_user + ((size_t)(u0 + u) * TT + t) * EMBD + k
                : g_u + (size_t)(u0 + u) * HD + (k - 64);
            unsigned dst = (unsigned)__cvta_generic_to_shared(Abuf[buf] + u * 36 + k4 * 4);
            asm volatile("cp.async.ca.shared.global [%0], [%1], 16;" :: "r"(dst), "l"(srcp) : "memory");
        }
#pragma unroll
        for (int i = 0; i < 4; i++) {       // B: 2048 chunks
            int idx = tid + i * 512;
            int n = idx >> 3, k4 = idx & 7;
            int k = kbase + k4 * 4;
            const float* srcp = (k < 64)
                ? W_ih + (size_t)(n0 + n) * EMBD + k
                : W_hh + (size_t)(n0 + n) * HD + (k - 64);
            unsigned dst = (unsigned)__cvta_generic_to_shared(Bbuf[buf] + n * 36 + k4 * 4);
            asm volatile("cp.async.ca.shared.global [%0], [%1], 16;" :: "r"(dst), "l"(srcp) : "memory");
        }
        asm volatile("cp.async.commit_group;" ::: "memory");
    };

    issue_tile(0, 0);

    int wid = tid >> 5, lane = tid & 31;
    int wm = wid >> 2, wn = wid & 3;
    int urow = wm * 32, ncol = wn * 64;
    int lr = lane >> 2, lc = lane & 3;

    float acc[2][8][4];
#pragma unroll
    for (int fm = 0; fm < 2; fm++)
#pragma unroll
        for (int fn = 0; fn < 8; fn++)
#pragma unroll
            for (int r = 0; r < 4; r++) acc[fm][fn][r] = 0.f;

#pragma unroll 1
    for (int kt = 0; kt < 6; kt++) {
        int cur = kt & 1;
        if (kt < 5) {
            issue_tile(kt + 1, cur ^ 1);
            asm volatile("cp.async.wait_group 1;" ::: "memory");
        } else {
            asm volatile("cp.async.wait_group 0;" ::: "memory");
        }
        __syncthreads();

        const float* A = Abuf[cur];
        const float* B = Bbuf[cur];
#pragma unroll
        for (int k8 = 0; k8 < 4; k8++) {
            int k0 = k8 * 8;
            unsigned afr[2][4], bfr[8][2];
#pragma unroll
            for (int fm = 0; fm < 2; fm++) {
                int r = urow + fm * 16 + lr;
                afr[fm][0] = __float_as_uint(A[r * 36 + k0 + lc]);
                afr[fm][1] = __float_as_uint(A[(r + 8) * 36 + k0 + lc]);
                afr[fm][2] = __float_as_uint(A[r * 36 + k0 + 4 + lc]);
                afr[fm][3] = __float_as_uint(A[(r + 8) * 36 + k0 + 4 + lc]);
            }
#pragma unroll
            for (int fn = 0; fn < 8; fn++) {
                int n = ncol + fn * 8 + lr;
                bfr[fn][0] = __float_as_uint(B[n * 36 + k0 + lc]);
                bfr[fn][1] = __float_as_uint(B[n * 36 + k0 + 4 + lc]);
            }
#pragma unroll
            for (int fm = 0; fm < 2; fm++)
#pragma unroll
                for (int fn = 0; fn < 8; fn++)
                    mma_tf32(acc[fm][fn], afr[fm], bfr[fn]);
        }
        __syncthreads();
    }

    // epilogue: write preactivations (bias added in cell kernel)
#pragma unroll
    for (int fm = 0; fm < 2; fm++) {
#pragma unroll
        for (int fn = 0; fn < 8; fn++) {
            int r = u0 + urow + fm * 16 + lr;
            int cc = n0 + ncol + fn * 8 + lc * 2;
            *(float2*)&g_gates[(size_t)r * 512 + cc] =
                make_float2(acc[fm][fn][0], acc[fm][fn][1]);
            *(float2*)&g_gates[(size_t)(r + 8) * 512 + cc] =
                make_float2(acc[fm][fn][2], acc[fm][fn][3]);
        }
    }
}

// cell update: c = sig(f)*c + sig(i)*tanh(g); h = sig(o)*tanh(c)
__global__ __launch_bounds__(256) void lstm_cell_kernel(
    const float* __restrict__ b_ih, const float* __restrict__ b_hh, int step)
{
    int idx = blockIdx.x * 256 + threadIdx.x;   // grid = NN*HD/256
    int u = idx >> 7, m = idx & 127;
    size_t base = (size_t)u * 512;
    float gi = g_gates[base + m]       + b_ih[m]       + b_hh[m];
    float gf = g_gates[base + 128 + m] + b_ih[128 + m] + b_hh[128 + m];
    float gg = g_gates[base + 256 + m] + b_ih[256 + m] + b_hh[256 + m];
    float go = g_gates[base + 384 + m] + b_ih[384 + m] + b_hh[384 + m];
    float cold = (step == 0) ? 0.f : g_cstate[idx];
    float c = sigmoidf_(gf) * cold + sigmoidf_(gi) * tanhf(gg);
    g_cstate[idx] = c;
    g_u[idx] = sigmoidf_(go) * tanhf(c);
}

// ---------------- content linear: c = x_content @ Wc^T + bc ----------------
__global__ __launch_bounds__(256) void content_kernel(
    const float* __restrict__ xc, const float* __restrict__ Wc, const float* __restrict__ bc)
{
    __shared__ float4 Wc4s[128 * 17];
    __shared__ float4 xs[32 * 17];
    int tid = threadIdx.x;
    int n0 = blockIdx.x * 32;

    for (int idx = tid; idx < 128 * 16; idx += 256) {
        int r = idx >> 4, col = idx & 15;
        Wc4s[r * 17 + col] = ((const float4*)Wc)[idx];
    }
    for (int idx = tid; idx < 32 * 16; idx += 256) {
        int n = idx >> 4, k4 = idx & 15;
        xs[n * 17 + k4] = ((const float4*)xc)[(n0 + n) * 16 + k4];
    }
    __syncthreads();

    int n = tid >> 3, q = tid & 7;
    float acc[16];
#pragma unroll
    for (int i = 0; i < 16; i++) acc[i] = bc[q + 8 * i];
#pragma unroll 1
    for (int k4 = 0; k4 < 16; k4++) {
        float4 xv = xs[n * 17 + k4];
#pragma unroll
        for (int i = 0; i < 16; i++) {
            float4 wv = Wc4s[(q + 8 * i) * 17 + k4];
            DOT4(acc[i], wv, xv);
        }
    }
#pragma unroll
    for (int i = 0; i < 16; i++)
        g_c[(n0 + n) * HD + q + 8 * i] = acc[i];
}

// ---------------- SAGE combine: out = relu(mean @ Wl^T + bl + self @ Wr^T) ----------------
#define COMBINE_SMEM ((2 * 128 * 33 + 2 * 32 * 33) * 16)
__global__ __launch_bounds__(256) void combine_kernel(
    const float* __restrict__ Wl, const float* __restrict__ bl,
    const float* __restrict__ Wr, int mode)
{
    extern __shared__ float smc[];
    float4* Wl4 = (float4*)smc;          // 128 x 33
    float4* Wr4 = Wl4 + 128 * 33;
    float4* xm4 = Wr4 + 128 * 33;        // 32 x 33
    float4* xs4 = xm4 + 32 * 33;

    const float* agg; const float* selfx; float* outp;
    if      (mode == 0) { agg = g_aggc; selfx = g_c;  outp = g_c2; }
    else if (mode == 1) { agg = g_aggu; selfx = g_u;  outp = g_u2; }
    else if (mode == 2) { agg = g_aggc; selfx = g_c2; outp = g_c;  }
    else                { agg = g_aggu; selfx = g_u2; outp = g_u;  }

    int tid = threadIdx.x;
    int n0 = blockIdx.x * 32;

    for (int idx = tid; idx < 128 * 32; idx += 256) {
        int r = idx >> 5, col = idx & 31;
        Wl4[r * 33 + col] = ((const float4*)Wl)[idx];
        Wr4[r * 33 + col] = ((const float4*)Wr)[idx];
    }
    for (int idx = tid; idx < 32 * 32; idx += 256) {
        int n = idx >> 5, k4 = idx & 31;
        xm4[n * 33 + k4] = ((const float4*)agg)[(n0 + n) * 32 + k4];
        xs4[n * 33 + k4] = ((const float4*)selfx)[(n0 + n) * 32 + k4];
    }
    __syncthreads();

    int n = tid >> 3, q = tid & 7;
    float acc[16];
#pragma unroll
    for (int i = 0; i < 16; i++) acc[i] = bl[q + 8 * i];
#pragma unroll 1
    for (int k4 = 0; k4 < 32; k4++) {
        float4 xm = xm4[n * 33 + k4];
        float4 xv = xs4[n * 33 + k4];
#pragma unroll
        for (int i = 0; i < 16; i++) {
            int j = q + 8 * i;
            float4 wlv = Wl4[j * 33 + k4];
            float4 wrv = Wr4[j * 33 + k4];
            DOT4(acc[i], wlv, xm);
            DOT4(acc[i], wrv, xv);
        }
    }
#pragma unroll
    for (int i = 0; i < 16; i++)
        outp[(n0 + n) * HD + q + 8 * i] = fmaxf(acc[i], 0.f);
}

// ---------------- classifier ----------------
#define CLS_SMEM ((128 * 65 + 32 * 65) * 16 + 512)
__global__ __launch_bounds__(256) void classifier_kernel(
    const float* __restrict__ W1, const float* __restrict__ b1,
    const float* __restrict__ W2, const float* __restrict__ b2,
    float* __restrict__ out)
{
    extern __shared__ float smk[];
    float4* W14 = (float4*)smk;
    float4* xc4 = W14 + 128 * 65;
    float*  W2s = (float*)(xc4 + 32 * 65);

    int tid = threadIdx.x;
    int n0 = blockIdx.x * 32;

    for (int idx = tid; idx < 128 * 64; idx += 256) {
        int r = idx >> 6, col = idx & 63;
        W14[r * 65 + col] = ((const float4*)W1)[idx];
    }
    for (int idx = tid; idx < 32 * 64; idx += 256) {
        int n = idx >> 6, k4 = idx & 63;
        float4 v = (k4 < 32) ? ((const float4*)g_u)[(n0 + n) * 32 + k4]
                             : ((const float4*)g_c)[(n0 + n) * 32 + (k4 - 32)];
        xc4[n * 65 + k4] = v;
    }
    if (tid < 128) W2s[tid] = W2[tid];
    __syncthreads();

    int n = tid >> 3, q = tid & 7;
    float acc[16];
#pragma unroll
    for (int i = 0; i < 16; i++) acc[i] = b1[q + 8 * i];
#pragma unroll 1
    for (int k4 = 0; k4 < 64; k4++) {
        float4 xv = xc4[n * 65 + k4];
#pragma unroll
        for (int i = 0; i < 16; i++) {
            float4 wv = W14[(q + 8 * i) * 65 + k4];
            DOT4(acc[i], wv, xv);
        }
    }
    float p = 0.f;
#pragma unroll
    for (int i = 0; i < 16; i++) {
        float h = fmaxf(acc[i], 0.f);
        p += h * W2s[q + 8 * i];
    }
    p += __shfl_xor_sync(0xffffffffu, p, 1);
    p += __shfl_xor_sync(0xffffffffu, p, 2);
    p += __shfl_xor_sync(0xffffffffu, p, 4);
    if (q == 0) out[n0 + n] = sigmoidf_(p + b2[0]);
}

// ---------------- launch ----------------
extern "C" void kernel_launch(void* const* d_in, const int* in_sizes, int n_in,
                              void* d_out, int out_size)
{
    const float* x_user    = (const float*)d_in[0];
    const float* x_content = (const float*)d_in[1];
    const int*   edge      = (const int*)  d_in[2];
    const float* W_ih      = (const float*)d_in[3];
    const float* W_hh      = (const float*)d_in[4];
    const float* b_ih      = (const float*)d_in[5];
    const float* b_hh      = (const float*)d_in[6];
    const float* Wc        = (const float*)d_in[7];
    const float* bc        = (const float*)d_in[8];
    const float* Wl0       = (const float*)d_in[9];
    const float* bl0       = (const float*)d_in[10];
    const float* Wr0       = (const float*)d_in[11];
    const float* Wl1       = (const float*)d_in[12];
    const float* bl1       = (const float*)d_in[13];
    const float* Wr1       = (const float*)d_in[14];
    const float* W1        = (const float*)d_in[15];
    const float* b1        = (const float*)d_in[16];
    const float* W2        = (const float*)d_in[17];
    const float* b2        = (const float*)d_in[18];
    float* out = (float*)d_out;

    const int* src = edge;
    const int* dst = edge + NE;

    cudaFuncSetAttribute(lstm_gemm_kernel,  cudaFuncAttributeMaxDynamicSharedMemorySize, GEMM_SMEM);
    cudaFuncSetAttribute(combine_kernel,    cudaFuncAttributeMaxDynamicSharedMemorySize, COMBINE_SMEM);
    cudaFuncSetAttribute(classifier_kernel, cudaFuncAttributeMaxDynamicSharedMemorySize, CLS_SMEM);

    // ---- CSR build (per call; deterministic; graph-capturable) ----
    zero_deg_kernel<<<NN / 256, 256>>>();
    count_kernel<<<NE / 256, 256>>>(src, dst);
    scan_kernel<<<2, 1024>>>();
    fill_kernel<<<NE / 256, 256>>>(src, dst);

    // ---- LSTM: 20 steps of (tf32 GEMM -> cell update) ----
    zero_h_kernel<<<NN * HD / 4 / 256, 256>>>();   // h_0 = 0
    for (int t = 0; t < TT; t++) {
        lstm_gemm_kernel<<<dim3(NN / 128, 2), 512, GEMM_SMEM>>>(x_user, W_ih, W_hh, t);
        lstm_cell_kernel<<<NN * HD / 256, 256>>>(b_ih, b_hh, t);
    }

    // ---- content features ----
    content_kernel<<<NN / 32, 256>>>(x_content, Wc, bc);   // -> g_c

    // ---- SAGE layer 0 ----
    agg_kernel<<<NN / 8, 256>>>(0);   // mean of u[src] per dst -> g_aggc
    agg_kernel<<<NN / 8, 256>>>(1);   // mean of c[dst] per src -> g_aggu
    combine_kernel<<<NN / 32, 256, COMBINE_SMEM>>>(Wl0, bl0, Wr0, 0);   // -> g_c2
    combine_kernel<<<NN / 32, 256, COMBINE_SMEM>>>(Wl0, bl0, Wr0, 1);   // -> g_u2

    // ---- SAGE layer 1 ----
    agg_kernel<<<NN / 8, 256>>>(2);   // mean of u2[src] per dst -> g_aggc
    agg_kernel<<<NN / 8, 256>>>(3);   // mean of c2[dst] per src -> g_aggu
    combine_kernel<<<NN / 32, 256, COMBINE_SMEM>>>(Wl1, bl1, Wr1, 2);   // -> g_c
    combine_kernel<<<NN / 32, 256, COMBINE_SMEM>>>(Wl1, bl1, Wr1, 3);   // -> g_u

    // ---- classifier ----
    classifier_kernel<<<NN / 32, 256, CLS_SMEM>>>(W1, b1, W2, b2, out);
}

// round 12
// speedup vs baseline: 20.8659x; 1.0256x over previous
#include <cuda_runtime.h>
#include <math.h>

#define NN   32768
#define TT   20
#define EMBD 64
#define HD   128
#define NE   1048576   // NN * 32

// ---------------- scratch (static device globals; no allocations) ----------------
__device__ float g_u   [NN * HD];
__device__ float g_c   [NN * HD];
__device__ float g_u2  [NN * HD];
__device__ float g_c2  [NN * HD];
__device__ float g_aggc[NN * HD];   // holds MEAN directly
__device__ float g_aggu[NN * HD];   // holds MEAN directly
__device__ float g_cstate[NN * HD]; // LSTM cell state

// CSR scratch
__device__ int g_deg_d[NN];
__device__ int g_deg_s[NN];
__device__ int g_off_d[NN + 1];
__device__ int g_off_s[NN + 1];
__device__ int g_cur_d[NN];
__device__ int g_cur_s[NN];
__device__ int g_eid_d[NE];   // grouped by dst, stores src (user) ids
__device__ int g_eid_s[NE];   // grouped by src, stores dst (content) ids

__device__ __forceinline__ float sigmoidf_(float x) { return 1.0f / (1.0f + expf(-x)); }

#define DOT4(acc, A, B) (acc) += (A).x*(B).x + (A).y*(B).y + (A).z*(B).z + (A).w*(B).w

// ================= CSR build =================
__global__ void zero_deg_kernel() {
    int i = blockIdx.x * blockDim.x + threadIdx.x;
    if (i < NN) { g_deg_d[i] = 0; g_deg_s[i] = 0; }
}

__global__ void count_kernel(const int* __restrict__ src, const int* __restrict__ dst) {
    int e = blockIdx.x * blockDim.x + threadIdx.x;
    if (e < NE) {
        atomicAdd(&g_deg_d[dst[e]], 1);
        atomicAdd(&g_deg_s[src[e]], 1);
    }
}

// grid = 2 blocks x 1024 threads; block 0 scans deg_d -> off_d/cur_d, block 1 deg_s
__global__ __launch_bounds__(1024) void scan_kernel() {
    const int* deg = (blockIdx.x == 0) ? g_deg_d : g_deg_s;
    int* off = (blockIdx.x == 0) ? g_off_d : g_off_s;
    int* cur = (blockIdx.x == 0) ? g_cur_d : g_cur_s;

    __shared__ int part[1024];
    int tid = threadIdx.x;
    int base = tid * 32;

    int s = 0;
#pragma unroll 4
    for (int k = 0; k < 32; k++) s += deg[base + k];
    part[tid] = s;
    __syncthreads();
    for (int d = 1; d < 1024; d <<= 1) {
        int v = (tid >= d) ? part[tid - d] : 0;
        __syncthreads();
        if (tid >= d) part[tid] += v;
        __syncthreads();
    }
    int run = (tid == 0) ? 0 : part[tid - 1];
#pragma unroll 4
    for (int k = 0; k < 32; k++) {
        off[base + k] = run;
        cur[base + k] = run;
        run += deg[base + k];
    }
    if (tid == 1023) off[NN] = run;
}

__global__ void fill_kernel(const int* __restrict__ src, const int* __restrict__ dst) {
    int e = blockIdx.x * blockDim.x + threadIdx.x;
    if (e < NE) {
        int s = src[e], d = dst[e];
        int p = atomicAdd(&g_cur_d[d], 1); g_eid_d[p] = s;
        int q = atomicAdd(&g_cur_s[s], 1); g_eid_s[q] = d;
    }
}

// ================= CSR mean-aggregate: one warp per node =================
__global__ __launch_bounds__(256) void agg_kernel(int mode)
{
    const int* off; const int* eid; const float* feat; float* outp;
    if      (mode == 0) { off = g_off_d; eid = g_eid_d; feat = g_u;  outp = g_aggc; }
    else if (mode == 1) { off = g_off_s; eid = g_eid_s; feat = g_c;  outp = g_aggu; }
    else if (mode == 2) { off = g_off_d; eid = g_eid_d; feat = g_u2; outp = g_aggc; }
    else                { off = g_off_s; eid = g_eid_s; feat = g_c2; outp = g_aggu; }

    int n = blockIdx.x * 8 + (threadIdx.x >> 5);
    int lane = threadIdx.x & 31;
    int a = off[n], b = off[n + 1];

    float4 acc = make_float4(0.f, 0.f, 0.f, 0.f);
    const float4* f4 = (const float4*)feat;

    int i = a;
    for (; i + 4 <= b; i += 4) {
        int e0 = __ldg(&eid[i]),     e1 = __ldg(&eid[i + 1]);
        int e2 = __ldg(&eid[i + 2]), e3 = __ldg(&eid[i + 3]);
        float4 v0 = f4[e0 * 32 + lane];
        float4 v1 = f4[e1 * 32 + lane];
        float4 v2 = f4[e2 * 32 + lane];
        float4 v3 = f4[e3 * 32 + lane];
        acc.x += v0.x + v1.x + v2.x + v3.x;
        acc.y += v0.y + v1.y + v2.y + v3.y;
        acc.z += v0.z + v1.z + v2.z + v3.z;
        acc.w += v0.w + v1.w + v2.w + v3.w;
    }
    for (; i < b; i++) {
        int e0 = __ldg(&eid[i]);
        float4 v0 = f4[e0 * 32 + lane];
        acc.x += v0.x; acc.y += v0.y; acc.z += v0.z; acc.w += v0.w;
    }
    float inv = (b > a) ? 1.0f / (float)(b - a) : 1.0f;   // mean / max(cnt,1)
    acc.x *= inv; acc.y *= inv; acc.z *= inv; acc.w *= inv;
    ((float4*)outp)[n * 32 + lane] = acc;
}

// =====================================================================
// LSTM step, fully fused: tf32 GEMM + cell update in one kernel.
//  Grid (NN/128, 2): block y owns hidden units [y*64, (y+1)*64) for its
//  128 users, across ALL FOUR gates (weight rows permuted at load:
//  local n -> global row gate*128 + y*64 + (n&63)). Epilogue dumps the
//  128x256 acc tile to smem and performs the cell update in-block,
//  writing h directly to g_u (next step's GEMM reads it).
// =====================================================================
// mainloop: 2*128*36 + 2*256*36 = 27648 floats; epilogue: 256*133 = 34048 floats
#define GEMM_SMEM (34048 * 4)

__global__ void zero_h_kernel() {
    int i = blockIdx.x * 256 + threadIdx.x;
    ((float4*)g_u)[i] = make_float4(0.f, 0.f, 0.f, 0.f);
}

__device__ __forceinline__ void mma_tf32(float d[4], const unsigned a[4], const unsigned b[2]) {
    asm volatile(
        "mma.sync.aligned.m16n8k8.row.col.f32.tf32.tf32.f32 "
        "{%0,%1,%2,%3}, {%4,%5,%6,%7}, {%8,%9}, {%0,%1,%2,%3};"
        : "+f"(d[0]), "+f"(d[1]), "+f"(d[2]), "+f"(d[3])
        : "r"(a[0]), "r"(a[1]), "r"(a[2]), "r"(a[3]), "r"(b[0]), "r"(b[1]));
}

__global__ __launch_bounds__(512, 1) void lstm_step_kernel(
    const float* __restrict__ x_user,
    const float* __restrict__ W_ih, const float* __restrict__ W_hh,
    const float* __restrict__ b_ih, const float* __restrict__ b_hh, int t)
{
    extern __shared__ float smg[];
    float* Abuf[2] = { smg, smg + 128 * 36 };
    float* Bbuf[2] = { smg + 2 * 128 * 36, smg + 2 * 128 * 36 + 256 * 36 };
    __shared__ float bs[256];   // fused bias for this block's 256 gate rows

    int tid = threadIdx.x;
    int u0 = blockIdx.x * 128;
    int y  = blockIdx.y;        // hidden-half index

    // bias: local gate-col n -> global row gate*128 + y*64 + (n&63)
    if (tid < 256) {
        int gate = tid >> 6, w = tid & 63;
        int grow = gate * 128 + y * 64 + w;
        bs[tid] = b_ih[grow] + b_hh[grow];
    }

    // stage tile kt into buffer buf via cp.async (16B chunks)
    auto issue_tile = [&](int kt, int buf) {
        int kbase = kt * 32;
#pragma unroll
        for (int i = 0; i < 2; i++) {       // A: 1024 chunks
            int idx = tid + i * 512;
            int u = idx >> 3, k4 = idx & 7;
            int k = kbase + k4 * 4;
            const float* srcp = (k < 64)
                ? x_user + ((size_t)(u0 + u) * TT + t) * EMBD + k
                : g_u + (size_t)(u0 + u) * HD + (k - 64);
            unsigned dst = (unsigned)__cvta_generic_to_shared(Abuf[buf] + u * 36 + k4 * 4);
            asm volatile("cp.async.ca.shared.global [%0], [%1], 16;" :: "r"(dst), "l"(srcp) : "memory");
        }
#pragma unroll
        for (int i = 0; i < 4; i++) {       // B: 2048 chunks, permuted rows
            int idx = tid + i * 512;
            int n = idx >> 3, k4 = idx & 7;
            int k = kbase + k4 * 4;
            int gate = n >> 6, w = n & 63;
            int grow = gate * 128 + y * 64 + w;
            const float* srcp = (k < 64)
                ? W_ih + (size_t)grow * EMBD + k
                : W_hh + (size_t)grow * HD + (k - 64);
            unsigned dst = (unsigned)__cvta_generic_to_shared(Bbuf[buf] + n * 36 + k4 * 4);
            asm volatile("cp.async.ca.shared.global [%0], [%1], 16;" :: "r"(dst), "l"(srcp) : "memory");
        }
        asm volatile("cp.async.commit_group;" ::: "memory");
    };

    issue_tile(0, 0);

    int wid = tid >> 5, lane = tid & 31;
    int wm = wid >> 2, wn = wid & 3;
    int urow = wm * 32, ncol = wn * 64;
    int lr = lane >> 2, lc = lane & 3;

    float acc[2][8][4];
#pragma unroll
    for (int fm = 0; fm < 2; fm++)
#pragma unroll
        for (int fn = 0; fn < 8; fn++)
#pragma unroll
            for (int r = 0; r < 4; r++) acc[fm][fn][r] = 0.f;

#pragma unroll 1
    for (int kt = 0; kt < 6; kt++) {
        int cur = kt & 1;
        if (kt < 5) {
            issue_tile(kt + 1, cur ^ 1);
            asm volatile("cp.async.wait_group 1;" ::: "memory");
        } else {
            asm volatile("cp.async.wait_group 0;" ::: "memory");
        }
        __syncthreads();

        const float* A = Abuf[cur];
        const float* B = Bbuf[cur];
#pragma unroll
        for (int k8 = 0; k8 < 4; k8++) {
            int k0 = k8 * 8;
            unsigned afr[2][4], bfr[8][2];
#pragma unroll
            for (int fm = 0; fm < 2; fm++) {
                int r = urow + fm * 16 + lr;
                afr[fm][0] = __float_as_uint(A[r * 36 + k0 + lc]);
                afr[fm][1] = __float_as_uint(A[(r + 8) * 36 + k0 + lc]);
                afr[fm][2] = __float_as_uint(A[r * 36 + k0 + 4 + lc]);
                afr[fm][3] = __float_as_uint(A[(r + 8) * 36 + k0 + 4 + lc]);
            }
#pragma unroll
            for (int fn = 0; fn < 8; fn++) {
                int n = ncol + fn * 8 + lr;
                bfr[fn][0] = __float_as_uint(B[n * 36 + k0 + lc]);
                bfr[fn][1] = __float_as_uint(B[n * 36 + k0 + 4 + lc]);
            }
#pragma unroll
            for (int fm = 0; fm < 2; fm++)
#pragma unroll
                for (int fn = 0; fn < 8; fn++)
                    mma_tf32(acc[fm][fn], afr[fm], bfr[fn]);
        }
        __syncthreads();
    }

    // ---- epilogue: dump acc tile to smem S[n][r] (stride 133), then cell ----
    float* S = smg;   // reuse: 256*133 floats
#pragma unroll
    for (int fm = 0; fm < 2; fm++) {
#pragma unroll
        for (int fn = 0; fn < 8; fn++) {
            int r = urow + fm * 16 + lr;
            int cc = ncol + fn * 8 + lc * 2;
            S[cc * 133 + r]           = acc[fm][fn][0];
            S[(cc + 1) * 133 + r]     = acc[fm][fn][1];
            S[cc * 133 + r + 8]       = acc[fm][fn][2];
            S[(cc + 1) * 133 + r + 8] = acc[fm][fn][3];
        }
    }
    __syncthreads();

    // cell update: 128 users x 64 hidden = 8192 updates, 16 per thread
#pragma unroll
    for (int i = 0; i < 16; i++) {
        int flat = tid + i * 512;
        int r = flat >> 6, w = flat & 63;
        float gi = S[w * 133 + r]          + bs[w];
        float gf = S[(w + 64) * 133 + r]   + bs[64 + w];
        float gg = S[(w + 128) * 133 + r]  + bs[128 + w];
        float go = S[(w + 192) * 133 + r]  + bs[192 + w];
        size_t gidx = (size_t)(u0 + r) * HD + y * 64 + w;
        float cold = (t == 0) ? 0.f : g_cstate[gidx];
        float c = sigmoidf_(gf) * cold + sigmoidf_(gi) * tanhf(gg);
        g_cstate[gidx] = c;
        g_u[gidx] = sigmoidf_(go) * tanhf(c);
    }
}

// ---------------- content linear: c = x_content @ Wc^T + bc ----------------
__global__ __launch_bounds__(256) void content_kernel(
    const float* __restrict__ xc, const float* __restrict__ Wc, const float* __restrict__ bc)
{
    __shared__ float4 Wc4s[128 * 17];
    __shared__ float4 xs[32 * 17];
    int tid = threadIdx.x;
    int n0 = blockIdx.x * 32;

    for (int idx = tid; idx < 128 * 16; idx += 256) {
        int r = idx >> 4, col = idx & 15;
        Wc4s[r * 17 + col] = ((const float4*)Wc)[idx];
    }
    for (int idx = tid; idx < 32 * 16; idx += 256) {
        int n = idx >> 4, k4 = idx & 15;
        xs[n * 17 + k4] = ((const float4*)xc)[(n0 + n) * 16 + k4];
    }
    __syncthreads();

    int n = tid >> 3, q = tid & 7;
    float acc[16];
#pragma unroll
    for (int i = 0; i < 16; i++) acc[i] = bc[q + 8 * i];
#pragma unroll 1
    for (int k4 = 0; k4 < 16; k4++) {
        float4 xv = xs[n * 17 + k4];
#pragma unroll
        for (int i = 0; i < 16; i++) {
            float4 wv = Wc4s[(q + 8 * i) * 17 + k4];
            DOT4(acc[i], wv, xv);
        }
    }
#pragma unroll
    for (int i = 0; i < 16; i++)
        g_c[(n0 + n) * HD + q + 8 * i] = acc[i];
}

// ---------------- SAGE combine: out = relu(mean @ Wl^T + bl + self @ Wr^T) ----------------
#define COMBINE_SMEM ((2 * 128 * 33 + 2 * 32 * 33) * 16)
__global__ __launch_bounds__(256) void combine_kernel(
    const float* __restrict__ Wl, const float* __restrict__ bl,
    const float* __restrict__ Wr, int mode)
{
    extern __shared__ float smc[];
    float4* Wl4 = (float4*)smc;          // 128 x 33
    float4* Wr4 = Wl4 + 128 * 33;
    float4* xm4 = Wr4 + 128 * 33;        // 32 x 33
    float4* xs4 = xm4 + 32 * 33;

    const float* agg; const float* selfx; float* outp;
    if      (mode == 0) { agg = g_aggc; selfx = g_c;  outp = g_c2; }
    else if (mode == 1) { agg = g_aggu; selfx = g_u;  outp = g_u2; }
    else if (mode == 2) { agg = g_aggc; selfx = g_c2; outp = g_c;  }
    else                { agg = g_aggu; selfx = g_u2; outp = g_u;  }

    int tid = threadIdx.x;
    int n0 = blockIdx.x * 32;

    for (int idx = tid; idx < 128 * 32; idx += 256) {
        int r = idx >> 5, col = idx & 31;
        Wl4[r * 33 + col] = ((const float4*)Wl)[idx];
        Wr4[r * 33 + col] = ((const float4*)Wr)[idx];
    }
    for (int idx = tid; idx < 32 * 32; idx += 256) {
        int n = idx >> 5, k4 = idx & 31;
        xm4[n * 33 + k4] = ((const float4*)agg)[(n0 + n) * 32 + k4];
        xs4[n * 33 + k4] = ((const float4*)selfx)[(n0 + n) * 32 + k4];
    }
    __syncthreads();

    int n = tid >> 3, q = tid & 7;
    float acc[16];
#pragma unroll
    for (int i = 0; i < 16; i++) acc[i] = bl[q + 8 * i];
#pragma unroll 1
    for (int k4 = 0; k4 < 32; k4++) {
        float4 xm = xm4[n * 33 + k4];
        float4 xv = xs4[n * 33 + k4];
#pragma unroll
        for (int i = 0; i < 16; i++) {
            int j = q + 8 * i;
            float4 wlv = Wl4[j * 33 + k4];
            float4 wrv = Wr4[j * 33 + k4];
            DOT4(acc[i], wlv, xm);
            DOT4(acc[i], wrv, xv);
        }
    }
#pragma unroll
    for (int i = 0; i < 16; i++)
        outp[(n0 + n) * HD + q + 8 * i] = fmaxf(acc[i], 0.f);
}

// ---------------- classifier ----------------
#define CLS_SMEM ((128 * 65 + 32 * 65) * 16 + 512)
__global__ __launch_bounds__(256) void classifier_kernel(
    const float* __restrict__ W1, const float* __restrict__ b1,
    const float* __restrict__ W2, const float* __restrict__ b2,
    float* __restrict__ out)
{
    extern __shared__ float smk[];
    float4* W14 = (float4*)smk;
    float4* xc4 = W14 + 128 * 65;
    float*  W2s = (float*)(xc4 + 32 * 65);

    int tid = threadIdx.x;
    int n0 = blockIdx.x * 32;

    for (int idx = tid; idx < 128 * 64; idx += 256) {
        int r = idx >> 6, col = idx & 63;
        W14[r * 65 + col] = ((const float4*)W1)[idx];
    }
    for (int idx = tid; idx < 32 * 64; idx += 256) {
        int n = idx >> 6, k4 = idx & 63;
        float4 v = (k4 < 32) ? ((const float4*)g_u)[(n0 + n) * 32 + k4]
                             : ((const float4*)g_c)[(n0 + n) * 32 + (k4 - 32)];
        xc4[n * 65 + k4] = v;
    }
    if (tid < 128) W2s[tid] = W2[tid];
    __syncthreads();

    int n = tid >> 3, q = tid & 7;
    float acc[16];
#pragma unroll
    for (int i = 0; i < 16; i++) acc[i] = b1[q + 8 * i];
#pragma unroll 1
    for (int k4 = 0; k4 < 64; k4++) {
        float4 xv = xc4[n * 65 + k4];
#pragma unroll
        for (int i = 0; i < 16; i++) {
            float4 wv = W14[(q + 8 * i) * 65 + k4];
            DOT4(acc[i], wv, xv);
        }
    }
    float p = 0.f;
#pragma unroll
    for (int i = 0; i < 16; i++) {
        float h = fmaxf(acc[i], 0.f);
        p += h * W2s[q + 8 * i];
    }
    p += __shfl_xor_sync(0xffffffffu, p, 1);
    p += __shfl_xor_sync(0xffffffffu, p, 2);
    p += __shfl_xor_sync(0xffffffffu, p, 4);
    if (q == 0) out[n0 + n] = sigmoidf_(p + b2[0]);
}

// ---------------- launch ----------------
extern "C" void kernel_launch(void* const* d_in, const int* in_sizes, int n_in,
                              void* d_out, int out_size)
{
    const float* x_user    = (const float*)d_in[0];
    const float* x_content = (const float*)d_in[1];
    const int*   edge      = (const int*)  d_in[2];
    const float* W_ih      = (const float*)d_in[3];
    const float* W_hh      = (const float*)d_in[4];
    const float* b_ih      = (const float*)d_in[5];
    const float* b_hh      = (const float*)d_in[6];
    const float* Wc        = (const float*)d_in[7];
    const float* bc        = (const float*)d_in[8];
    const float* Wl0       = (const float*)d_in[9];
    const float* bl0       = (const float*)d_in[10];
    const float* Wr0       = (const float*)d_in[11];
    const float* Wl1       = (const float*)d_in[12];
    const float* bl1       = (const float*)d_in[13];
    const float* Wr1       = (const float*)d_in[14];
    const float* W1        = (const float*)d_in[15];
    const float* b1        = (const float*)d_in[16];
    const float* W2        = (const float*)d_in[17];
    const float* b2        = (const float*)d_in[18];
    float* out = (float*)d_out;

    const int* src = edge;
    const int* dst = edge + NE;

    cudaFuncSetAttribute(lstm_step_kernel,  cudaFuncAttributeMaxDynamicSharedMemorySize, GEMM_SMEM);
    cudaFuncSetAttribute(combine_kernel,    cudaFuncAttributeMaxDynamicSharedMemorySize, COMBINE_SMEM);
    cudaFuncSetAttribute(classifier_kernel, cudaFuncAttributeMaxDynamicSharedMemorySize, CLS_SMEM);

    // ---- CSR build (per call; deterministic; graph-capturable) ----
    zero_deg_kernel<<<NN / 256, 256>>>();
    count_kernel<<<NE / 256, 256>>>(src, dst);
    scan_kernel<<<2, 1024>>>();
    fill_kernel<<<NE / 256, 256>>>(src, dst);

    // ---- LSTM: 20 fused (tf32 GEMM + cell) steps ----
    zero_h_kernel<<<NN * HD / 4 / 256, 256>>>();   // h_0 = 0
    for (int t = 0; t < TT; t++)
        lstm_step_kernel<<<dim3(NN / 128, 2), 512, GEMM_SMEM>>>(
            x_user, W_ih, W_hh, b_ih, b_hh, t);

    // ---- content features ----
    content_kernel<<<NN / 32, 256>>>(x_content, Wc, bc);   // -> g_c

    // ---- SAGE layer 0 ----
    agg_kernel<<<NN / 8, 256>>>(0);   // mean of u[src] per dst -> g_aggc
    agg_kernel<<<NN / 8, 256>>>(1);   // mean of c[dst] per src -> g_aggu
    combine_kernel<<<NN / 32, 256, COMBINE_SMEM>>>(Wl0, bl0, Wr0, 0);   // -> g_c2
    combine_kernel<<<NN / 32, 256, COMBINE_SMEM>>>(Wl0, bl0, Wr0, 1);   // -> g_u2

    // ---- SAGE layer 1 ----
    agg_kernel<<<NN / 8, 256>>>(2);   // mean of u2[src] per dst -> g_aggc
    agg_kernel<<<NN / 8, 256>>>(3);   // mean of c2[dst] per src -> g_aggu
    combine_kernel<<<NN / 32, 256, COMBINE_SMEM>>>(Wl1, bl1, Wr1, 2);   // -> g_c
    combine_kernel<<<NN / 32, 256, COMBINE_SMEM>>>(Wl1, bl1, Wr1, 3);   // -> g_u

    // ---- classifier ----
    classifier_kernel<<<NN / 32, 256, CLS_SMEM>>>(W1, b1, W2, b2, out);
}

// round 13
// speedup vs baseline: 21.2157x; 1.0168x over previous
#include <cuda_runtime.h>
#include <math.h>

#define NN   32768
#define TT   20
#define EMBD 64
#define HD   128
#define NE   1048576   // NN * 32

// ---------------- scratch (static device globals; no allocations) ----------------
__device__ float g_u   [NN * HD];
__device__ float g_c   [NN * HD];
__device__ float g_u2  [NN * HD];
__device__ float g_c2  [NN * HD];
__device__ float g_aggc[NN * HD];   // holds MEAN directly
__device__ float g_aggu[NN * HD];   // holds MEAN directly
__device__ float g_cstate[NN * HD]; // LSTM cell state

// CSR scratch
__device__ int g_deg_d[NN];
__device__ int g_deg_s[NN];
__device__ int g_off_d[NN + 1];
__device__ int g_off_s[NN + 1];
__device__ int g_cur_d[NN];
__device__ int g_cur_s[NN];
__device__ int g_eid_d[NE];   // grouped by dst, stores src (user) ids
__device__ int g_eid_s[NE];   // grouped by src, stores dst (content) ids

__device__ __forceinline__ float sigmoidf_(float x) { return 1.0f / (1.0f + expf(-x)); }

#define DOT4(acc, A, B) (acc) += (A).x*(B).x + (A).y*(B).y + (A).z*(B).z + (A).w*(B).w

// ================= CSR build =================
__global__ void zero_deg_kernel() {
    int i = blockIdx.x * blockDim.x + threadIdx.x;
    if (i < NN) { g_deg_d[i] = 0; g_deg_s[i] = 0; }
}

__global__ void count_kernel(const int* __restrict__ src, const int* __restrict__ dst) {
    int e = blockIdx.x * blockDim.x + threadIdx.x;
    if (e < NE) {
        atomicAdd(&g_deg_d[dst[e]], 1);
        atomicAdd(&g_deg_s[src[e]], 1);
    }
}

__global__ __launch_bounds__(1024) void scan_kernel() {
    const int* deg = (blockIdx.x == 0) ? g_deg_d : g_deg_s;
    int* off = (blockIdx.x == 0) ? g_off_d : g_off_s;
    int* cur = (blockIdx.x == 0) ? g_cur_d : g_cur_s;

    __shared__ int part[1024];
    int tid = threadIdx.x;
    int base = tid * 32;

    int s = 0;
#pragma unroll 4
    for (int k = 0; k < 32; k++) s += deg[base + k];
    part[tid] = s;
    __syncthreads();
    for (int d = 1; d < 1024; d <<= 1) {
        int v = (tid >= d) ? part[tid - d] : 0;
        __syncthreads();
        if (tid >= d) part[tid] += v;
        __syncthreads();
    }
    int run = (tid == 0) ? 0 : part[tid - 1];
#pragma unroll 4
    for (int k = 0; k < 32; k++) {
        off[base + k] = run;
        cur[base + k] = run;
        run += deg[base + k];
    }
    if (tid == 1023) off[NN] = run;
}

__global__ void fill_kernel(const int* __restrict__ src, const int* __restrict__ dst) {
    int e = blockIdx.x * blockDim.x + threadIdx.x;
    if (e < NE) {
        int s = src[e], d = dst[e];
        int p = atomicAdd(&g_cur_d[d], 1); g_eid_d[p] = s;
        int q = atomicAdd(&g_cur_s[s], 1); g_eid_s[q] = d;
    }
}

// ================= CSR mean-aggregate: one warp per node =================
__global__ __launch_bounds__(256) void agg_kernel(int mode)
{
    const int* off; const int* eid; const float* feat; float* outp;
    if      (mode == 0) { off = g_off_d; eid = g_eid_d; feat = g_u;  outp = g_aggc; }
    else if (mode == 1) { off = g_off_s; eid = g_eid_s; feat = g_c;  outp = g_aggu; }
    else if (mode == 2) { off = g_off_d; eid = g_eid_d; feat = g_u2; outp = g_aggc; }
    else                { off = g_off_s; eid = g_eid_s; feat = g_c2; outp = g_aggu; }

    int n = blockIdx.x * 8 + (threadIdx.x >> 5);
    int lane = threadIdx.x & 31;
    int a = off[n], b = off[n + 1];

    float4 acc = make_float4(0.f, 0.f, 0.f, 0.f);
    const float4* f4 = (const float4*)feat;

    int i = a;
    for (; i + 4 <= b; i += 4) {
        int e0 = __ldg(&eid[i]),     e1 = __ldg(&eid[i + 1]);
        int e2 = __ldg(&eid[i + 2]), e3 = __ldg(&eid[i + 3]);
        float4 v0 = f4[e0 * 32 + lane];
        float4 v1 = f4[e1 * 32 + lane];
        float4 v2 = f4[e2 * 32 + lane];
        float4 v3 = f4[e3 * 32 + lane];
        acc.x += v0.x + v1.x + v2.x + v3.x;
        acc.y += v0.y + v1.y + v2.y + v3.y;
        acc.z += v0.z + v1.z + v2.z + v3.z;
        acc.w += v0.w + v1.w + v2.w + v3.w;
    }
    for (; i < b; i++) {
        int e0 = __ldg(&eid[i]);
        float4 v0 = f4[e0 * 32 + lane];
        acc.x += v0.x; acc.y += v0.y; acc.z += v0.z; acc.w += v0.w;
    }
    float inv = (b > a) ? 1.0f / (float)(b - a) : 1.0f;
    acc.x *= inv; acc.y *= inv; acc.z *= inv; acc.w *= inv;
    ((float4*)outp)[n * 32 + lane] = acc;
}

// =====================================================================
// LSTM step, fused tf32 GEMM + cell, OCCUPANCY-2 VERSION.
//  Grid (NN/128, 4), 256 threads, __launch_bounds__(256,2).
//  Block (x,y): users [x*128,(x+1)*128), hidden units [y*32,(y+1)*32)
//  across all 4 gates (local col n -> global weight row gate*128+y*32+(n&31)).
//  Tile 128x128, K=192 in 12 chunks of 16, cp.async double-buffered.
//  Smem: mainloop 2*(128*20)*2 = 40KB; epilogue reuses it (two 64-row passes).
// =====================================================================
#define GEMM_SMEM (10240 * 4)   // 40 KB

__global__ void zero_h_kernel() {
    int i = blockIdx.x * 256 + threadIdx.x;
    ((float4*)g_u)[i] = make_float4(0.f, 0.f, 0.f, 0.f);
}

__device__ __forceinline__ void mma_tf32(float d[4], const unsigned a[4], const unsigned b[2]) {
    asm volatile(
        "mma.sync.aligned.m16n8k8.row.col.f32.tf32.tf32.f32 "
        "{%0,%1,%2,%3}, {%4,%5,%6,%7}, {%8,%9}, {%0,%1,%2,%3};"
        : "+f"(d[0]), "+f"(d[1]), "+f"(d[2]), "+f"(d[3])
        : "r"(a[0]), "r"(a[1]), "r"(a[2]), "r"(a[3]), "r"(b[0]), "r"(b[1]));
}

__global__ __launch_bounds__(256, 2) void lstm_step_kernel(
    const float* __restrict__ x_user,
    const float* __restrict__ W_ih, const float* __restrict__ W_hh,
    const float* __restrict__ b_ih, const float* __restrict__ b_hh, int t)
{
    extern __shared__ float smg[];
    float* Abuf[2] = { smg, smg + 128 * 20 };
    float* Bbuf[2] = { smg + 2 * 128 * 20, smg + 2 * 128 * 20 + 128 * 20 };
    __shared__ float bs[128];

    int tid = threadIdx.x;
    int u0 = blockIdx.x * 128;
    int y  = blockIdx.y;        // hidden quarter: units y*32..y*32+31

    if (tid < 128) {
        int gate = tid >> 5, w = tid & 31;
        int grow = gate * 128 + y * 32 + w;
        bs[tid] = b_ih[grow] + b_hh[grow];
    }

    // stage K-chunk kt (16 floats per row) into buffer buf
    auto issue_tile = [&](int kt, int buf) {
        int kbase = kt * 16;
#pragma unroll
        for (int i = 0; i < 2; i++) {       // A: 512 chunks of 16B
            int idx = tid + i * 256;
            int u = idx >> 2, k4 = idx & 3;
            int k = kbase + k4 * 4;
            const float* srcp = (k < 64)
                ? x_user + ((size_t)(u0 + u) * TT + t) * EMBD + k
                : g_u + (size_t)(u0 + u) * HD + (k - 64);
            unsigned dst = (unsigned)__cvta_generic_to_shared(Abuf[buf] + u * 20 + k4 * 4);
            asm volatile("cp.async.ca.shared.global [%0], [%1], 16;" :: "r"(dst), "l"(srcp) : "memory");
        }
#pragma unroll
        for (int i = 0; i < 2; i++) {       // B: 512 chunks, permuted rows
            int idx = tid + i * 256;
            int n = idx >> 2, k4 = idx & 3;
            int k = kbase + k4 * 4;
            int gate = n >> 5, w = n & 31;
            int grow = gate * 128 + y * 32 + w;
            const float* srcp = (k < 64)
                ? W_ih + (size_t)grow * EMBD + k
                : W_hh + (size_t)grow * HD + (k - 64);
            unsigned dst = (unsigned)__cvta_generic_to_shared(Bbuf[buf] + n * 20 + k4 * 4);
            asm volatile("cp.async.ca.shared.global [%0], [%1], 16;" :: "r"(dst), "l"(srcp) : "memory");
        }
        asm volatile("cp.async.commit_group;" ::: "memory");
    };

    issue_tile(0, 0);

    int wid = tid >> 5, lane = tid & 31;
    int wm = wid >> 1, wn = wid & 1;     // warp grid 4(M) x 2(N)
    int urow = wm * 32, ncol = wn * 64;
    int lr = lane >> 2, lc = lane & 3;

    float acc[2][8][4];
#pragma unroll
    for (int fm = 0; fm < 2; fm++)
#pragma unroll
        for (int fn = 0; fn < 8; fn++)
#pragma unroll
            for (int r = 0; r < 4; r++) acc[fm][fn][r] = 0.f;

#pragma unroll 1
    for (int kt = 0; kt < 12; kt++) {
        int cur = kt & 1;
        if (kt < 11) {
            issue_tile(kt + 1, cur ^ 1);
            asm volatile("cp.async.wait_group 1;" ::: "memory");
        } else {
            asm volatile("cp.async.wait_group 0;" ::: "memory");
        }
        __syncthreads();

        const float* A = Abuf[cur];
        const float* B = Bbuf[cur];
#pragma unroll
        for (int k8 = 0; k8 < 2; k8++) {
            int k0 = k8 * 8;
            unsigned afr[2][4], bfr[8][2];
#pragma unroll
            for (int fm = 0; fm < 2; fm++) {
                int r = urow + fm * 16 + lr;
                afr[fm][0] = __float_as_uint(A[r * 20 + k0 + lc]);
                afr[fm][1] = __float_as_uint(A[(r + 8) * 20 + k0 + lc]);
                afr[fm][2] = __float_as_uint(A[r * 20 + k0 + 4 + lc]);
                afr[fm][3] = __float_as_uint(A[(r + 8) * 20 + k0 + 4 + lc]);
            }
#pragma unroll
            for (int fn = 0; fn < 8; fn++) {
                int n = ncol + fn * 8 + lr;
                bfr[fn][0] = __float_as_uint(B[n * 20 + k0 + lc]);
                bfr[fn][1] = __float_as_uint(B[n * 20 + k0 + 4 + lc]);
            }
#pragma unroll
            for (int fm = 0; fm < 2; fm++)
#pragma unroll
                for (int fn = 0; fn < 8; fn++)
                    mma_tf32(acc[fm][fn], afr[fm], bfr[fn]);
        }
        __syncthreads();
    }

    // ---- epilogue: two 64-row passes through smem, then cell update ----
    float* S = smg;   // [128 cols][stride 69], 8832 floats <= 10240
#pragma unroll 1
    for (int p = 0; p < 2; p++) {
        if ((wm >> 1) == p) {                 // warps wm in {2p, 2p+1}
            int rbase = urow - p * 64;        // in [0, 32]
#pragma unroll
            for (int fm = 0; fm < 2; fm++) {
#pragma unroll
                for (int fn = 0; fn < 8; fn++) {
                    int rr = rbase + fm * 16 + lr;
                    int cc = ncol + fn * 8 + lc * 2;
                    S[cc * 69 + rr]           = acc[fm][fn][0];
                    S[(cc + 1) * 69 + rr]     = acc[fm][fn][1];
                    S[cc * 69 + rr + 8]       = acc[fm][fn][2];
                    S[(cc + 1) * 69 + rr + 8] = acc[fm][fn][3];
                }
            }
        }
        __syncthreads();

        // 64 users x 32 hidden = 2048 updates, 8 per thread
#pragma unroll
        for (int i = 0; i < 8; i++) {
            int flat = tid + i * 256;
            int rr = flat >> 5, w = flat & 31;
            float gi = S[w * 69 + rr]          + bs[w];
            float gf = S[(w + 32) * 69 + rr]   + bs[32 + w];
            float gg = S[(w + 64) * 69 + rr]   + bs[64 + w];
            float go = S[(w + 96) * 69 + rr]   + bs[96 + w];
            size_t gidx = (size_t)(u0 + p * 64 + rr) * HD + y * 32 + w;
            float cold = (t == 0) ? 0.f : g_cstate[gidx];
            float c = sigmoidf_(gf) * cold + sigmoidf_(gi) * tanhf(gg);
            g_cstate[gidx] = c;
            g_u[gidx] = sigmoidf_(go) * tanhf(c);
        }
        __syncthreads();
    }
}

// ---------------- content linear: c = x_content @ Wc^T + bc ----------------
__global__ __launch_bounds__(256) void content_kernel(
    const float* __restrict__ xc, const float* __restrict__ Wc, const float* __restrict__ bc)
{
    __shared__ float4 Wc4s[128 * 17];
    __shared__ float4 xs[32 * 17];
    int tid = threadIdx.x;
    int n0 = blockIdx.x * 32;

    for (int idx = tid; idx < 128 * 16; idx += 256) {
        int r = idx >> 4, col = idx & 15;
        Wc4s[r * 17 + col] = ((const float4*)Wc)[idx];
    }
    for (int idx = tid; idx < 32 * 16; idx += 256) {
        int n = idx >> 4, k4 = idx & 15;
        xs[n * 17 + k4] = ((const float4*)xc)[(n0 + n) * 16 + k4];
    }
    __syncthreads();

    int n = tid >> 3, q = tid & 7;
    float acc[16];
#pragma unroll
    for (int i = 0; i < 16; i++) acc[i] = bc[q + 8 * i];
#pragma unroll 1
    for (int k4 = 0; k4 < 16; k4++) {
        float4 xv = xs[n * 17 + k4];
#pragma unroll
        for (int i = 0; i < 16; i++) {
            float4 wv = Wc4s[(q + 8 * i) * 17 + k4];
            DOT4(acc[i], wv, xv);
        }
    }
#pragma unroll
    for (int i = 0; i < 16; i++)
        g_c[(n0 + n) * HD + q + 8 * i] = acc[i];
}

// ---------------- SAGE combine: out = relu(mean @ Wl^T + bl + self @ Wr^T) ----------------
#define COMBINE_SMEM ((2 * 128 * 33 + 2 * 32 * 33) * 16)
__global__ __launch_bounds__(256) void combine_kernel(
    const float* __restrict__ Wl, const float* __restrict__ bl,
    const float* __restrict__ Wr, int mode)
{
    extern __shared__ float smc[];
    float4* Wl4 = (float4*)smc;          // 128 x 33
    float4* Wr4 = Wl4 + 128 * 33;
    float4* xm4 = Wr4 + 128 * 33;        // 32 x 33
    float4* xs4 = xm4 + 32 * 33;

    const float* agg; const float* selfx; float* outp;
    if      (mode == 0) { agg = g_aggc; selfx = g_c;  outp = g_c2; }
    else if (mode == 1) { agg = g_aggu; selfx = g_u;  outp = g_u2; }
    else if (mode == 2) { agg = g_aggc; selfx = g_c2; outp = g_c;  }
    else                { agg = g_aggu; selfx = g_u2; outp = g_u;  }

    int tid = threadIdx.x;
    int n0 = blockIdx.x * 32;

    for (int idx = tid; idx < 128 * 32; idx += 256) {
        int r = idx >> 5, col = idx & 31;
        Wl4[r * 33 + col] = ((const float4*)Wl)[idx];
        Wr4[r * 33 + col] = ((const float4*)Wr)[idx];
    }
    for (int idx = tid; idx < 32 * 32; idx += 256) {
        int n = idx >> 5, k4 = idx & 31;
        xm4[n * 33 + k4] = ((const float4*)agg)[(n0 + n) * 32 + k4];
        xs4[n * 33 + k4] = ((const float4*)selfx)[(n0 + n) * 32 + k4];
    }
    __syncthreads();

    int n = tid >> 3, q = tid & 7;
    float acc[16];
#pragma unroll
    for (int i = 0; i < 16; i++) acc[i] = bl[q + 8 * i];
#pragma unroll 1
    for (int k4 = 0; k4 < 32; k4++) {
        float4 xm = xm4[n * 33 + k4];
        float4 xv = xs4[n * 33 + k4];
#pragma unroll
        for (int i = 0; i < 16; i++) {
            int j = q + 8 * i;
            float4 wlv = Wl4[j * 33 + k4];
            float4 wrv = Wr4[j * 33 + k4];
            DOT4(acc[i], wlv, xm);
            DOT4(acc[i], wrv, xv);
        }
    }
#pragma unroll
    for (int i = 0; i < 16; i++)
        outp[(n0 + n) * HD + q + 8 * i] = fmaxf(acc[i], 0.f);
}

// ---------------- classifier ----------------
#define CLS_SMEM ((128 * 65 + 32 * 65) * 16 + 512)
__global__ __launch_bounds__(256) void classifier_kernel(
    const float* __restrict__ W1, const float* __restrict__ b1,
    const float* __restrict__ W2, const float* __restrict__ b2,
    float* __restrict__ out)
{
    extern __shared__ float smk[];
    float4* W14 = (float4*)smk;
    float4* xc4 = W14 + 128 * 65;
    float*  W2s = (float*)(xc4 + 32 * 65);

    int tid = threadIdx.x;
    int n0 = blockIdx.x * 32;

    for (int idx = tid; idx < 128 * 64; idx += 256) {
        int r = idx >> 6, col = idx & 63;
        W14[r * 65 + col] = ((const float4*)W1)[idx];
    }
    for (int idx = tid; idx < 32 * 64; idx += 256) {
        int n = idx >> 6, k4 = idx & 63;
        float4 v = (k4 < 32) ? ((const float4*)g_u)[(n0 + n) * 32 + k4]
                             : ((const float4*)g_c)[(n0 + n) * 32 + (k4 - 32)];
        xc4[n * 65 + k4] = v;
    }
    if (tid < 128) W2s[tid] = W2[tid];
    __syncthreads();

    int n = tid >> 3, q = tid & 7;
    float acc[16];
#pragma unroll
    for (int i = 0; i < 16; i++) acc[i] = b1[q + 8 * i];
#pragma unroll 1
    for (int k4 = 0; k4 < 64; k4++) {
        float4 xv = xc4[n * 65 + k4];
#pragma unroll
        for (int i = 0; i < 16; i++) {
            float4 wv = W14[(q + 8 * i) * 65 + k4];
            DOT4(acc[i], wv, xv);
        }
    }
    float p = 0.f;
#pragma unroll
    for (int i = 0; i < 16; i++) {
        float h = fmaxf(acc[i], 0.f);
        p += h * W2s[q + 8 * i];
    }
    p += __shfl_xor_sync(0xffffffffu, p, 1);
    p += __shfl_xor_sync(0xffffffffu, p, 2);
    p += __shfl_xor_sync(0xffffffffu, p, 4);
    if (q == 0) out[n0 + n] = sigmoidf_(p + b2[0]);
}

// ---------------- launch ----------------
extern "C" void kernel_launch(void* const* d_in, const int* in_sizes, int n_in,
                              void* d_out, int out_size)
{
    const float* x_user    = (const float*)d_in[0];
    const float* x_content = (const float*)d_in[1];
    const int*   edge      = (const int*)  d_in[2];
    const float* W_ih      = (const float*)d_in[3];
    const float* W_hh      = (const float*)d_in[4];
    const float* b_ih      = (const float*)d_in[5];
    const float* b_hh      = (const float*)d_in[6];
    const float* Wc        = (const float*)d_in[7];
    const float* bc        = (const float*)d_in[8];
    const float* Wl0       = (const float*)d_in[9];
    const float* bl0       = (const float*)d_in[10];
    const float* Wr0       = (const float*)d_in[11];
    const float* Wl1       = (const float*)d_in[12];
    const float* bl1       = (const float*)d_in[13];
    const float* Wr1       = (const float*)d_in[14];
    const float* W1        = (const float*)d_in[15];
    const float* b1        = (const float*)d_in[16];
    const float* W2        = (const float*)d_in[17];
    const float* b2        = (const float*)d_in[18];
    float* out = (float*)d_out;

    const int* src = edge;
    const int* dst = edge + NE;

    cudaFuncSetAttribute(lstm_step_kernel,  cudaFuncAttributeMaxDynamicSharedMemorySize, GEMM_SMEM);
    cudaFuncSetAttribute(combine_kernel,    cudaFuncAttributeMaxDynamicSharedMemorySize, COMBINE_SMEM);
    cudaFuncSetAttribute(classifier_kernel, cudaFuncAttributeMaxDynamicSharedMemorySize, CLS_SMEM);

    // ---- LSTM first (so ncu's fixed capture slot lands on lstm_step) ----
    zero_h_kernel<<<NN * HD / 4 / 256, 256>>>();   // h_0 = 0
    for (int t = 0; t < TT; t++)
        lstm_step_kernel<<<dim3(NN / 128, 4), 256, GEMM_SMEM>>>(
            x_user, W_ih, W_hh, b_ih, b_hh, t);

    // ---- content features ----
    content_kernel<<<NN / 32, 256>>>(x_content, Wc, bc);   // -> g_c

    // ---- CSR build (independent of LSTM; needed before aggs) ----
    zero_deg_kernel<<<NN / 256, 256>>>();
    count_kernel<<<NE / 256, 256>>>(src, dst);
    scan_kernel<<<2, 1024>>>();
    fill_kernel<<<NE / 256, 256>>>(src, dst);

    // ---- SAGE layer 0 ----
    agg_kernel<<<NN / 8, 256>>>(0);
    agg_kernel<<<NN / 8, 256>>>(1);
    combine_kernel<<<NN / 32, 256, COMBINE_SMEM>>>(Wl0, bl0, Wr0, 0);   // -> g_c2
    combine_kernel<<<NN / 32, 256, COMBINE_SMEM>>>(Wl0, bl0, Wr0, 1);   // -> g_u2

    // ---- SAGE layer 1 ----
    agg_kernel<<<NN / 8, 256>>>(2);
    agg_kernel<<<NN / 8, 256>>>(3);
    combine_kernel<<<NN / 32, 256, COMBINE_SMEM>>>(Wl1, bl1, Wr1, 2);   // -> g_c
    combine_kernel<<<NN / 32, 256, COMBINE_SMEM>>>(Wl1, bl1, Wr1, 3);   // -> g_u

    // ---- classifier ----
    classifier_kernel<<<NN / 32, 256, CLS_SMEM>>>(W1, b1, W2, b2, out);
}

// round 14
// speedup vs baseline: 22.2920x; 1.0507x over previous
#include <cuda_runtime.h>
#include <math.h>

#define NN   32768
#define TT   20
#define EMBD 64
#define HD   128
#define NE   1048576   // NN * 32

// ---------------- scratch (static device globals; no allocations) ----------------
__device__ float g_u   [NN * HD];
__device__ float g_c   [NN * HD];
__device__ float g_u2  [NN * HD];
__device__ float g_c2  [NN * HD];
__device__ float g_aggc[NN * HD];   // holds MEAN directly
__device__ float g_aggu[NN * HD];   // holds MEAN directly
__device__ float g_cstate[NN * HD]; // LSTM cell state
__device__ float g_Wpack[98304];    // fragment-packed LSTM weights [y][kt][wn][k8][j][lane][4]

// CSR scratch
__device__ int g_deg_d[NN];
__device__ int g_deg_s[NN];
__device__ int g_off_d[NN + 1];
__device__ int g_off_s[NN + 1];
__device__ int g_cur_d[NN];
__device__ int g_cur_s[NN];
__device__ int g_eid_d[NE];
__device__ int g_eid_s[NE];

__device__ __forceinline__ float sigmoidf_(float x) { return 1.0f / (1.0f + expf(-x)); }

#define DOT4(acc, A, B) (acc) += (A).x*(B).x + (A).y*(B).y + (A).z*(B).z + (A).w*(B).w

// ================= CSR build =================
__global__ void zero_deg_kernel() {
    int i = blockIdx.x * blockDim.x + threadIdx.x;
    if (i < NN) { g_deg_d[i] = 0; g_deg_s[i] = 0; }
}

__global__ void count_kernel(const int* __restrict__ src, const int* __restrict__ dst) {
    int e = blockIdx.x * blockDim.x + threadIdx.x;
    if (e < NE) {
        atomicAdd(&g_deg_d[dst[e]], 1);
        atomicAdd(&g_deg_s[src[e]], 1);
    }
}

__global__ __launch_bounds__(1024) void scan_kernel() {
    const int* deg = (blockIdx.x == 0) ? g_deg_d : g_deg_s;
    int* off = (blockIdx.x == 0) ? g_off_d : g_off_s;
    int* cur = (blockIdx.x == 0) ? g_cur_d : g_cur_s;

    __shared__ int part[1024];
    int tid = threadIdx.x;
    int base = tid * 32;

    int s = 0;
#pragma unroll 4
    for (int k = 0; k < 32; k++) s += deg[base + k];
    part[tid] = s;
    __syncthreads();
    for (int d = 1; d < 1024; d <<= 1) {
        int v = (tid >= d) ? part[tid - d] : 0;
        __syncthreads();
        if (tid >= d) part[tid] += v;
        __syncthreads();
    }
    int run = (tid == 0) ? 0 : part[tid - 1];
#pragma unroll 4
    for (int k = 0; k < 32; k++) {
        off[base + k] = run;
        cur[base + k] = run;
        run += deg[base + k];
    }
    if (tid == 1023) off[NN] = run;
}

__global__ void fill_kernel(const int* __restrict__ src, const int* __restrict__ dst) {
    int e = blockIdx.x * blockDim.x + threadIdx.x;
    if (e < NE) {
        int s = src[e], d = dst[e];
        int p = atomicAdd(&g_cur_d[d], 1); g_eid_d[p] = s;
        int q = atomicAdd(&g_cur_s[s], 1); g_eid_s[q] = d;
    }
}

// ================= CSR mean-aggregate: one warp per node =================
__global__ __launch_bounds__(256) void agg_kernel(int mode)
{
    const int* off; const int* eid; const float* feat; float* outp;
    if      (mode == 0) { off = g_off_d; eid = g_eid_d; feat = g_u;  outp = g_aggc; }
    else if (mode == 1) { off = g_off_s; eid = g_eid_s; feat = g_c;  outp = g_aggu; }
    else if (mode == 2) { off = g_off_d; eid = g_eid_d; feat = g_u2; outp = g_aggc; }
    else                { off = g_off_s; eid = g_eid_s; feat = g_c2; outp = g_aggu; }

    int n = blockIdx.x * 8 + (threadIdx.x >> 5);
    int lane = threadIdx.x & 31;
    int a = off[n], b = off[n + 1];

    float4 acc = make_float4(0.f, 0.f, 0.f, 0.f);
    const float4* f4 = (const float4*)feat;

    int i = a;
    for (; i + 4 <= b; i += 4) {
        int e0 = __ldg(&eid[i]),     e1 = __ldg(&eid[i + 1]);
        int e2 = __ldg(&eid[i + 2]), e3 = __ldg(&eid[i + 3]);
        float4 v0 = f4[e0 * 32 + lane];
        float4 v1 = f4[e1 * 32 + lane];
        float4 v2 = f4[e2 * 32 + lane];
        float4 v3 = f4[e3 * 32 + lane];
        acc.x += v0.x + v1.x + v2.x + v3.x;
        acc.y += v0.y + v1.y + v2.y + v3.y;
        acc.z += v0.z + v1.z + v2.z + v3.z;
        acc.w += v0.w + v1.w + v2.w + v3.w;
    }
    for (; i < b; i++) {
        int e0 = __ldg(&eid[i]);
        float4 v0 = f4[e0 * 32 + lane];
        acc.x += v0.x; acc.y += v0.y; acc.z += v0.z; acc.w += v0.w;
    }
    float inv = (b > a) ? 1.0f / (float)(b - a) : 1.0f;
    acc.x *= inv; acc.y *= inv; acc.z *= inv; acc.w *= inv;
    ((float4*)outp)[n * 32 + lane] = acc;
}

// =====================================================================
// LSTM weight pre-pack: fragment-order layout so the GEMM's B-fragment
// loads become LDS.128. Layout index (per y, kt chunk of 16 k):
//   [y][kt][wn][k8][j][lane][v]  (2*2*4*32*4 = 2048 floats per (y,kt))
//   value = W[grow][k]: fn=2j+(v>>1), reg=v&1, lr=lane>>2, lc=lane&3,
//   n = wn*64+fn*8+lr, k = kt*16 + k8*8 + reg*4 + lc,
//   grow = (n>>5)*128 + y*32 + (n&31).
// =====================================================================
__global__ void pack_w_kernel(const float* __restrict__ W_ih, const float* __restrict__ W_hh) {
    int i = blockIdx.x * 256 + threadIdx.x;   // 98304 total
    int rest = i & 2047;
    int ykt = i >> 11;
    int y = ykt / 12, kt = ykt % 12;
    int v = rest & 3, lane = (rest >> 2) & 31, j = (rest >> 7) & 3;
    int k8 = (rest >> 9) & 1, wn = (rest >> 10) & 1;
    int fn = 2 * j + (v >> 1), reg = v & 1;
    int lr = lane >> 2, lc = lane & 3;
    int n = wn * 64 + fn * 8 + lr;
    int k = kt * 16 + k8 * 8 + reg * 4 + lc;
    int grow = (n >> 5) * 128 + y * 32 + (n & 31);
    g_Wpack[i] = (k < 64) ? W_ih[grow * 64 + k] : W_hh[grow * 128 + k - 64];
}

// =====================================================================
// LSTM step, fused tf32 GEMM + cell. Occ-2, ldmatrix A, packed-LDS.128 B.
//  Grid (NN/128, 4), 256 thr. Block (x,y): users [x*128,..), hidden
//  units [y*32,(y+1)*32) across all 4 gates. K=192 in 12 chunks of 16.
//  Smem: A 2x128x20 + Bpack 2x2048 = 9216 floats (36 KB); epilogue reuses.
// =====================================================================
#define GEMM_SMEM (9216 * 4)

__global__ void zero_h_kernel() {
    int i = blockIdx.x * 256 + threadIdx.x;
    ((float4*)g_u)[i] = make_float4(0.f, 0.f, 0.f, 0.f);
}

__device__ __forceinline__ void mma_tf32(float d[4], const unsigned a[4], const unsigned b[2]) {
    asm volatile(
        "mma.sync.aligned.m16n8k8.row.col.f32.tf32.tf32.f32 "
        "{%0,%1,%2,%3}, {%4,%5,%6,%7}, {%8,%9}, {%0,%1,%2,%3};"
        : "+f"(d[0]), "+f"(d[1]), "+f"(d[2]), "+f"(d[3])
        : "r"(a[0]), "r"(a[1]), "r"(a[2]), "r"(a[3]), "r"(b[0]), "r"(b[1]));
}

__global__ __launch_bounds__(256, 2) void lstm_step_kernel(
    const float* __restrict__ x_user,
    const float* __restrict__ b_ih, const float* __restrict__ b_hh, int t)
{
    extern __shared__ float smg[];
    float* Abuf[2] = { smg, smg + 128 * 20 };
    float* Bbuf[2] = { smg + 2 * 128 * 20, smg + 2 * 128 * 20 + 2048 };
    __shared__ float bs[128];

    int tid = threadIdx.x;
    int u0 = blockIdx.x * 128;
    int y  = blockIdx.y;

    if (tid < 128) {
        int gate = tid >> 5, w = tid & 31;
        int grow = gate * 128 + y * 32 + w;
        bs[tid] = b_ih[grow] + b_hh[grow];
    }

    auto issue_tile = [&](int kt, int buf) {
        int kbase = kt * 16;
#pragma unroll
        for (int i = 0; i < 2; i++) {       // A: 512 x 16B
            int idx = tid + i * 256;
            int u = idx >> 2, k4 = idx & 3;
            int k = kbase + k4 * 4;
            const float* srcp = (k < 64)
                ? x_user + ((size_t)(u0 + u) * TT + t) * EMBD + k
                : g_u + (size_t)(u0 + u) * HD + (k - 64);
            unsigned dst = (unsigned)__cvta_generic_to_shared(Abuf[buf] + u * 20 + k4 * 4);
            asm volatile("cp.async.ca.shared.global [%0], [%1], 16;" :: "r"(dst), "l"(srcp) : "memory");
        }
        {                                    // B: 512 x 16B, contiguous pack
            const float* base = g_Wpack + ((size_t)(y * 12 + kt)) * 2048;
#pragma unroll
            for (int i = 0; i < 2; i++) {
                int idx = tid + i * 256;
                const float* srcp = base + idx * 4;
                unsigned dst = (unsigned)__cvta_generic_to_shared(Bbuf[buf] + idx * 4);
                asm volatile("cp.async.ca.shared.global [%0], [%1], 16;" :: "r"(dst), "l"(srcp) : "memory");
            }
        }
        asm volatile("cp.async.commit_group;" ::: "memory");
    };

    issue_tile(0, 0);

    int wid = tid >> 5, lane = tid & 31;
    int wm = wid >> 1, wn = wid & 1;     // warp grid 4(M) x 2(N)
    int urow = wm * 32, ncol = wn * 64;
    int lr = lane >> 2, lc = lane & 3;

    // ldmatrix per-lane row address component (tile t = lane>>3, row-in-tile = lane&7)
    int tmat = lane >> 3, rin = lane & 7;
    unsigned aoff = (unsigned)(((urow + (tmat & 1) * 8 + rin) * 20 + (tmat >> 1) * 4) * 4);
    unsigned sA[2] = { (unsigned)__cvta_generic_to_shared(Abuf[0]),
                       (unsigned)__cvta_generic_to_shared(Abuf[1]) };

    float acc[2][8][4];
#pragma unroll
    for (int fm = 0; fm < 2; fm++)
#pragma unroll
        for (int fn = 0; fn < 8; fn++)
#pragma unroll
            for (int r = 0; r < 4; r++) acc[fm][fn][r] = 0.f;

#pragma unroll 1
    for (int kt = 0; kt < 12; kt++) {
        int cur = kt & 1;
        if (kt < 11) {
            issue_tile(kt + 1, cur ^ 1);
            asm volatile("cp.async.wait_group 1;" ::: "memory");
        } else {
            asm volatile("cp.async.wait_group 0;" ::: "memory");
        }
        __syncthreads();

        const float4* Bp = (const float4*)Bbuf[cur];
#pragma unroll
        for (int k8 = 0; k8 < 2; k8++) {
            unsigned afr[2][4], bfr[8][2];
#pragma unroll
            for (int fm = 0; fm < 2; fm++) {
                unsigned ad = sA[cur] + aoff + (unsigned)(fm * 1280 + k8 * 32);
                asm volatile("ldmatrix.sync.aligned.m8n8.x4.shared.b16 {%0,%1,%2,%3}, [%4];"
                             : "=r"(afr[fm][0]), "=r"(afr[fm][1]),
                               "=r"(afr[fm][2]), "=r"(afr[fm][3])
                             : "r"(ad));
            }
#pragma unroll
            for (int j = 0; j < 4; j++) {
                float4 v = Bp[(((wn * 2 + k8) * 4 + j) * 32) + lane];
                bfr[2 * j][0]     = __float_as_uint(v.x);
                bfr[2 * j][1]     = __float_as_uint(v.y);
                bfr[2 * j + 1][0] = __float_as_uint(v.z);
                bfr[2 * j + 1][1] = __float_as_uint(v.w);
            }
#pragma unroll
            for (int fm = 0; fm < 2; fm++)
#pragma unroll
                for (int fn = 0; fn < 8; fn++)
                    mma_tf32(acc[fm][fn], afr[fm], bfr[fn]);
        }
        __syncthreads();
    }

    // ---- epilogue: two 64-row passes through smem, then cell update ----
    float* S = smg;   // [128 cols][stride 69], 8832 floats <= 9216
#pragma unroll 1
    for (int p = 0; p < 2; p++) {
        if ((wm >> 1) == p) {
            int rbase = urow - p * 64;
#pragma unroll
            for (int fm = 0; fm < 2; fm++) {
#pragma unroll
                for (int fn = 0; fn < 8; fn++) {
                    int rr = rbase + fm * 16 + lr;
                    int cc = ncol + fn * 8 + lc * 2;
                    S[cc * 69 + rr]           = acc[fm][fn][0];
                    S[(cc + 1) * 69 + rr]     = acc[fm][fn][1];
                    S[cc * 69 + rr + 8]       = acc[fm][fn][2];
                    S[(cc + 1) * 69 + rr + 8] = acc[fm][fn][3];
                }
            }
        }
        __syncthreads();

#pragma unroll
        for (int i = 0; i < 8; i++) {
            int flat = tid + i * 256;
            int rr = flat >> 5, w = flat & 31;
            float gi = S[w * 69 + rr]          + bs[w];
            float gf = S[(w + 32) * 69 + rr]   + bs[32 + w];
            float gg = S[(w + 64) * 69 + rr]   + bs[64 + w];
            float go = S[(w + 96) * 69 + rr]   + bs[96 + w];
            size_t gidx = (size_t)(u0 + p * 64 + rr) * HD + y * 32 + w;
            float cold = (t == 0) ? 0.f : g_cstate[gidx];
            float c = sigmoidf_(gf) * cold + sigmoidf_(gi) * tanhf(gg);
            g_cstate[gidx] = c;
            g_u[gidx] = sigmoidf_(go) * tanhf(c);
        }
        __syncthreads();
    }
}

// ---------------- content linear: c = x_content @ Wc^T + bc ----------------
__global__ __launch_bounds__(256) void content_kernel(
    const float* __restrict__ xc, const float* __restrict__ Wc, const float* __restrict__ bc)
{
    __shared__ float4 Wc4s[128 * 17];
    __shared__ float4 xs[32 * 17];
    int tid = threadIdx.x;
    int n0 = blockIdx.x * 32;

    for (int idx = tid; idx < 128 * 16; idx += 256) {
        int r = idx >> 4, col = idx & 15;
        Wc4s[r * 17 + col] = ((const float4*)Wc)[idx];
    }
    for (int idx = tid; idx < 32 * 16; idx += 256) {
        int n = idx >> 4, k4 = idx & 15;
        xs[n * 17 + k4] = ((const float4*)xc)[(n0 + n) * 16 + k4];
    }
    __syncthreads();

    int n = tid >> 3, q = tid & 7;
    float acc[16];
#pragma unroll
    for (int i = 0; i < 16; i++) acc[i] = bc[q + 8 * i];
#pragma unroll 1
    for (int k4 = 0; k4 < 16; k4++) {
        float4 xv = xs[n * 17 + k4];
#pragma unroll
        for (int i = 0; i < 16; i++) {
            float4 wv = Wc4s[(q + 8 * i) * 17 + k4];
            DOT4(acc[i], wv, xv);
        }
    }
#pragma unroll
    for (int i = 0; i < 16; i++)
        g_c[(n0 + n) * HD + q + 8 * i] = acc[i];
}

// ---------------- SAGE combine ----------------
#define COMBINE_SMEM ((2 * 128 * 33 + 2 * 32 * 33) * 16)
__global__ __launch_bounds__(256) void combine_kernel(
    const float* __restrict__ Wl, const float* __restrict__ bl,
    const float* __restrict__ Wr, int mode)
{
    extern __shared__ float smc[];
    float4* Wl4 = (float4*)smc;
    float4* Wr4 = Wl4 + 128 * 33;
    float4* xm4 = Wr4 + 128 * 33;
    float4* xs4 = xm4 + 32 * 33;

    const float* agg; const float* selfx; float* outp;
    if      (mode == 0) { agg = g_aggc; selfx = g_c;  outp = g_c2; }
    else if (mode == 1) { agg = g_aggu; selfx = g_u;  outp = g_u2; }
    else if (mode == 2) { agg = g_aggc; selfx = g_c2; outp = g_c;  }
    else                { agg = g_aggu; selfx = g_u2; outp = g_u;  }

    int tid = threadIdx.x;
    int n0 = blockIdx.x * 32;

    for (int idx = tid; idx < 128 * 32; idx += 256) {
        int r = idx >> 5, col = idx & 31;
        Wl4[r * 33 + col] = ((const float4*)Wl)[idx];
        Wr4[r * 33 + col] = ((const float4*)Wr)[idx];
    }
    for (int idx = tid; idx < 32 * 32; idx += 256) {
        int n = idx >> 5, k4 = idx & 31;
        xm4[n * 33 + k4] = ((const float4*)agg)[(n0 + n) * 32 + k4];
        xs4[n * 33 + k4] = ((const float4*)selfx)[(n0 + n) * 32 + k4];
    }
    __syncthreads();

    int n = tid >> 3, q = tid & 7;
    float acc[16];
#pragma unroll
    for (int i = 0; i < 16; i++) acc[i] = bl[q + 8 * i];
#pragma unroll 1
    for (int k4 = 0; k4 < 32; k4++) {
        float4 xm = xm4[n * 33 + k4];
        float4 xv = xs4[n * 33 + k4];
#pragma unroll
        for (int i = 0; i < 16; i++) {
            int j = q + 8 * i;
            float4 wlv = Wl4[j * 33 + k4];
            float4 wrv = Wr4[j * 33 + k4];
            DOT4(acc[i], wlv, xm);
            DOT4(acc[i], wrv, xv);
        }
    }
#pragma unroll
    for (int i = 0; i < 16; i++)
        outp[(n0 + n) * HD + q + 8 * i] = fmaxf(acc[i], 0.f);
}

// ---------------- classifier ----------------
#define CLS_SMEM ((128 * 65 + 32 * 65) * 16 + 512)
__global__ __launch_bounds__(256) void classifier_kernel(
    const float* __restrict__ W1, const float* __restrict__ b1,
    const float* __restrict__ W2, const float* __restrict__ b2,
    float* __restrict__ out)
{
    extern __shared__ float smk[];
    float4* W14 = (float4*)smk;
    float4* xc4 = W14 + 128 * 65;
    float*  W2s = (float*)(xc4 + 32 * 65);

    int tid = threadIdx.x;
    int n0 = blockIdx.x * 32;

    for (int idx = tid; idx < 128 * 64; idx += 256) {
        int r = idx >> 6, col = idx & 63;
        W14[r * 65 + col] = ((const float4*)W1)[idx];
    }
    for (int idx = tid; idx < 32 * 64; idx += 256) {
        int n = idx >> 6, k4 = idx & 63;
        float4 v = (k4 < 32) ? ((const float4*)g_u)[(n0 + n) * 32 + k4]
                             : ((const float4*)g_c)[(n0 + n) * 32 + (k4 - 32)];
        xc4[n * 65 + k4] = v;
    }
    if (tid < 128) W2s[tid] = W2[tid];
    __syncthreads();

    int n = tid >> 3, q = tid & 7;
    float acc[16];
#pragma unroll
    for (int i = 0; i < 16; i++) acc[i] = b1[q + 8 * i];
#pragma unroll 1
    for (int k4 = 0; k4 < 64; k4++) {
        float4 xv = xc4[n * 65 + k4];
#pragma unroll
        for (int i = 0; i < 16; i++) {
            float4 wv = W14[(q + 8 * i) * 65 + k4];
            DOT4(acc[i], wv, xv);
        }
    }
    float p = 0.f;
#pragma unroll
    for (int i = 0; i < 16; i++) {
        float h = fmaxf(acc[i], 0.f);
        p += h * W2s[q + 8 * i];
    }
    p += __shfl_xor_sync(0xffffffffu, p, 1);
    p += __shfl_xor_sync(0xffffffffu, p, 2);
    p += __shfl_xor_sync(0xffffffffu, p, 4);
    if (q == 0) out[n0 + n] = sigmoidf_(p + b2[0]);
}

// ---------------- launch ----------------
extern "C" void kernel_launch(void* const* d_in, const int* in_sizes, int n_in,
                              void* d_out, int out_size)
{
    const float* x_user    = (const float*)d_in[0];
    const float* x_content = (const float*)d_in[1];
    const int*   edge      = (const int*)  d_in[2];
    const float* W_ih      = (const float*)d_in[3];
    const float* W_hh      = (const float*)d_in[4];
    const float* b_ih      = (const float*)d_in[5];
    const float* b_hh      = (const float*)d_in[6];
    const float* Wc        = (const float*)d_in[7];
    const float* bc        = (const float*)d_in[8];
    const float* Wl0       = (const float*)d_in[9];
    const float* bl0       = (const float*)d_in[10];
    const float* Wr0       = (const float*)d_in[11];
    const float* Wl1       = (const float*)d_in[12];
    const float* bl1       = (const float*)d_in[13];
    const float* Wr1       = (const float*)d_in[14];
    const float* W1        = (const float*)d_in[15];
    const float* b1        = (const float*)d_in[16];
    const float* W2        = (const float*)d_in[17];
    const float* b2        = (const float*)d_in[18];
    float* out = (float*)d_out;

    const int* src = edge;
    const int* dst = edge + NE;

    cudaFuncSetAttribute(lstm_step_kernel,  cudaFuncAttributeMaxDynamicSharedMemorySize, GEMM_SMEM);
    cudaFuncSetAttribute(combine_kernel,    cudaFuncAttributeMaxDynamicSharedMemorySize, COMBINE_SMEM);
    cudaFuncSetAttribute(classifier_kernel, cudaFuncAttributeMaxDynamicSharedMemorySize, CLS_SMEM);

    // ---- LSTM (packed weights; profile slot lands on lstm_step) ----
    zero_h_kernel<<<NN * HD / 4 / 256, 256>>>();
    pack_w_kernel<<<98304 / 256, 256>>>(W_ih, W_hh);
    for (int t = 0; t < TT; t++)
        lstm_step_kernel<<<dim3(NN / 128, 4), 256, GEMM_SMEM>>>(
            x_user, b_ih, b_hh, t);

    // ---- content features ----
    content_kernel<<<NN / 32, 256>>>(x_content, Wc, bc);

    // ---- CSR build ----
    zero_deg_kernel<<<NN / 256, 256>>>();
    count_kernel<<<NE / 256, 256>>>(src, dst);
    scan_kernel<<<2, 1024>>>();
    fill_kernel<<<NE / 256, 256>>>(src, dst);

    // ---- SAGE layer 0 ----
    agg_kernel<<<NN / 8, 256>>>(0);
    agg_kernel<<<NN / 8, 256>>>(1);
    combine_kernel<<<NN / 32, 256, COMBINE_SMEM>>>(Wl0, bl0, Wr0, 0);
    combine_kernel<<<NN / 32, 256, COMBINE_SMEM>>>(Wl0, bl0, Wr0, 1);

    // ---- SAGE layer 1 ----
    agg_kernel<<<NN / 8, 256>>>(2);
    agg_kernel<<<NN / 8, 256>>>(3);
    combine_kernel<<<NN / 32, 256, COMBINE_SMEM>>>(Wl1, bl1, Wr1, 2);
    combine_kernel<<<NN / 32, 256, COMBINE_SMEM>>>(Wl1, bl1, Wr1, 3);

    // ---- classifier ----
    classifier_kernel<<<NN / 32, 256, CLS_SMEM>>>(W1, b1, W2, b2, out);
}

// round 15
// speedup vs baseline: 26.2892x; 1.1793x over previous
#include <cuda_runtime.h>
#include <cuda_bf16.h>
#include <math.h>

#define NN   32768
#define TT   20
#define EMBD 64
#define HD   128
#define NE   1048576   // NN * 32

// ---------------- scratch (static device globals; no allocations) ----------------
__device__ float g_u   [NN * HD];
__device__ float g_c   [NN * HD];
__device__ float g_u2  [NN * HD];
__device__ float g_c2  [NN * HD];
__device__ float g_aggc[NN * HD];   // holds MEAN directly
__device__ float g_aggu[NN * HD];   // holds MEAN directly
__device__ float g_cstate[NN * HD]; // LSTM cell state (fp32)
__device__ __nv_bfloat16 g_xbf[NN * TT * EMBD];  // x_user in bf16
__device__ __nv_bfloat16 g_hbf[NN * HD];         // h state in bf16 (MMA input)
__device__ unsigned g_Wpk[49152];   // bf16-pair fragment-packed LSTM weights

// CSR scratch
__device__ int g_deg_d[NN];
__device__ int g_deg_s[NN];
__device__ int g_off_d[NN + 1];
__device__ int g_off_s[NN + 1];
__device__ int g_cur_d[NN];
__device__ int g_cur_s[NN];
__device__ int g_eid_d[NE];
__device__ int g_eid_s[NE];

__device__ __forceinline__ float sigmoidf_(float x) { return 1.0f / (1.0f + expf(-x)); }

#define DOT4(acc, A, B) (acc) += (A).x*(B).x + (A).y*(B).y + (A).z*(B).z + (A).w*(B).w

// ================= CSR build =================
__global__ void zero_deg_kernel() {
    int i = blockIdx.x * blockDim.x + threadIdx.x;
    if (i < NN) { g_deg_d[i] = 0; g_deg_s[i] = 0; }
}

__global__ void count_kernel(const int* __restrict__ src, const int* __restrict__ dst) {
    int e = blockIdx.x * blockDim.x + threadIdx.x;
    if (e < NE) {
        atomicAdd(&g_deg_d[dst[e]], 1);
        atomicAdd(&g_deg_s[src[e]], 1);
    }
}

__global__ __launch_bounds__(1024) void scan_kernel() {
    const int* deg = (blockIdx.x == 0) ? g_deg_d : g_deg_s;
    int* off = (blockIdx.x == 0) ? g_off_d : g_off_s;
    int* cur = (blockIdx.x == 0) ? g_cur_d : g_cur_s;

    __shared__ int part[1024];
    int tid = threadIdx.x;
    int base = tid * 32;

    int s = 0;
#pragma unroll 4
    for (int k = 0; k < 32; k++) s += deg[base + k];
    part[tid] = s;
    __syncthreads();
    for (int d = 1; d < 1024; d <<= 1) {
        int v = (tid >= d) ? part[tid - d] : 0;
        __syncthreads();
        if (tid >= d) part[tid] += v;
        __syncthreads();
    }
    int run = (tid == 0) ? 0 : part[tid - 1];
#pragma unroll 4
    for (int k = 0; k < 32; k++) {
        off[base + k] = run;
        cur[base + k] = run;
        run += deg[base + k];
    }
    if (tid == 1023) off[NN] = run;
}

__global__ void fill_kernel(const int* __restrict__ src, const int* __restrict__ dst) {
    int e = blockIdx.x * blockDim.x + threadIdx.x;
    if (e < NE) {
        int s = src[e], d = dst[e];
        int p = atomicAdd(&g_cur_d[d], 1); g_eid_d[p] = s;
        int q = atomicAdd(&g_cur_s[s], 1); g_eid_s[q] = d;
    }
}

// ================= CSR mean-aggregate: one warp per node =================
__global__ __launch_bounds__(256) void agg_kernel(int mode)
{
    const int* off; const int* eid; const float* feat; float* outp;
    if      (mode == 0) { off = g_off_d; eid = g_eid_d; feat = g_u;  outp = g_aggc; }
    else if (mode == 1) { off = g_off_s; eid = g_eid_s; feat = g_c;  outp = g_aggu; }
    else if (mode == 2) { off = g_off_d; eid = g_eid_d; feat = g_u2; outp = g_aggc; }
    else                { off = g_off_s; eid = g_eid_s; feat = g_c2; outp = g_aggu; }

    int n = blockIdx.x * 8 + (threadIdx.x >> 5);
    int lane = threadIdx.x & 31;
    int a = off[n], b = off[n + 1];

    float4 acc = make_float4(0.f, 0.f, 0.f, 0.f);
    const float4* f4 = (const float4*)feat;

    int i = a;
    for (; i + 4 <= b; i += 4) {
        int e0 = __ldg(&eid[i]),     e1 = __ldg(&eid[i + 1]);
        int e2 = __ldg(&eid[i + 2]), e3 = __ldg(&eid[i + 3]);
        float4 v0 = f4[e0 * 32 + lane];
        float4 v1 = f4[e1 * 32 + lane];
        float4 v2 = f4[e2 * 32 + lane];
        float4 v3 = f4[e3 * 32 + lane];
        acc.x += v0.x + v1.x + v2.x + v3.x;
        acc.y += v0.y + v1.y + v2.y + v3.y;
        acc.z += v0.z + v1.z + v2.z + v3.z;
        acc.w += v0.w + v1.w + v2.w + v3.w;
    }
    for (; i < b; i++) {
        int e0 = __ldg(&eid[i]);
        float4 v0 = f4[e0 * 32 + lane];
        acc.x += v0.x; acc.y += v0.y; acc.z += v0.z; acc.w += v0.w;
    }
    float inv = (b > a) ? 1.0f / (float)(b - a) : 1.0f;
    acc.x *= inv; acc.y *= inv; acc.z *= inv; acc.w *= inv;
    ((float4*)outp)[n * 32 + lane] = acc;
}

// ================= LSTM prep: x -> bf16, weights -> fragment pack =================
__device__ __forceinline__ unsigned pack_bf2(float lo, float hi) {
    unsigned short s0 = __bfloat16_as_ushort(__float2bfloat16(lo));
    unsigned short s1 = __bfloat16_as_ushort(__float2bfloat16(hi));
    return ((unsigned)s1 << 16) | s0;
}

__global__ void conv_x_kernel(const float* __restrict__ x_user) {
    int i = blockIdx.x * 256 + threadIdx.x;    // each converts 8 floats
    const float4* s = (const float4*)x_user + (size_t)i * 2;
    float4 a = s[0], b = s[1];
    uint4 o;
    o.x = pack_bf2(a.x, a.y);
    o.y = pack_bf2(a.z, a.w);
    o.z = pack_bf2(b.x, b.y);
    o.w = pack_bf2(b.z, b.w);
    ((uint4*)g_xbf)[i] = o;
}

__global__ void zero_h_kernel() {
    int i = blockIdx.x * 256 + threadIdx.x;    // NN*HD/8 uint4 writes
    ((uint4*)g_hbf)[i] = make_uint4(0, 0, 0, 0);
}

// Pack layout per (y in 4, kt in 6): u32 index = (((wn*2+ki)*4+jp)*32+lane)*4 + v
// fn = 2*jp + (v>>1), r = v&1; n = wn*64 + fn*8 + (lane>>2);
// k = kt*32 + ki*16 + (lane&3)*2 + r*8; grow = (n>>5)*128 + y*32 + (n&31).
// Value = bf16 pair (W[grow][k], W[grow][k+1]).
__global__ void pack_w_kernel(const float* __restrict__ W_ih, const float* __restrict__ W_hh) {
    int i = blockIdx.x * 256 + threadIdx.x;    // 49152
    int rest = i & 2047;
    int ykt = i >> 11;                         // 0..23
    int y = ykt / 6, kt = ykt % 6;
    int v = rest & 3, lane = (rest >> 2) & 31, jp = (rest >> 7) & 3;
    int ki = (rest >> 9) & 1, wn = (rest >> 10) & 1;
    int fn = 2 * jp + (v >> 1), r = v & 1;
    int n = wn * 64 + fn * 8 + (lane >> 2);
    int k = kt * 32 + ki * 16 + (lane & 3) * 2 + r * 8;
    int grow = (n >> 5) * 128 + y * 32 + (n & 31);
    float w0 = (k < 64) ? W_ih[grow * 64 + k]     : W_hh[grow * 128 + k - 64];
    float w1 = (k < 63) ? W_ih[grow * 64 + k + 1] : W_hh[grow * 128 + k + 1 - 64];
    g_Wpk[i] = pack_bf2(w0, w1);
}

// =====================================================================
// LSTM step, fused bf16 GEMM (m16n8k16, fp32 accum) + cell update.
//  Grid (NN/128, 4), 256 thr, occ 2. Block (x,y): users [x*128,..),
//  hidden [y*32,(y+1)*32) across all 4 gates. K=192 in 6 chunks of 32.
//  Smem: A 2x(128x40 bf16)=20480B + B 2x8192B=16384B -> 36864B; epilogue reuses.
// =====================================================================
#define GEMM_SMEM 36864

__device__ __forceinline__ void mma_bf16(float d[4], const unsigned a[4], const unsigned b[2]) {
    asm volatile(
        "mma.sync.aligned.m16n8k16.row.col.f32.bf16.bf16.f32 "
        "{%0,%1,%2,%3}, {%4,%5,%6,%7}, {%8,%9}, {%0,%1,%2,%3};"
        : "+f"(d[0]), "+f"(d[1]), "+f"(d[2]), "+f"(d[3])
        : "r"(a[0]), "r"(a[1]), "r"(a[2]), "r"(a[3]), "r"(b[0]), "r"(b[1]));
}

__global__ __launch_bounds__(256, 2) void lstm_step_kernel(
    const float* __restrict__ b_ih, const float* __restrict__ b_hh, int t)
{
    extern __shared__ char smraw[];
    // A buffers at 0 / 10240 bytes (128 rows x 40 bf16 = 80B/row)
    // B buffers at 20480 / 28672 bytes (2048 u32 each)
    __nv_bfloat16* Abf[2] = { (__nv_bfloat16*)smraw, (__nv_bfloat16*)(smraw + 10240) };
    unsigned* Bu[2] = { (unsigned*)(smraw + 20480), (unsigned*)(smraw + 28672) };
    __shared__ float bs[128];

    int tid = threadIdx.x;
    int u0 = blockIdx.x * 128;
    int y  = blockIdx.y;

    if (tid < 128) {
        int gate = tid >> 5, w = tid & 31;
        int grow = gate * 128 + y * 32 + w;
        bs[tid] = b_ih[grow] + b_hh[grow];
    }

    unsigned sA[2] = { (unsigned)__cvta_generic_to_shared(Abf[0]),
                       (unsigned)__cvta_generic_to_shared(Abf[1]) };
    unsigned sB[2] = { (unsigned)__cvta_generic_to_shared(Bu[0]),
                       (unsigned)__cvta_generic_to_shared(Bu[1]) };

    auto issue_tile = [&](int kt, int buf) {
#pragma unroll
        for (int i = 0; i < 2; i++) {       // A: 512 x 16B (8 bf16)
            int idx = tid + i * 256;
            int u = idx >> 2, k4 = idx & 3;
            const __nv_bfloat16* srcp = (kt < 2)
                ? g_xbf + ((size_t)(u0 + u) * TT + t) * EMBD + kt * 32 + k4 * 8
                : g_hbf + (size_t)(u0 + u) * HD + (kt - 2) * 32 + k4 * 8;
            unsigned dst = sA[buf] + (unsigned)(u * 80 + k4 * 16);
            asm volatile("cp.async.ca.shared.global [%0], [%1], 16;" :: "r"(dst), "l"(srcp) : "memory");
        }
        {                                    // B: 512 x 16B contiguous pack
            const unsigned* basep = g_Wpk + (size_t)(y * 6 + kt) * 2048;
#pragma unroll
            for (int i = 0; i < 2; i++) {
                int idx = tid + i * 256;
                const unsigned* srcp = basep + idx * 4;
                unsigned dst = sB[buf] + (unsigned)(idx * 16);
                asm volatile("cp.async.ca.shared.global [%0], [%1], 16;" :: "r"(dst), "l"(srcp) : "memory");
            }
        }
        asm volatile("cp.async.commit_group;" ::: "memory");
    };

    issue_tile(0, 0);

    int wid = tid >> 5, lane = tid & 31;
    int wm = wid >> 1, wn = wid & 1;     // warp grid 4(M) x 2(N)
    int urow = wm * 32, ncol = wn * 64;
    int lr = lane >> 2, lc = lane & 3;

    // ldmatrix address component: row = urow + (lane&15), k-half = lane>>4
    unsigned aoff = (unsigned)((urow + (lane & 15)) * 80 + (lane >> 4) * 16);

    float acc[2][8][4];
#pragma unroll
    for (int fm = 0; fm < 2; fm++)
#pragma unroll
        for (int fn = 0; fn < 8; fn++)
#pragma unroll
            for (int r = 0; r < 4; r++) acc[fm][fn][r] = 0.f;

#pragma unroll 1
    for (int kt = 0; kt < 6; kt++) {
        int cur = kt & 1;
        if (kt < 5) {
            issue_tile(kt + 1, cur ^ 1);
            asm volatile("cp.async.wait_group 1;" ::: "memory");
        } else {
            asm volatile("cp.async.wait_group 0;" ::: "memory");
        }
        __syncthreads();

        const uint4* Bp = (const uint4*)Bu[cur];
#pragma unroll
        for (int ki = 0; ki < 2; ki++) {
            unsigned afr[2][4], bfr[8][2];
#pragma unroll
            for (int fm = 0; fm < 2; fm++) {
                unsigned ad = sA[cur] + aoff + (unsigned)(fm * 16 * 80 + ki * 32);
                asm volatile("ldmatrix.sync.aligned.m8n8.x4.shared.b16 {%0,%1,%2,%3}, [%4];"
                             : "=r"(afr[fm][0]), "=r"(afr[fm][1]),
                               "=r"(afr[fm][2]), "=r"(afr[fm][3])
                             : "r"(ad));
            }
#pragma unroll
            for (int jp = 0; jp < 4; jp++) {
                uint4 v = Bp[(((wn * 2 + ki) * 4 + jp) * 32) + lane];
                bfr[2 * jp][0]     = v.x;
                bfr[2 * jp][1]     = v.y;
                bfr[2 * jp + 1][0] = v.z;
                bfr[2 * jp + 1][1] = v.w;
            }
#pragma unroll
            for (int fm = 0; fm < 2; fm++)
#pragma unroll
                for (int fn = 0; fn < 8; fn++)
                    mma_bf16(acc[fm][fn], afr[fm], bfr[fn]);
        }
        __syncthreads();
    }

    // ---- epilogue: two 64-row passes through smem, then cell update ----
    float* S = (float*)smraw;   // [128 cols][stride 69] = 35328B <= 36864B
#pragma unroll 1
    for (int p = 0; p < 2; p++) {
        if ((wm >> 1) == p) {
            int rbase = urow - p * 64;
#pragma unroll
            for (int fm = 0; fm < 2; fm++) {
#pragma unroll
                for (int fn = 0; fn < 8; fn++) {
                    int rr = rbase + fm * 16 + lr;
                    int cc = ncol + fn * 8 + lc * 2;
                    S[cc * 69 + rr]           = acc[fm][fn][0];
                    S[(cc + 1) * 69 + rr]     = acc[fm][fn][1];
                    S[cc * 69 + rr + 8]       = acc[fm][fn][2];
                    S[(cc + 1) * 69 + rr + 8] = acc[fm][fn][3];
                }
            }
        }
        __syncthreads();

#pragma unroll
        for (int i = 0; i < 8; i++) {
            int flat = tid + i * 256;
            int rr = flat >> 5, w = flat & 31;
            float gi = S[w * 69 + rr]          + bs[w];
            float gf = S[(w + 32) * 69 + rr]   + bs[32 + w];
            float gg = S[(w + 64) * 69 + rr]   + bs[64 + w];
            float go = S[(w + 96) * 69 + rr]   + bs[96 + w];
            size_t gidx = (size_t)(u0 + p * 64 + rr) * HD + y * 32 + w;
            float cold = (t == 0) ? 0.f : g_cstate[gidx];
            float c = sigmoidf_(gf) * cold + sigmoidf_(gi) * tanhf(gg);
            g_cstate[gidx] = c;
            float h = sigmoidf_(go) * tanhf(c);
            g_hbf[gidx] = __float2bfloat16(h);
            if (t == TT - 1) g_u[gidx] = h;
        }
        __syncthreads();
    }
}

// ---------------- content linear: c = x_content @ Wc^T + bc ----------------
__global__ __launch_bounds__(256) void content_kernel(
    const float* __restrict__ xc, const float* __restrict__ Wc, const float* __restrict__ bc)
{
    __shared__ float4 Wc4s[128 * 17];
    __shared__ float4 xs[32 * 17];
    int tid = threadIdx.x;
    int n0 = blockIdx.x * 32;

    for (int idx = tid; idx < 128 * 16; idx += 256) {
        int r = idx >> 4, col = idx & 15;
        Wc4s[r * 17 + col] = ((const float4*)Wc)[idx];
    }
    for (int idx = tid; idx < 32 * 16; idx += 256) {
        int n = idx >> 4, k4 = idx & 15;
        xs[n * 17 + k4] = ((const float4*)xc)[(n0 + n) * 16 + k4];
    }
    __syncthreads();

    int n = tid >> 3, q = tid & 7;
    float acc[16];
#pragma unroll
    for (int i = 0; i < 16; i++) acc[i] = bc[q + 8 * i];
#pragma unroll 1
    for (int k4 = 0; k4 < 16; k4++) {
        float4 xv = xs[n * 17 + k4];
#pragma unroll
        for (int i = 0; i < 16; i++) {
            float4 wv = Wc4s[(q + 8 * i) * 17 + k4];
            DOT4(acc[i], wv, xv);
        }
    }
#pragma unroll
    for (int i = 0; i < 16; i++)
        g_c[(n0 + n) * HD + q + 8 * i] = acc[i];
}

// ---------------- SAGE combine ----------------
#define COMBINE_SMEM ((2 * 128 * 33 + 2 * 32 * 33) * 16)
__global__ __launch_bounds__(256) void combine_kernel(
    const float* __restrict__ Wl, const float* __restrict__ bl,
    const float* __restrict__ Wr, int mode)
{
    extern __shared__ float smc[];
    float4* Wl4 = (float4*)smc;
    float4* Wr4 = Wl4 + 128 * 33;
    float4* xm4 = Wr4 + 128 * 33;
    float4* xs4 = xm4 + 32 * 33;

    const float* agg; const float* selfx; float* outp;
    if      (mode == 0) { agg = g_aggc; selfx = g_c;  outp = g_c2; }
    else if (mode == 1) { agg = g_aggu; selfx = g_u;  outp = g_u2; }
    else if (mode == 2) { agg = g_aggc; selfx = g_c2; outp = g_c;  }
    else                { agg = g_aggu; selfx = g_u2; outp = g_u;  }

    int tid = threadIdx.x;
    int n0 = blockIdx.x * 32;

    for (int idx = tid; idx < 128 * 32; idx += 256) {
        int r = idx >> 5, col = idx & 31;
        Wl4[r * 33 + col] = ((const float4*)Wl)[idx];
        Wr4[r * 33 + col] = ((const float4*)Wr)[idx];
    }
    for (int idx = tid; idx < 32 * 32; idx += 256) {
        int n = idx >> 5, k4 = idx & 31;
        xm4[n * 33 + k4] = ((const float4*)agg)[(n0 + n) * 32 + k4];
        xs4[n * 33 + k4] = ((const float4*)selfx)[(n0 + n) * 32 + k4];
    }
    __syncthreads();

    int n = tid >> 3, q = tid & 7;
    float acc[16];
#pragma unroll
    for (int i = 0; i < 16; i++) acc[i] = bl[q + 8 * i];
#pragma unroll 1
    for (int k4 = 0; k4 < 32; k4++) {
        float4 xm = xm4[n * 33 + k4];
        float4 xv = xs4[n * 33 + k4];
#pragma unroll
        for (int i = 0; i < 16; i++) {
            int j = q + 8 * i;
            float4 wlv = Wl4[j * 33 + k4];
            float4 wrv = Wr4[j * 33 + k4];
            DOT4(acc[i], wlv, xm);
            DOT4(acc[i], wrv, xv);
        }
    }
#pragma unroll
    for (int i = 0; i < 16; i++)
        outp[(n0 + n) * HD + q + 8 * i] = fmaxf(acc[i], 0.f);
}

// ---------------- classifier ----------------
#define CLS_SMEM ((128 * 65 + 32 * 65) * 16 + 512)
__global__ __launch_bounds__(256) void classifier_kernel(
    const float* __restrict__ W1, const float* __restrict__ b1,
    const float* __restrict__ W2, const float* __restrict__ b2,
    float* __restrict__ out)
{
    extern __shared__ float smk[];
    float4* W14 = (float4*)smk;
    float4* xc4 = W14 + 128 * 65;
    float*  W2s = (float*)(xc4 + 32 * 65);

    int tid = threadIdx.x;
    int n0 = blockIdx.x * 32;

    for (int idx = tid; idx < 128 * 64; idx += 256) {
        int r = idx >> 6, col = idx & 63;
        W14[r * 65 + col] = ((const float4*)W1)[idx];
    }
    for (int idx = tid; idx < 32 * 64; idx += 256) {
        int n = idx >> 6, k4 = idx & 63;
        float4 v = (k4 < 32) ? ((const float4*)g_u)[(n0 + n) * 32 + k4]
                             : ((const float4*)g_c)[(n0 + n) * 32 + (k4 - 32)];
        xc4[n * 65 + k4] = v;
    }
    if (tid < 128) W2s[tid] = W2[tid];
    __syncthreads();

    int n = tid >> 3, q = tid & 7;
    float acc[16];
#pragma unroll
    for (int i = 0; i < 16; i++) acc[i] = b1[q + 8 * i];
#pragma unroll 1
    for (int k4 = 0; k4 < 64; k4++) {
        float4 xv = xc4[n * 65 + k4];
#pragma unroll
        for (int i = 0; i < 16; i++) {
            float4 wv = W14[(q + 8 * i) * 65 + k4];
            DOT4(acc[i], wv, xv);
        }
    }
    float p = 0.f;
#pragma unroll
    for (int i = 0; i < 16; i++) {
        float h = fmaxf(acc[i], 0.f);
        p += h * W2s[q + 8 * i];
    }
    p += __shfl_xor_sync(0xffffffffu, p, 1);
    p += __shfl_xor_sync(0xffffffffu, p, 2);
    p += __shfl_xor_sync(0xffffffffu, p, 4);
    if (q == 0) out[n0 + n] = sigmoidf_(p + b2[0]);
}

// ---------------- launch ----------------
extern "C" void kernel_launch(void* const* d_in, const int* in_sizes, int n_in,
                              void* d_out, int out_size)
{
    const float* x_user    = (const float*)d_in[0];
    const float* x_content = (const float*)d_in[1];
    const int*   edge      = (const int*)  d_in[2];
    const float* W_ih      = (const float*)d_in[3];
    const float* W_hh      = (const float*)d_in[4];
    const float* b_ih      = (const float*)d_in[5];
    const float* b_hh      = (const float*)d_in[6];
    const float* Wc        = (const float*)d_in[7];
    const float* bc        = (const float*)d_in[8];
    const float* Wl0       = (const float*)d_in[9];
    const float* bl0       = (const float*)d_in[10];
    const float* Wr0       = (const float*)d_in[11];
    const float* Wl1       = (const float*)d_in[12];
    const float* bl1       = (const float*)d_in[13];
    const float* Wr1       = (const float*)d_in[14];
    const float* W1        = (const float*)d_in[15];
    const float* b1        = (const float*)d_in[16];
    const float* W2        = (const float*)d_in[17];
    const float* b2        = (const float*)d_in[18];
    float* out = (float*)d_out;

    const int* src = edge;
    const int* dst = edge + NE;

    cudaFuncSetAttribute(lstm_step_kernel,  cudaFuncAttributeMaxDynamicSharedMemorySize, GEMM_SMEM);
    cudaFuncSetAttribute(combine_kernel,    cudaFuncAttributeMaxDynamicSharedMemorySize, COMBINE_SMEM);
    cudaFuncSetAttribute(classifier_kernel, cudaFuncAttributeMaxDynamicSharedMemorySize, CLS_SMEM);

    // ---- LSTM prep + steps (profile slot lands on lstm_step) ----
    conv_x_kernel<<<NN * TT * EMBD / 8 / 256, 256>>>(x_user);
    pack_w_kernel<<<49152 / 256, 256>>>(W_ih, W_hh);
    zero_h_kernel<<<NN * HD / 8 / 256, 256>>>();
    for (int t = 0; t < TT; t++)
        lstm_step_kernel<<<dim3(NN / 128, 4), 256, GEMM_SMEM>>>(b_ih, b_hh, t);

    // ---- content features ----
    content_kernel<<<NN / 32, 256>>>(x_content, Wc, bc);

    // ---- CSR build ----
    zero_deg_kernel<<<NN / 256, 256>>>();
    count_kernel<<<NE / 256, 256>>>(src, dst);
    scan_kernel<<<2, 1024>>>();
    fill_kernel<<<NE / 256, 256>>>(src, dst);

    // ---- SAGE layer 0 ----
    agg_kernel<<<NN / 8, 256>>>(0);
    agg_kernel<<<NN / 8, 256>>>(1);
    combine_kernel<<<NN / 32, 256, COMBINE_SMEM>>>(Wl0, bl0, Wr0, 0);
    combine_kernel<<<NN / 32, 256, COMBINE_SMEM>>>(Wl0, bl0, Wr0, 1);

    // ---- SAGE layer 1 ----
    agg_kernel<<<NN / 8, 256>>>(2);
    agg_kernel<<<NN / 8, 256>>>(3);
    combine_kernel<<<NN / 32, 256, COMBINE_SMEM>>>(Wl1, bl1, Wr1, 2);
    combine_kernel<<<NN / 32, 256, COMBINE_SMEM>>>(Wl1, bl1, Wr1, 3);

    // ---- classifier ----
    classifier_kernel<<<NN / 32, 256, CLS_SMEM>>>(W1, b1, W2, b2, out);
}

// round 16
// speedup vs baseline: 35.8896x; 1.3652x over previous
#include <cuda_runtime.h>
#include <cuda_bf16.h>
#include <math.h>

#define NN   32768
#define TT   20
#define EMBD 64
#define HD   128
#define NE   1048576   // NN * 32

// ---------------- scratch (static device globals; no allocations) ----------------
__device__ float g_u   [NN * HD];
__device__ float g_c   [NN * HD];
__device__ float g_u2  [NN * HD];
__device__ float g_c2  [NN * HD];
__device__ float g_cstate[NN * HD]; // LSTM cell state (fp32)
__device__ __nv_bfloat16 g_xbf[NN * TT * EMBD];  // x_user in bf16
__device__ __nv_bfloat16 g_hbf[NN * HD];         // h (= u) in bf16
__device__ __nv_bfloat16 g_cbf   [NN * HD];      // content bf16
__device__ __nv_bfloat16 g_c2bf  [NN * HD];
__device__ __nv_bfloat16 g_u2bf  [NN * HD];
__device__ __nv_bfloat16 g_aggc_bf[NN * HD];     // mean (bf16) for combine A
__device__ __nv_bfloat16 g_aggu_bf[NN * HD];
__device__ unsigned g_Wpk [49152];  // LSTM weights, fragment-packed bf16 pairs
__device__ unsigned g_Wcpk[32768];  // combine weights: layer0 [0,16384), layer1 [16384,32768)

// CSR scratch
__device__ int g_deg_d[NN];
__device__ int g_deg_s[NN];
__device__ int g_off_d[NN + 1];
__device__ int g_off_s[NN + 1];
__device__ int g_cur_d[NN];
__device__ int g_cur_s[NN];
__device__ int g_eid_d[NE];
__device__ int g_eid_s[NE];

__device__ __forceinline__ float sigmoidf_(float x) { return 1.0f / (1.0f + expf(-x)); }

#define DOT4(acc, A, B) (acc) += (A).x*(B).x + (A).y*(B).y + (A).z*(B).z + (A).w*(B).w

__device__ __forceinline__ unsigned pack_bf2(float lo, float hi) {
    unsigned short s0 = __bfloat16_as_ushort(__float2bfloat16(lo));
    unsigned short s1 = __bfloat16_as_ushort(__float2bfloat16(hi));
    return ((unsigned)s1 << 16) | s0;
}

// ================= CSR build =================
__global__ void zero_deg_kernel() {
    int i = blockIdx.x * blockDim.x + threadIdx.x;
    if (i < NN) { g_deg_d[i] = 0; g_deg_s[i] = 0; }
}

__global__ void count_kernel(const int* __restrict__ src, const int* __restrict__ dst) {
    int e = blockIdx.x * blockDim.x + threadIdx.x;
    if (e < NE) {
        atomicAdd(&g_deg_d[dst[e]], 1);
        atomicAdd(&g_deg_s[src[e]], 1);
    }
}

__global__ __launch_bounds__(1024) void scan_kernel() {
    const int* deg = (blockIdx.x == 0) ? g_deg_d : g_deg_s;
    int* off = (blockIdx.x == 0) ? g_off_d : g_off_s;
    int* cur = (blockIdx.x == 0) ? g_cur_d : g_cur_s;

    __shared__ int part[1024];
    int tid = threadIdx.x;
    int base = tid * 32;

    int s = 0;
#pragma unroll 4
    for (int k = 0; k < 32; k++) s += deg[base + k];
    part[tid] = s;
    __syncthreads();
    for (int d = 1; d < 1024; d <<= 1) {
        int v = (tid >= d) ? part[tid - d] : 0;
        __syncthreads();
        if (tid >= d) part[tid] += v;
        __syncthreads();
    }
    int run = (tid == 0) ? 0 : part[tid - 1];
#pragma unroll 4
    for (int k = 0; k < 32; k++) {
        off[base + k] = run;
        cur[base + k] = run;
        run += deg[base + k];
    }
    if (tid == 1023) off[NN] = run;
}

__global__ void fill_kernel(const int* __restrict__ src, const int* __restrict__ dst) {
    int e = blockIdx.x * blockDim.x + threadIdx.x;
    if (e < NE) {
        int s = src[e], d = dst[e];
        int p = atomicAdd(&g_cur_d[d], 1); g_eid_d[p] = s;
        int q = atomicAdd(&g_cur_s[s], 1); g_eid_s[q] = d;
    }
}

// ================= CSR mean-aggregate: one warp per node -> bf16 mean =================
__global__ __launch_bounds__(256) void agg_kernel(int mode)
{
    const int* off; const int* eid; const float* feat; __nv_bfloat16* outbf;
    if      (mode == 0) { off = g_off_d; eid = g_eid_d; feat = g_u;  outbf = g_aggc_bf; }
    else if (mode == 1) { off = g_off_s; eid = g_eid_s; feat = g_c;  outbf = g_aggu_bf; }
    else if (mode == 2) { off = g_off_d; eid = g_eid_d; feat = g_u2; outbf = g_aggc_bf; }
    else                { off = g_off_s; eid = g_eid_s; feat = g_c2; outbf = g_aggu_bf; }

    int n = blockIdx.x * 8 + (threadIdx.x >> 5);
    int lane = threadIdx.x & 31;
    int a = off[n], b = off[n + 1];

    float4 acc = make_float4(0.f, 0.f, 0.f, 0.f);
    const float4* f4 = (const float4*)feat;

    int i = a;
    for (; i + 4 <= b; i += 4) {
        int e0 = __ldg(&eid[i]),     e1 = __ldg(&eid[i + 1]);
        int e2 = __ldg(&eid[i + 2]), e3 = __ldg(&eid[i + 3]);
        float4 v0 = f4[e0 * 32 + lane];
        float4 v1 = f4[e1 * 32 + lane];
        float4 v2 = f4[e2 * 32 + lane];
        float4 v3 = f4[e3 * 32 + lane];
        acc.x += v0.x + v1.x + v2.x + v3.x;
        acc.y += v0.y + v1.y + v2.y + v3.y;
        acc.z += v0.z + v1.z + v2.z + v3.z;
        acc.w += v0.w + v1.w + v2.w + v3.w;
    }
    for (; i < b; i++) {
        int e0 = __ldg(&eid[i]);
        float4 v0 = f4[e0 * 32 + lane];
        acc.x += v0.x; acc.y += v0.y; acc.z += v0.z; acc.w += v0.w;
    }
    float inv = (b > a) ? 1.0f / (float)(b - a) : 1.0f;
    uint2 o;
    o.x = pack_bf2(acc.x * inv, acc.y * inv);
    o.y = pack_bf2(acc.z * inv, acc.w * inv);
    ((uint2*)outbf)[n * 32 + lane] = o;
}

// ================= LSTM prep =================
__global__ void conv_x_kernel(const float* __restrict__ x_user) {
    int i = blockIdx.x * 256 + threadIdx.x;
    const float4* s = (const float4*)x_user + (size_t)i * 2;
    float4 a = s[0], b = s[1];
    uint4 o;
    o.x = pack_bf2(a.x, a.y);
    o.y = pack_bf2(a.z, a.w);
    o.z = pack_bf2(b.x, b.y);
    o.w = pack_bf2(b.z, b.w);
    ((uint4*)g_xbf)[i] = o;
}

__global__ void zero_h_kernel() {
    int i = blockIdx.x * 256 + threadIdx.x;
    ((uint4*)g_hbf)[i] = make_uint4(0, 0, 0, 0);
}

// LSTM weight pack (unchanged from R15)
__global__ void pack_w_kernel(const float* __restrict__ W_ih, const float* __restrict__ W_hh) {
    int i = blockIdx.x * 256 + threadIdx.x;    // 49152
    int rest = i & 2047;
    int ykt = i >> 11;
    int y = ykt / 6, kt = ykt % 6;
    int v = rest & 3, lane = (rest >> 2) & 31, jp = (rest >> 7) & 3;
    int ki = (rest >> 9) & 1, wn = (rest >> 10) & 1;
    int fn = 2 * jp + (v >> 1), r = v & 1;
    int n = wn * 64 + fn * 8 + (lane >> 2);
    int k = kt * 32 + ki * 16 + (lane & 3) * 2 + r * 8;
    int grow = (n >> 5) * 128 + y * 32 + (n & 31);
    float w0 = (k < 64) ? W_ih[grow * 64 + k]     : W_hh[grow * 128 + k - 64];
    float w1 = (k < 63) ? W_ih[grow * 64 + k + 1] : W_hh[grow * 128 + k + 1 - 64];
    g_Wpk[i] = pack_bf2(w0, w1);
}

// Combine weight pack: [Wl | Wr] per layer, N=128 rows, K=256.
// offset = L*16384 + kt*2048 + (((wn*2+ki)*4+jp)*32+lane)*4 + v
// fn=2*jp+(v>>1), r=v&1; n = wn*64+fn*8+(lane>>2); k = kt*32+ki*16+(lane&3)*2+r*8.
__global__ void pack_wc_kernel(
    const float* __restrict__ Wl0, const float* __restrict__ Wr0,
    const float* __restrict__ Wl1, const float* __restrict__ Wr1)
{
    int i = blockIdx.x * 256 + threadIdx.x;    // 32768
    int L = i >> 14;
    int rest = i & 16383;
    int kt = rest >> 11;
    int sub = rest & 2047;
    int v = sub & 3, lane = (sub >> 2) & 31, jp = (sub >> 7) & 3;
    int ki = (sub >> 9) & 1, wn = (sub >> 10) & 1;
    int fn = 2 * jp + (v >> 1), r = v & 1;
    int n = wn * 64 + fn * 8 + (lane >> 2);
    int k = kt * 32 + ki * 16 + (lane & 3) * 2 + r * 8;
    const float* Wl = L ? Wl1 : Wl0;
    const float* Wr = L ? Wr1 : Wr0;
    float w0 = (k < 128) ? Wl[n * 128 + k]     : Wr[n * 128 + k - 128];
    float w1 = (k < 128) ? Wl[n * 128 + k + 1] : Wr[n * 128 + k + 1 - 128];
    g_Wcpk[i] = pack_bf2(w0, w1);
}

// =====================================================================
// LSTM step (unchanged from R15): bf16 GEMM m16n8k16 + fused cell.
// =====================================================================
#define GEMM_SMEM 36864

__device__ __forceinline__ void mma_bf16(float d[4], const unsigned a[4], const unsigned b[2]) {
    asm volatile(
        "mma.sync.aligned.m16n8k16.row.col.f32.bf16.bf16.f32 "
        "{%0,%1,%2,%3}, {%4,%5,%6,%7}, {%8,%9}, {%0,%1,%2,%3};"
        : "+f"(d[0]), "+f"(d[1]), "+f"(d[2]), "+f"(d[3])
        : "r"(a[0]), "r"(a[1]), "r"(a[2]), "r"(a[3]), "r"(b[0]), "r"(b[1]));
}

__global__ __launch_bounds__(256, 2) void lstm_step_kernel(
    const float* __restrict__ b_ih, const float* __restrict__ b_hh, int t)
{
    extern __shared__ char smraw[];
    __nv_bfloat16* Abf[2] = { (__nv_bfloat16*)smraw, (__nv_bfloat16*)(smraw + 10240) };
    unsigned* Bu[2] = { (unsigned*)(smraw + 20480), (unsigned*)(smraw + 28672) };
    __shared__ float bs[128];

    int tid = threadIdx.x;
    int u0 = blockIdx.x * 128;
    int y  = blockIdx.y;

    if (tid < 128) {
        int gate = tid >> 5, w = tid & 31;
        int grow = gate * 128 + y * 32 + w;
        bs[tid] = b_ih[grow] + b_hh[grow];
    }

    unsigned sA[2] = { (unsigned)__cvta_generic_to_shared(Abf[0]),
                       (unsigned)__cvta_generic_to_shared(Abf[1]) };
    unsigned sB[2] = { (unsigned)__cvta_generic_to_shared(Bu[0]),
                       (unsigned)__cvta_generic_to_shared(Bu[1]) };

    auto issue_tile = [&](int kt, int buf) {
#pragma unroll
        for (int i = 0; i < 2; i++) {
            int idx = tid + i * 256;
            int u = idx >> 2, k4 = idx & 3;
            const __nv_bfloat16* srcp = (kt < 2)
                ? g_xbf + ((size_t)(u0 + u) * TT + t) * EMBD + kt * 32 + k4 * 8
                : g_hbf + (size_t)(u0 + u) * HD + (kt - 2) * 32 + k4 * 8;
            unsigned dst = sA[buf] + (unsigned)(u * 80 + k4 * 16);
            asm volatile("cp.async.ca.shared.global [%0], [%1], 16;" :: "r"(dst), "l"(srcp) : "memory");
        }
        {
            const unsigned* basep = g_Wpk + (size_t)(y * 6 + kt) * 2048;
#pragma unroll
            for (int i = 0; i < 2; i++) {
                int idx = tid + i * 256;
                const unsigned* srcp = basep + idx * 4;
                unsigned dst = sB[buf] + (unsigned)(idx * 16);
                asm volatile("cp.async.ca.shared.global [%0], [%1], 16;" :: "r"(dst), "l"(srcp) : "memory");
            }
        }
        asm volatile("cp.async.commit_group;" ::: "memory");
    };

    issue_tile(0, 0);

    int wid = tid >> 5, lane = tid & 31;
    int wm = wid >> 1, wn = wid & 1;
    int urow = wm * 32, ncol = wn * 64;
    int lr = lane >> 2, lc = lane & 3;

    unsigned aoff = (unsigned)((urow + (lane & 15)) * 80 + (lane >> 4) * 16);

    float acc[2][8][4];
#pragma unroll
    for (int fm = 0; fm < 2; fm++)
#pragma unroll
        for (int fn = 0; fn < 8; fn++)
#pragma unroll
            for (int r = 0; r < 4; r++) acc[fm][fn][r] = 0.f;

#pragma unroll 1
    for (int kt = 0; kt < 6; kt++) {
        int cur = kt & 1;
        if (kt < 5) {
            issue_tile(kt + 1, cur ^ 1);
            asm volatile("cp.async.wait_group 1;" ::: "memory");
        } else {
            asm volatile("cp.async.wait_group 0;" ::: "memory");
        }
        __syncthreads();

        const uint4* Bp = (const uint4*)Bu[cur];
#pragma unroll
        for (int ki = 0; ki < 2; ki++) {
            unsigned afr[2][4], bfr[8][2];
#pragma unroll
            for (int fm = 0; fm < 2; fm++) {
                unsigned ad = sA[cur] + aoff + (unsigned)(fm * 16 * 80 + ki * 32);
                asm volatile("ldmatrix.sync.aligned.m8n8.x4.shared.b16 {%0,%1,%2,%3}, [%4];"
                             : "=r"(afr[fm][0]), "=r"(afr[fm][1]),
                               "=r"(afr[fm][2]), "=r"(afr[fm][3])
                             : "r"(ad));
            }
#pragma unroll
            for (int jp = 0; jp < 4; jp++) {
                uint4 v = Bp[(((wn * 2 + ki) * 4 + jp) * 32) + lane];
                bfr[2 * jp][0]     = v.x;
                bfr[2 * jp][1]     = v.y;
                bfr[2 * jp + 1][0] = v.z;
                bfr[2 * jp + 1][1] = v.w;
            }
#pragma unroll
            for (int fm = 0; fm < 2; fm++)
#pragma unroll
                for (int fn = 0; fn < 8; fn++)
                    mma_bf16(acc[fm][fn], afr[fm], bfr[fn]);
        }
        __syncthreads();
    }

    float* S = (float*)smraw;
#pragma unroll 1
    for (int p = 0; p < 2; p++) {
        if ((wm >> 1) == p) {
            int rbase = urow - p * 64;
#pragma unroll
            for (int fm = 0; fm < 2; fm++) {
#pragma unroll
                for (int fn = 0; fn < 8; fn++) {
                    int rr = rbase + fm * 16 + lr;
                    int cc = ncol + fn * 8 + lc * 2;
                    S[cc * 69 + rr]           = acc[fm][fn][0];
                    S[(cc + 1) * 69 + rr]     = acc[fm][fn][1];
                    S[cc * 69 + rr + 8]       = acc[fm][fn][2];
                    S[(cc + 1) * 69 + rr + 8] = acc[fm][fn][3];
                }
            }
        }
        __syncthreads();

#pragma unroll
        for (int i = 0; i < 8; i++) {
            int flat = tid + i * 256;
            int rr = flat >> 5, w = flat & 31;
            float gi = S[w * 69 + rr]          + bs[w];
            float gf = S[(w + 32) * 69 + rr]   + bs[32 + w];
            float gg = S[(w + 64) * 69 + rr]   + bs[64 + w];
            float go = S[(w + 96) * 69 + rr]   + bs[96 + w];
            size_t gidx = (size_t)(u0 + p * 64 + rr) * HD + y * 32 + w;
            float cold = (t == 0) ? 0.f : g_cstate[gidx];
            float c = sigmoidf_(gf) * cold + sigmoidf_(gi) * tanhf(gg);
            g_cstate[gidx] = c;
            float h = sigmoidf_(go) * tanhf(c);
            g_hbf[gidx] = __float2bfloat16(h);
            if (t == TT - 1) g_u[gidx] = h;
        }
        __syncthreads();
    }
}

// =====================================================================
// SAGE combine as bf16 GEMM: out = relu([mean | self] @ [Wl|Wr]^T + bl)
//  Grid NN/128, 256 thr, occ 2. Tile 128(M users) x 128(N outs), K=256
//  in 8 chunks of 32. Epilogue: bias+relu from fragments, fp32 + bf16 out.
// =====================================================================
__global__ __launch_bounds__(256, 2) void combine_gemm_kernel(
    const float* __restrict__ bl, int mode)
{
    extern __shared__ char smraw[];
    __nv_bfloat16* Abf[2] = { (__nv_bfloat16*)smraw, (__nv_bfloat16*)(smraw + 10240) };
    unsigned* Bu[2] = { (unsigned*)(smraw + 20480), (unsigned*)(smraw + 28672) };
    __shared__ float bs[128];

    const __nv_bfloat16* aggsrc; const __nv_bfloat16* selfsrc;
    const unsigned* wp; float* outf; __nv_bfloat16* outbf;
    if      (mode == 0) { aggsrc = g_aggc_bf; selfsrc = g_cbf;  wp = g_Wcpk;         outf = g_c2; outbf = g_c2bf; }
    else if (mode == 1) { aggsrc = g_aggu_bf; selfsrc = g_hbf;  wp = g_Wcpk;         outf = g_u2; outbf = g_u2bf; }
    else if (mode == 2) { aggsrc = g_aggc_bf; selfsrc = g_c2bf; wp = g_Wcpk + 16384; outf = g_c;  outbf = 0; }
    else                { aggsrc = g_aggu_bf; selfsrc = g_u2bf; wp = g_Wcpk + 16384; outf = g_u;  outbf = 0; }

    int tid = threadIdx.x;
    int u0 = blockIdx.x * 128;

    if (tid < 128) bs[tid] = bl[tid];

    unsigned sA[2] = { (unsigned)__cvta_generic_to_shared(Abf[0]),
                       (unsigned)__cvta_generic_to_shared(Abf[1]) };
    unsigned sB[2] = { (unsigned)__cvta_generic_to_shared(Bu[0]),
                       (unsigned)__cvta_generic_to_shared(Bu[1]) };

    auto issue_tile = [&](int kt, int buf) {
#pragma unroll
        for (int i = 0; i < 2; i++) {
            int idx = tid + i * 256;
            int u = idx >> 2, k4 = idx & 3;
            const __nv_bfloat16* srcp = (kt < 4)
                ? aggsrc  + (size_t)(u0 + u) * HD + kt * 32 + k4 * 8
                : selfsrc + (size_t)(u0 + u) * HD + (kt - 4) * 32 + k4 * 8;
            unsigned dst = sA[buf] + (unsigned)(u * 80 + k4 * 16);
            asm volatile("cp.async.ca.shared.global [%0], [%1], 16;" :: "r"(dst), "l"(srcp) : "memory");
        }
        {
            const unsigned* basep = wp + (size_t)kt * 2048;
#pragma unroll
            for (int i = 0; i < 2; i++) {
                int idx = tid + i * 256;
                const unsigned* srcp = basep + idx * 4;
                unsigned dst = sB[buf] + (unsigned)(idx * 16);
                asm volatile("cp.async.ca.shared.global [%0], [%1], 16;" :: "r"(dst), "l"(srcp) : "memory");
            }
        }
        asm volatile("cp.async.commit_group;" ::: "memory");
    };

    issue_tile(0, 0);

    int wid = tid >> 5, lane = tid & 31;
    int wm = wid >> 1, wn = wid & 1;
    int urow = wm * 32, ncol = wn * 64;
    int lr = lane >> 2, lc = lane & 3;

    unsigned aoff = (unsigned)((urow + (lane & 15)) * 80 + (lane >> 4) * 16);

    float acc[2][8][4];
#pragma unroll
    for (int fm = 0; fm < 2; fm++)
#pragma unroll
        for (int fn = 0; fn < 8; fn++)
#pragma unroll
            for (int r = 0; r < 4; r++) acc[fm][fn][r] = 0.f;

#pragma unroll 1
    for (int kt = 0; kt < 8; kt++) {
        int cur = kt & 1;
        if (kt < 7) {
            issue_tile(kt + 1, cur ^ 1);
            asm volatile("cp.async.wait_group 1;" ::: "memory");
        } else {
            asm volatile("cp.async.wait_group 0;" ::: "memory");
        }
        __syncthreads();

        const uint4* Bp = (const uint4*)Bu[cur];
#pragma unroll
        for (int ki = 0; ki < 2; ki++) {
            unsigned afr[2][4], bfr[8][2];
#pragma unroll
            for (int fm = 0; fm < 2; fm++) {
                unsigned ad = sA[cur] + aoff + (unsigned)(fm * 16 * 80 + ki * 32);
                asm volatile("ldmatrix.sync.aligned.m8n8.x4.shared.b16 {%0,%1,%2,%3}, [%4];"
                             : "=r"(afr[fm][0]), "=r"(afr[fm][1]),
                               "=r"(afr[fm][2]), "=r"(afr[fm][3])
                             : "r"(ad));
            }
#pragma unroll
            for (int jp = 0; jp < 4; jp++) {
                uint4 v = Bp[(((wn * 2 + ki) * 4 + jp) * 32) + lane];
                bfr[2 * jp][0]     = v.x;
                bfr[2 * jp][1]     = v.y;
                bfr[2 * jp + 1][0] = v.z;
                bfr[2 * jp + 1][1] = v.w;
            }
#pragma unroll
            for (int fm = 0; fm < 2; fm++)
#pragma unroll
                for (int fn = 0; fn < 8; fn++)
                    mma_bf16(acc[fm][fn], afr[fm], bfr[fn]);
        }
        __syncthreads();
    }

    // epilogue: bias + relu, fp32 out (+ optional bf16 mirror)
#pragma unroll
    for (int fm = 0; fm < 2; fm++) {
#pragma unroll
        for (int fn = 0; fn < 8; fn++) {
            int row = u0 + urow + fm * 16 + lr;
            int col = ncol + fn * 8 + lc * 2;
            float b0 = bs[col], b1 = bs[col + 1];
            float v0 = fmaxf(acc[fm][fn][0] + b0, 0.f);
            float v1 = fmaxf(acc[fm][fn][1] + b1, 0.f);
            float v2 = fmaxf(acc[fm][fn][2] + b0, 0.f);
            float v3 = fmaxf(acc[fm][fn][3] + b1, 0.f);
            *(float2*)&outf[(size_t)row * HD + col]       = make_float2(v0, v1);
            *(float2*)&outf[(size_t)(row + 8) * HD + col] = make_float2(v2, v3);
            if (outbf) {
                ((unsigned*)outbf)[((size_t)row * HD + col) >> 1]       = pack_bf2(v0, v1);
                ((unsigned*)outbf)[((size_t)(row + 8) * HD + col) >> 1] = pack_bf2(v2, v3);
            }
        }
    }
}

// ---------------- content linear: c = x_content @ Wc^T + bc (+ bf16 mirror) ----------------
__global__ __launch_bounds__(256) void content_kernel(
    const float* __restrict__ xc, const float* __restrict__ Wc, const float* __restrict__ bc)
{
    __shared__ float4 Wc4s[128 * 17];
    __shared__ float4 xs[32 * 17];
    int tid = threadIdx.x;
    int n0 = blockIdx.x * 32;

    for (int idx = tid; idx < 128 * 16; idx += 256) {
        int r = idx >> 4, col = idx & 15;
        Wc4s[r * 17 + col] = ((const float4*)Wc)[idx];
    }
    for (int idx = tid; idx < 32 * 16; idx += 256) {
        int n = idx >> 4, k4 = idx & 15;
        xs[n * 17 + k4] = ((const float4*)xc)[(n0 + n) * 16 + k4];
    }
    __syncthreads();

    int n = tid >> 3, q = tid & 7;
    float acc[16];
#pragma unroll
    for (int i = 0; i < 16; i++) acc[i] = bc[q + 8 * i];
#pragma unroll 1
    for (int k4 = 0; k4 < 16; k4++) {
        float4 xv = xs[n * 17 + k4];
#pragma unroll
        for (int i = 0; i < 16; i++) {
            float4 wv = Wc4s[(q + 8 * i) * 17 + k4];
            DOT4(acc[i], wv, xv);
        }
    }
#pragma unroll
    for (int i = 0; i < 16; i++) {
        int m = q + 8 * i;
        g_c[(n0 + n) * HD + m] = acc[i];
        g_cbf[(n0 + n) * HD + m] = __float2bfloat16(acc[i]);
    }
}

// ---------------- classifier ----------------
#define CLS_SMEM ((128 * 65 + 32 * 65) * 16 + 512)
__global__ __launch_bounds__(256) void classifier_kernel(
    const float* __restrict__ W1, const float* __restrict__ b1,
    const float* __restrict__ W2, const float* __restrict__ b2,
    float* __restrict__ out)
{
    extern __shared__ float smk[];
    float4* W14 = (float4*)smk;
    float4* xc4 = W14 + 128 * 65;
    float*  W2s = (float*)(xc4 + 32 * 65);

    int tid = threadIdx.x;
    int n0 = blockIdx.x * 32;

    for (int idx = tid; idx < 128 * 64; idx += 256) {
        int r = idx >> 6, col = idx & 63;
        W14[r * 65 + col] = ((const float4*)W1)[idx];
    }
    for (int idx = tid; idx < 32 * 64; idx += 256) {
        int n = idx >> 6, k4 = idx & 63;
        float4 v = (k4 < 32) ? ((const float4*)g_u)[(n0 + n) * 32 + k4]
                             : ((const float4*)g_c)[(n0 + n) * 32 + (k4 - 32)];
        xc4[n * 65 + k4] = v;
    }
    if (tid < 128) W2s[tid] = W2[tid];
    __syncthreads();

    int n = tid >> 3, q = tid & 7;
    float acc[16];
#pragma unroll
    for (int i = 0; i < 16; i++) acc[i] = b1[q + 8 * i];
#pragma unroll 1
    for (int k4 = 0; k4 < 64; k4++) {
        float4 xv = xc4[n * 65 + k4];
#pragma unroll
        for (int i = 0; i < 16; i++) {
            float4 wv = W14[(q + 8 * i) * 65 + k4];
            DOT4(acc[i], wv, xv);
        }
    }
    float p = 0.f;
#pragma unroll
    for (int i = 0; i < 16; i++) {
        float h = fmaxf(acc[i], 0.f);
        p += h * W2s[q + 8 * i];
    }
    p += __shfl_xor_sync(0xffffffffu, p, 1);
    p += __shfl_xor_sync(0xffffffffu, p, 2);
    p += __shfl_xor_sync(0xffffffffu, p, 4);
    if (q == 0) out[n0 + n] = sigmoidf_(p + b2[0]);
}

// ---------------- launch ----------------
extern "C" void kernel_launch(void* const* d_in, const int* in_sizes, int n_in,
                              void* d_out, int out_size)
{
    const float* x_user    = (const float*)d_in[0];
    const float* x_content = (const float*)d_in[1];
    const int*   edge      = (const int*)  d_in[2];
    const float* W_ih      = (const float*)d_in[3];
    const float* W_hh      = (const float*)d_in[4];
    const float* b_ih      = (const float*)d_in[5];
    const float* b_hh      = (const float*)d_in[6];
    const float* Wc        = (const float*)d_in[7];
    const float* bc        = (const float*)d_in[8];
    const float* Wl0       = (const float*)d_in[9];
    const float* bl0       = (const float*)d_in[10];
    const float* Wr0       = (const float*)d_in[11];
    const float* Wl1       = (const float*)d_in[12];
    const float* bl1       = (const float*)d_in[13];
    const float* Wr1       = (const float*)d_in[14];
    const float* W1        = (const float*)d_in[15];
    const float* b1        = (const float*)d_in[16];
    const float* W2        = (const float*)d_in[17];
    const float* b2        = (const float*)d_in[18];
    float* out = (float*)d_out;

    const int* src = edge;
    const int* dst = edge + NE;

    cudaFuncSetAttribute(lstm_step_kernel,    cudaFuncAttributeMaxDynamicSharedMemorySize, GEMM_SMEM);
    cudaFuncSetAttribute(combine_gemm_kernel, cudaFuncAttributeMaxDynamicSharedMemorySize, GEMM_SMEM);
    cudaFuncSetAttribute(classifier_kernel,   cudaFuncAttributeMaxDynamicSharedMemorySize, CLS_SMEM);

    // ---- LSTM prep + steps ----
    conv_x_kernel<<<NN * TT * EMBD / 8 / 256, 256>>>(x_user);
    pack_w_kernel<<<49152 / 256, 256>>>(W_ih, W_hh);
    zero_h_kernel<<<NN * HD / 8 / 256, 256>>>();
    pack_wc_kernel<<<32768 / 256, 256>>>(Wl0, Wr0, Wl1, Wr1);
    for (int t = 0; t < TT; t++)
        lstm_step_kernel<<<dim3(NN / 128, 4), 256, GEMM_SMEM>>>(b_ih, b_hh, t);

    // ---- content features ----
    content_kernel<<<NN / 32, 256>>>(x_content, Wc, bc);

    // ---- CSR build ----
    zero_deg_kernel<<<NN / 256, 256>>>();
    count_kernel<<<NE / 256, 256>>>(src, dst);
    scan_kernel<<<2, 1024>>>();
    fill_kernel<<<NE / 256, 256>>>(src, dst);

    // ---- SAGE layer 0 ----
    agg_kernel<<<NN / 8, 256>>>(0);
    agg_kernel<<<NN / 8, 256>>>(1);
    combine_gemm_kernel<<<NN / 128, 256, GEMM_SMEM>>>(bl0, 0);   // -> g_c2 (+bf)
    combine_gemm_kernel<<<NN / 128, 256, GEMM_SMEM>>>(bl0, 1);   // -> g_u2 (+bf)

    // ---- SAGE layer 1 ----
    agg_kernel<<<NN / 8, 256>>>(2);
    agg_kernel<<<NN / 8, 256>>>(3);
    combine_gemm_kernel<<<NN / 128, 256, GEMM_SMEM>>>(bl1, 2);   // -> g_c
    combine_gemm_kernel<<<NN / 128, 256, GEMM_SMEM>>>(bl1, 3);   // -> g_u

    // ---- classifier ----
    classifier_kernel<<<NN / 32, 256, CLS_SMEM>>>(W1, b1, W2, b2, out);
}

// round 17
// speedup vs baseline: 36.7750x; 1.0247x over previous
#include <cuda_runtime.h>
#include <cuda_bf16.h>
#include <math.h>

#define NN   32768
#define TT   20
#define EMBD 64
#define HD   128
#define NE   1048576   // NN * 32

// ---------------- scratch (static device globals; no allocations) ----------------
__device__ float g_u   [NN * HD];
__device__ float g_c   [NN * HD];
__device__ float g_u2  [NN * HD];
__device__ float g_c2  [NN * HD];
__device__ __nv_bfloat16 g_xbf[NN * TT * EMBD];  // x_user in bf16
__device__ __nv_bfloat16 g_hbf[NN * HD];         // final h (= u) in bf16
__device__ __nv_bfloat16 g_cbf   [NN * HD];      // content bf16
__device__ __nv_bfloat16 g_c2bf  [NN * HD];
__device__ __nv_bfloat16 g_u2bf  [NN * HD];
__device__ __nv_bfloat16 g_aggc_bf[NN * HD];     // mean (bf16) for combine A
__device__ __nv_bfloat16 g_aggu_bf[NN * HD];
__device__ unsigned g_Wpk [49152];  // LSTM weights, gate-minor fragment pack (6 chunks x 8192 u32)
__device__ unsigned g_Wcpk[32768];  // combine weights: layer0 [0,16384), layer1 [16384,32768)

// CSR scratch
__device__ int g_deg_d[NN];
__device__ int g_deg_s[NN];
__device__ int g_off_d[NN + 1];
__device__ int g_off_s[NN + 1];
__device__ int g_cur_d[NN];
__device__ int g_cur_s[NN];
__device__ int g_eid_d[NE];
__device__ int g_eid_s[NE];

__device__ __forceinline__ float sigmoidf_(float x) { return 1.0f / (1.0f + expf(-x)); }

#define DOT4(acc, A, B) (acc) += (A).x*(B).x + (A).y*(B).y + (A).z*(B).z + (A).w*(B).w

__device__ __forceinline__ unsigned pack_bf2(float lo, float hi) {
    unsigned short s0 = __bfloat16_as_ushort(__float2bfloat16(lo));
    unsigned short s1 = __bfloat16_as_ushort(__float2bfloat16(hi));
    return ((unsigned)s1 << 16) | s0;
}

// ================= CSR build =================
__global__ void zero_deg_kernel() {
    int i = blockIdx.x * blockDim.x + threadIdx.x;
    if (i < NN) { g_deg_d[i] = 0; g_deg_s[i] = 0; }
}

__global__ void count_kernel(const int* __restrict__ src, const int* __restrict__ dst) {
    int e = blockIdx.x * blockDim.x + threadIdx.x;
    if (e < NE) {
        atomicAdd(&g_deg_d[dst[e]], 1);
        atomicAdd(&g_deg_s[src[e]], 1);
    }
}

__global__ __launch_bounds__(1024) void scan_kernel() {
    const int* deg = (blockIdx.x == 0) ? g_deg_d : g_deg_s;
    int* off = (blockIdx.x == 0) ? g_off_d : g_off_s;
    int* cur = (blockIdx.x == 0) ? g_cur_d : g_cur_s;

    __shared__ int part[1024];
    int tid = threadIdx.x;
    int base = tid * 32;

    int s = 0;
#pragma unroll 4
    for (int k = 0; k < 32; k++) s += deg[base + k];
    part[tid] = s;
    __syncthreads();
    for (int d = 1; d < 1024; d <<= 1) {
        int v = (tid >= d) ? part[tid - d] : 0;
        __syncthreads();
        if (tid >= d) part[tid] += v;
        __syncthreads();
    }
    int run = (tid == 0) ? 0 : part[tid - 1];
#pragma unroll 4
    for (int k = 0; k < 32; k++) {
        off[base + k] = run;
        cur[base + k] = run;
        run += deg[base + k];
    }
    if (tid == 1023) off[NN] = run;
}

__global__ void fill_kernel(const int* __restrict__ src, const int* __restrict__ dst) {
    int e = blockIdx.x * blockDim.x + threadIdx.x;
    if (e < NE) {
        int s = src[e], d = dst[e];
        int p = atomicAdd(&g_cur_d[d], 1); g_eid_d[p] = s;
        int q = atomicAdd(&g_cur_s[s], 1); g_eid_s[q] = d;
    }
}

// ================= CSR mean-aggregate: one warp per node -> bf16 mean =================
__global__ __launch_bounds__(256) void agg_kernel(int mode)
{
    const int* off; const int* eid; const float* feat; __nv_bfloat16* outbf;
    if      (mode == 0) { off = g_off_d; eid = g_eid_d; feat = g_u;  outbf = g_aggc_bf; }
    else if (mode == 1) { off = g_off_s; eid = g_eid_s; feat = g_c;  outbf = g_aggu_bf; }
    else if (mode == 2) { off = g_off_d; eid = g_eid_d; feat = g_u2; outbf = g_aggc_bf; }
    else                { off = g_off_s; eid = g_eid_s; feat = g_c2; outbf = g_aggu_bf; }

    int n = blockIdx.x * 8 + (threadIdx.x >> 5);
    int lane = threadIdx.x & 31;
    int a = off[n], b = off[n + 1];

    float4 acc = make_float4(0.f, 0.f, 0.f, 0.f);
    const float4* f4 = (const float4*)feat;

    int i = a;
    for (; i + 4 <= b; i += 4) {
        int e0 = __ldg(&eid[i]),     e1 = __ldg(&eid[i + 1]);
        int e2 = __ldg(&eid[i + 2]), e3 = __ldg(&eid[i + 3]);
        float4 v0 = f4[e0 * 32 + lane];
        float4 v1 = f4[e1 * 32 + lane];
        float4 v2 = f4[e2 * 32 + lane];
        float4 v3 = f4[e3 * 32 + lane];
        acc.x += v0.x + v1.x + v2.x + v3.x;
        acc.y += v0.y + v1.y + v2.y + v3.y;
        acc.z += v0.z + v1.z + v2.z + v3.z;
        acc.w += v0.w + v1.w + v2.w + v3.w;
    }
    for (; i < b; i++) {
        int e0 = __ldg(&eid[i]);
        float4 v0 = f4[e0 * 32 + lane];
        acc.x += v0.x; acc.y += v0.y; acc.z += v0.z; acc.w += v0.w;
    }
    float inv = (b > a) ? 1.0f / (float)(b - a) : 1.0f;
    uint2 o;
    o.x = pack_bf2(acc.x * inv, acc.y * inv);
    o.y = pack_bf2(acc.z * inv, acc.w * inv);
    ((uint2*)outbf)[n * 32 + lane] = o;
}

// ================= LSTM prep =================
__global__ void conv_x_kernel(const float* __restrict__ x_user) {
    int i = blockIdx.x * 256 + threadIdx.x;
    const float4* s = (const float4*)x_user + (size_t)i * 2;
    float4 a = s[0], b = s[1];
    uint4 o;
    o.x = pack_bf2(a.x, a.y);
    o.y = pack_bf2(a.z, a.w);
    o.z = pack_bf2(b.x, b.y);
    o.w = pack_bf2(b.z, b.w);
    ((uint4*)g_xbf)[i] = o;
}

// LSTM weight pack, GATE-MINOR: col n -> gate = n&3, hidden = n>>2.
// Per chunk kt (6 total, 8192 u32 each): u32 idx = kt*8192 + (((wn*2+ki)*4+jp)*32+lane)*4 + v
// fn = 2*jp+(v>>1), r = v&1; n = wn*64 + fn*8 + (lane>>2);
// k = kt*32 + ki*16 + (lane&3)*2 + r*8; grow = (n&3)*128 + (n>>2).
__global__ void pack_w_kernel(const float* __restrict__ W_ih, const float* __restrict__ W_hh) {
    int i = blockIdx.x * 256 + threadIdx.x;    // 49152
    int kt = i >> 13;
    int sub = i & 8191;
    int v = sub & 3, lane = (sub >> 2) & 31, jp = (sub >> 7) & 3;
    int ki = (sub >> 9) & 1, wn = (sub >> 10) & 7;
    int fn = 2 * jp + (v >> 1), r = v & 1;
    int n = wn * 64 + fn * 8 + (lane >> 2);
    int k = kt * 32 + ki * 16 + (lane & 3) * 2 + r * 8;
    int grow = (n & 3) * 128 + (n >> 2);
    float w0 = (k < 64) ? W_ih[grow * 64 + k]     : W_hh[grow * 128 + k - 64];
    float w1 = (k < 64) ? W_ih[grow * 64 + k + 1] : W_hh[grow * 128 + k + 1 - 64];
    g_Wpk[i] = pack_bf2(w0, w1);
}

// Combine weight pack (unchanged from R16)
__global__ void pack_wc_kernel(
    const float* __restrict__ Wl0, const float* __restrict__ Wr0,
    const float* __restrict__ Wl1, const float* __restrict__ Wr1)
{
    int i = blockIdx.x * 256 + threadIdx.x;    // 32768
    int L = i >> 14;
    int rest = i & 16383;
    int kt = rest >> 11;
    int sub = rest & 2047;
    int v = sub & 3, lane = (sub >> 2) & 31, jp = (sub >> 7) & 3;
    int ki = (sub >> 9) & 1, wn = (sub >> 10) & 1;
    int fn = 2 * jp + (v >> 1), r = v & 1;
    int n = wn * 64 + fn * 8 + (lane >> 2);
    int k = kt * 32 + ki * 16 + (lane & 3) * 2 + r * 8;
    const float* Wl = L ? Wl1 : Wl0;
    const float* Wr = L ? Wr1 : Wr0;
    float w0 = (k < 128) ? Wl[n * 128 + k]     : Wr[n * 128 + k - 128];
    float w1 = (k < 128) ? Wl[n * 128 + k + 1] : Wr[n * 128 + k + 1 - 128];
    g_Wcpk[i] = pack_bf2(w0, w1);
}

__device__ __forceinline__ void mma_bf16(float d[4], const unsigned a[4], const unsigned b[2]) {
    asm volatile(
        "mma.sync.aligned.m16n8k16.row.col.f32.bf16.bf16.f32 "
        "{%0,%1,%2,%3}, {%4,%5,%6,%7}, {%8,%9}, {%0,%1,%2,%3};"
        : "+f"(d[0]), "+f"(d[1]), "+f"(d[2]), "+f"(d[3])
        : "r"(a[0]), "r"(a[1]), "r"(a[2]), "r"(a[3]), "r"(b[0]), "r"(b[1]));
}

// =====================================================================
// PERSISTENT LSTM: one launch, t-loop in-kernel.
//  Grid 512 blocks (64 users each), 512 threads (16 warps = 2M x 8N).
//  Tile 64 x 512, K=192 in 6 chunks of 32. h lives in smem (A layout,
//  chunks 2-5); cell state in REGISTERS (16/thread, static map).
//  Weights streamed cyclically from gate-minor pack; x_{t+1} prefetched.
//  smem: XR 2x10240 | HR 20480 | B 2x32768 | bias 2048 = 108544 B, occ 1.
// =====================================================================
#define LSTM_SMEM 108544

__global__ __launch_bounds__(512, 1) void lstm_all_kernel(
    const float* __restrict__ b_ih, const float* __restrict__ b_hh)
{
    extern __shared__ char sm[];
    char* XR0 = sm;
    char* XR1 = sm + 10240;
    char* HR  = sm + 20480;
    char* B0  = sm + 40960;
    char* B1  = sm + 73728;
    float* bsm = (float*)(sm + 106496);   // [4][128] fused bias, gate-major

    int tid = threadIdx.x;
    int u0 = blockIdx.x * 64;

    bsm[tid] = b_ih[tid] + b_hh[tid];
    for (int i = tid; i < 5120; i += 512) ((unsigned*)HR)[i] = 0;   // h_0 = 0

    unsigned sX[2] = { (unsigned)__cvta_generic_to_shared(XR0),
                       (unsigned)__cvta_generic_to_shared(XR1) };
    unsigned sH    = (unsigned)__cvta_generic_to_shared(HR);
    unsigned sB[2] = { (unsigned)__cvta_generic_to_shared(B0),
                       (unsigned)__cvta_generic_to_shared(B1) };

    // B chunk kt -> buffer buf (32 KB = 2048 uint4; 4 per thread)
    auto issue_B = [&](int kt, int buf) {
        const uint4* srcp = (const uint4*)(g_Wpk + kt * 8192);
#pragma unroll
        for (int i = 0; i < 4; i++) {
            int idx = tid + i * 512;
            unsigned dst = sB[buf] + (unsigned)(idx * 16);
            asm volatile("cp.async.ca.shared.global [%0], [%1], 16;"
                         :: "r"(dst), "l"(srcp + idx) : "memory");
        }
    };
    // x_t -> region reg (8 KB payload into 2 chunk slots; 1 x 16B per thread)
    auto issue_X = [&](int t, int reg) {
        int u = tid >> 3, part = tid & 7;
        const __nv_bfloat16* srcp = g_xbf + ((size_t)(u0 + u) * TT + t) * EMBD + part * 8;
        unsigned dst = sX[reg] + (unsigned)((part >> 2) * 5120 + u * 80 + (part & 3) * 16);
        asm volatile("cp.async.ca.shared.global [%0], [%1], 16;"
                     :: "r"(dst), "l"(srcp) : "memory");
    };

    issue_X(0, 0);
    issue_B(0, 0);
    asm volatile("cp.async.commit_group;" ::: "memory");

    int wid = tid >> 5, lane = tid & 31;
    int wm = wid >> 3, wn = wid & 7;        // 2(M) x 8(N)
    int urow = wm * 32, ncol = wn * 64;
    int lr = lane >> 2, lc = lane & 3;
    unsigned arowoff = (unsigned)((urow + (lane & 15)) * 80 + (lane >> 4) * 16);
    int hbase = (ncol >> 2);                // warp's first hidden unit (16 per warp)
    int odd = lane & 1;

    float c_st[16];
#pragma unroll
    for (int i = 0; i < 16; i++) c_st[i] = 0.f;

    float acc[2][8][4];

#pragma unroll 1
    for (int t = 0; t < TT; t++) {
#pragma unroll
        for (int fm = 0; fm < 2; fm++)
#pragma unroll
            for (int fn = 0; fn < 8; fn++)
#pragma unroll
                for (int r = 0; r < 4; r++) acc[fm][fn][r] = 0.f;

#pragma unroll 1
        for (int kt = 0; kt < 6; kt++) {
            int cur = kt & 1;
            bool last = (t == TT - 1) && (kt == 5);
            if (!last) {
                issue_B((kt + 1) % 6, cur ^ 1);
                if (kt == 5) issue_X(t + 1, (t + 1) & 1);
                asm volatile("cp.async.commit_group;" ::: "memory");
                asm volatile("cp.async.wait_group 1;" ::: "memory");
            } else {
                asm volatile("cp.async.wait_group 0;" ::: "memory");
            }
            __syncthreads();

            unsigned abase = (kt < 2) ? (sX[t & 1] + (unsigned)(kt * 5120))
                                      : (sH + (unsigned)((kt - 2) * 5120));
            const uint4* Bp = (const uint4*)((cur == 0) ? B0 : B1);
#pragma unroll
            for (int ki = 0; ki < 2; ki++) {
                unsigned afr[2][4], bfr[8][2];
#pragma unroll
                for (int fm = 0; fm < 2; fm++) {
                    unsigned ad = abase + arowoff + (unsigned)(fm * 16 * 80 + ki * 32);
                    asm volatile("ldmatrix.sync.aligned.m8n8.x4.shared.b16 {%0,%1,%2,%3}, [%4];"
                                 : "=r"(afr[fm][0]), "=r"(afr[fm][1]),
                                   "=r"(afr[fm][2]), "=r"(afr[fm][3])
                                 : "r"(ad));
                }
#pragma unroll
                for (int jp = 0; jp < 4; jp++) {
                    uint4 v = Bp[(((wn * 2 + ki) * 4 + jp) * 32) + lane];
                    bfr[2 * jp][0]     = v.x;
                    bfr[2 * jp][1]     = v.y;
                    bfr[2 * jp + 1][0] = v.z;
                    bfr[2 * jp + 1][1] = v.w;
                }
#pragma unroll
                for (int fm = 0; fm < 2; fm++)
#pragma unroll
                    for (int fn = 0; fn < 8; fn++)
                        mma_bf16(acc[fm][fn], afr[fm], bfr[fn]);
            }
            __syncthreads();
        }

        // ---- epilogue: cell update fully in registers via shfl pairing ----
        // even lane holds (i,f) cols, odd holds (g,o); xor-1 partner shares hidden unit.
        bool fin = (t == TT - 1);
        __nv_bfloat16* HRb = (__nv_bfloat16*)HR;
#pragma unroll
        for (int fm = 0; fm < 2; fm++) {
#pragma unroll
            for (int fn = 0; fn < 8; fn++) {
                float s0 = odd ? acc[fm][fn][0] : acc[fm][fn][2];
                float r0 = __shfl_xor_sync(0xffffffffu, s0, 1);
                float s1 = odd ? acc[fm][fn][1] : acc[fm][fn][3];
                float r1 = __shfl_xor_sync(0xffffffffu, s1, 1);
                float gi, gf, gg, go;
                if (!odd) { gi = acc[fm][fn][0]; gf = acc[fm][fn][1]; gg = r0; go = r1; }
                else      { gi = r0; gf = r1; gg = acc[fm][fn][2]; go = acc[fm][fn][3]; }
                int hloc = hbase + fn * 2 + (lc >> 1);
                int row  = urow + fm * 16 + lr + (odd ? 8 : 0);
                gi += bsm[hloc];
                gf += bsm[128 + hloc];
                gg += bsm[256 + hloc];
                go += bsm[384 + hloc];
                int idx = fm * 8 + fn;
                float cc = sigmoidf_(gf) * c_st[idx] + sigmoidf_(gi) * tanhf(gg);
                c_st[idx] = cc;
                float h = sigmoidf_(go) * tanhf(cc);
                HRb[(hloc >> 5) * 2560 + row * 40 + ((hloc & 31) >> 3) * 8 + (hloc & 7)]
                    = __float2bfloat16(h);
                if (fin) {
                    size_t gidx = (size_t)(u0 + row) * HD + hloc;
                    g_u[gidx] = h;
                    g_hbf[gidx] = __float2bfloat16(h);
                }
            }
        }
        // no barrier needed here: next iteration's chunk-0 sync orders h writes
        // before any chunk-2 read (chunks 0/1 don't touch HR).
    }
}

// =====================================================================
// SAGE combine as bf16 GEMM (unchanged from R16)
// =====================================================================
#define GEMM_SMEM 36864

__global__ __launch_bounds__(256, 2) void combine_gemm_kernel(
    const float* __restrict__ bl, int mode)
{
    extern __shared__ char smraw[];
    __nv_bfloat16* Abf[2] = { (__nv_bfloat16*)smraw, (__nv_bfloat16*)(smraw + 10240) };
    unsigned* Bu[2] = { (unsigned*)(smraw + 20480), (unsigned*)(smraw + 28672) };
    __shared__ float bs[128];

    const __nv_bfloat16* aggsrc; const __nv_bfloat16* selfsrc;
    const unsigned* wp; float* outf; __nv_bfloat16* outbf;
    if      (mode == 0) { aggsrc = g_aggc_bf; selfsrc = g_cbf;  wp = g_Wcpk;         outf = g_c2; outbf = g_c2bf; }
    else if (mode == 1) { aggsrc = g_aggu_bf; selfsrc = g_hbf;  wp = g_Wcpk;         outf = g_u2; outbf = g_u2bf; }
    else if (mode == 2) { aggsrc = g_aggc_bf; selfsrc = g_c2bf; wp = g_Wcpk + 16384; outf = g_c;  outbf = 0; }
    else                { aggsrc = g_aggu_bf; selfsrc = g_u2bf; wp = g_Wcpk + 16384; outf = g_u;  outbf = 0; }

    int tid = threadIdx.x;
    int u0 = blockIdx.x * 128;

    if (tid < 128) bs[tid] = bl[tid];

    unsigned sA[2] = { (unsigned)__cvta_generic_to_shared(Abf[0]),
                       (unsigned)__cvta_generic_to_shared(Abf[1]) };
    unsigned sB[2] = { (unsigned)__cvta_generic_to_shared(Bu[0]),
                       (unsigned)__cvta_generic_to_shared(Bu[1]) };

    auto issue_tile = [&](int kt, int buf) {
#pragma unroll
        for (int i = 0; i < 2; i++) {
            int idx = tid + i * 256;
            int u = idx >> 2, k4 = idx & 3;
            const __nv_bfloat16* srcp = (kt < 4)
                ? aggsrc  + (size_t)(u0 + u) * HD + kt * 32 + k4 * 8
                : selfsrc + (size_t)(u0 + u) * HD + (kt - 4) * 32 + k4 * 8;
            unsigned dst = sA[buf] + (unsigned)(u * 80 + k4 * 16);
            asm volatile("cp.async.ca.shared.global [%0], [%1], 16;" :: "r"(dst), "l"(srcp) : "memory");
        }
        {
            const unsigned* basep = wp + (size_t)kt * 2048;
#pragma unroll
            for (int i = 0; i < 2; i++) {
                int idx = tid + i * 256;
                const unsigned* srcp = basep + idx * 4;
                unsigned dst = sB[buf] + (unsigned)(idx * 16);
                asm volatile("cp.async.ca.shared.global [%0], [%1], 16;" :: "r"(dst), "l"(srcp) : "memory");
            }
        }
        asm volatile("cp.async.commit_group;" ::: "memory");
    };

    issue_tile(0, 0);

    int wid = tid >> 5, lane = tid & 31;
    int wm = wid >> 1, wn = wid & 1;
    int urow = wm * 32, ncol = wn * 64;
    int lr = lane >> 2, lc = lane & 3;

    unsigned aoff = (unsigned)((urow + (lane & 15)) * 80 + (lane >> 4) * 16);

    float acc[2][8][4];
#pragma unroll
    for (int fm = 0; fm < 2; fm++)
#pragma unroll
        for (int fn = 0; fn < 8; fn++)
#pragma unroll
            for (int r = 0; r < 4; r++) acc[fm][fn][r] = 0.f;

#pragma unroll 1
    for (int kt = 0; kt < 8; kt++) {
        int cur = kt & 1;
        if (kt < 7) {
            issue_tile(kt + 1, cur ^ 1);
            asm volatile("cp.async.wait_group 1;" ::: "memory");
        } else {
            asm volatile("cp.async.wait_group 0;" ::: "memory");
        }
        __syncthreads();

        const uint4* Bp = (const uint4*)Bu[cur];
#pragma unroll
        for (int ki = 0; ki < 2; ki++) {
            unsigned afr[2][4], bfr[8][2];
#pragma unroll
            for (int fm = 0; fm < 2; fm++) {
                unsigned ad = sA[cur] + aoff + (unsigned)(fm * 16 * 80 + ki * 32);
                asm volatile("ldmatrix.sync.aligned.m8n8.x4.shared.b16 {%0,%1,%2,%3}, [%4];"
                             : "=r"(afr[fm][0]), "=r"(afr[fm][1]),
                               "=r"(afr[fm][2]), "=r"(afr[fm][3])
                             : "r"(ad));
            }
#pragma unroll
            for (int jp = 0; jp < 4; jp++) {
                uint4 v = Bp[(((wn * 2 + ki) * 4 + jp) * 32) + lane];
                bfr[2 * jp][0]     = v.x;
                bfr[2 * jp][1]     = v.y;
                bfr[2 * jp + 1][0] = v.z;
                bfr[2 * jp + 1][1] = v.w;
            }
#pragma unroll
            for (int fm = 0; fm < 2; fm++)
#pragma unroll
                for (int fn = 0; fn < 8; fn++)
                    mma_bf16(acc[fm][fn], afr[fm], bfr[fn]);
        }
        __syncthreads();
    }

#pragma unroll
    for (int fm = 0; fm < 2; fm++) {
#pragma unroll
        for (int fn = 0; fn < 8; fn++) {
            int row = u0 + urow + fm * 16 + lr;
            int col = ncol + fn * 8 + lc * 2;
            float b0 = bs[col], b1 = bs[col + 1];
            float v0 = fmaxf(acc[fm][fn][0] + b0, 0.f);
            float v1 = fmaxf(acc[fm][fn][1] + b1, 0.f);
            float v2 = fmaxf(acc[fm][fn][2] + b0, 0.f);
            float v3 = fmaxf(acc[fm][fn][3] + b1, 0.f);
            *(float2*)&outf[(size_t)row * HD + col]       = make_float2(v0, v1);
            *(float2*)&outf[(size_t)(row + 8) * HD + col] = make_float2(v2, v3);
            if (outbf) {
                ((unsigned*)outbf)[((size_t)row * HD + col) >> 1]       = pack_bf2(v0, v1);
                ((unsigned*)outbf)[((size_t)(row + 8) * HD + col) >> 1] = pack_bf2(v2, v3);
            }
        }
    }
}

// ---------------- content linear: c = x_content @ Wc^T + bc (+ bf16 mirror) ----------------
__global__ __launch_bounds__(256) void content_kernel(
    const float* __restrict__ xc, const float* __restrict__ Wc, const float* __restrict__ bc)
{
    __shared__ float4 Wc4s[128 * 17];
    __shared__ float4 xs[32 * 17];
    int tid = threadIdx.x;
    int n0 = blockIdx.x * 32;

    for (int idx = tid; idx < 128 * 16; idx += 256) {
        int r = idx >> 4, col = idx & 15;
        Wc4s[r * 17 + col] = ((const float4*)Wc)[idx];
    }
    for (int idx = tid; idx < 32 * 16; idx += 256) {
        int n = idx >> 4, k4 = idx & 15;
        xs[n * 17 + k4] = ((const float4*)xc)[(n0 + n) * 16 + k4];
    }
    __syncthreads();

    int n = tid >> 3, q = tid & 7;
    float acc[16];
#pragma unroll
    for (int i = 0; i < 16; i++) acc[i] = bc[q + 8 * i];
#pragma unroll 1
    for (int k4 = 0; k4 < 16; k4++) {
        float4 xv = xs[n * 17 + k4];
#pragma unroll
        for (int i = 0; i < 16; i++) {
            float4 wv = Wc4s[(q + 8 * i) * 17 + k4];
            DOT4(acc[i], wv, xv);
        }
    }
#pragma unroll
    for (int i = 0; i < 16; i++) {
        int m = q + 8 * i;
        g_c[(n0 + n) * HD + m] = acc[i];
        g_cbf[(n0 + n) * HD + m] = __float2bfloat16(acc[i]);
    }
}

// ---------------- classifier ----------------
#define CLS_SMEM ((128 * 65 + 32 * 65) * 16 + 512)
__global__ __launch_bounds__(256) void classifier_kernel(
    const float* __restrict__ W1, const float* __restrict__ b1,
    const float* __restrict__ W2, const float* __restrict__ b2,
    float* __restrict__ out)
{
    extern __shared__ float smk[];
    float4* W14 = (float4*)smk;
    float4* xc4 = W14 + 128 * 65;
    float*  W2s = (float*)(xc4 + 32 * 65);

    int tid = threadIdx.x;
    int n0 = blockIdx.x * 32;

    for (int idx = tid; idx < 128 * 64; idx += 256) {
        int r = idx >> 6, col = idx & 63;
        W14[r * 65 + col] = ((const float4*)W1)[idx];
    }
    for (int idx = tid; idx < 32 * 64; idx += 256) {
        int n = idx >> 6, k4 = idx & 63;
        float4 v = (k4 < 32) ? ((const float4*)g_u)[(n0 + n) * 32 + k4]
                             : ((const float4*)g_c)[(n0 + n) * 32 + (k4 - 32)];
        xc4[n * 65 + k4] = v;
    }
    if (tid < 128) W2s[tid] = W2[tid];
    __syncthreads();

    int n = tid >> 3, q = tid & 7;
    float acc[16];
#pragma unroll
    for (int i = 0; i < 16; i++) acc[i] = b1[q + 8 * i];
#pragma unroll 1
    for (int k4 = 0; k4 < 64; k4++) {
        float4 xv = xc4[n * 65 + k4];
#pragma unroll
        for (int i = 0; i < 16; i++) {
            float4 wv = W14[(q + 8 * i) * 65 + k4];
            DOT4(acc[i], wv, xv);
        }
    }
    float p = 0.f;
#pragma unroll
    for (int i = 0; i < 16; i++) {
        float h = fmaxf(acc[i], 0.f);
        p += h * W2s[q + 8 * i];
    }
    p += __shfl_xor_sync(0xffffffffu, p, 1);
    p += __shfl_xor_sync(0xffffffffu, p, 2);
    p += __shfl_xor_sync(0xffffffffu, p, 4);
    if (q == 0) out[n0 + n] = sigmoidf_(p + b2[0]);
}

// ---------------- launch ----------------
extern "C" void kernel_launch(void* const* d_in, const int* in_sizes, int n_in,
                              void* d_out, int out_size)
{
    const float* x_user    = (const float*)d_in[0];
    const float* x_content = (const float*)d_in[1];
    const int*   edge      = (const int*)  d_in[2];
    const float* W_ih      = (const float*)d_in[3];
    const float* W_hh      = (const float*)d_in[4];
    const float* b_ih      = (const float*)d_in[5];
    const float* b_hh      = (const float*)d_in[6];
    const float* Wc        = (const float*)d_in[7];
    const float* bc        = (const float*)d_in[8];
    const float* Wl0       = (const float*)d_in[9];
    const float* bl0       = (const float*)d_in[10];
    const float* Wr0       = (const float*)d_in[11];
    const float* Wl1       = (const float*)d_in[12];
    const float* bl1       = (const float*)d_in[13];
    const float* Wr1       = (const float*)d_in[14];
    const float* W1        = (const float*)d_in[15];
    const float* b1        = (const float*)d_in[16];
    const float* W2        = (const float*)d_in[17];
    const float* b2        = (const float*)d_in[18];
    float* out = (float*)d_out;

    const int* src = edge;
    const int* dst = edge + NE;

    cudaFuncSetAttribute(lstm_all_kernel,     cudaFuncAttributeMaxDynamicSharedMemorySize, LSTM_SMEM);
    cudaFuncSetAttribute(combine_gemm_kernel, cudaFuncAttributeMaxDynamicSharedMemorySize, GEMM_SMEM);
    cudaFuncSetAttribute(classifier_kernel,   cudaFuncAttributeMaxDynamicSharedMemorySize, CLS_SMEM);

    // prep (ordered so lstm_all is the 6th launch -> ncu -s 5 captures it)
    pack_w_kernel<<<49152 / 256, 256>>>(W_ih, W_hh);
    pack_wc_kernel<<<32768 / 256, 256>>>(Wl0, Wr0, Wl1, Wr1);
    conv_x_kernel<<<NN * TT * EMBD / 8 / 256, 256>>>(x_user);
    zero_deg_kernel<<<NN / 256, 256>>>();
    count_kernel<<<NE / 256, 256>>>(src, dst);

    // ---- persistent LSTM (one launch) ----
    lstm_all_kernel<<<NN / 64, 512, LSTM_SMEM>>>(b_ih, b_hh);

    // ---- rest of CSR build ----
    scan_kernel<<<2, 1024>>>();
    fill_kernel<<<NE / 256, 256>>>(src, dst);

    // ---- content features ----
    content_kernel<<<NN / 32, 256>>>(x_content, Wc, bc);

    // ---- SAGE layer 0 ----
    agg_kernel<<<NN / 8, 256>>>(0);
    agg_kernel<<<NN / 8, 256>>>(1);
    combine_gemm_kernel<<<NN / 128, 256, GEMM_SMEM>>>(bl0, 0);
    combine_gemm_kernel<<<NN / 128, 256, GEMM_SMEM>>>(bl0, 1);

    // ---- SAGE layer 1 ----
    agg_kernel<<<NN / 8, 256>>>(2);
    agg_kernel<<<NN / 8, 256>>>(3);
    combine_gemm_kernel<<<NN / 128, 256, GEMM_SMEM>>>(bl1, 2);
    combine_gemm_kernel<<<NN / 128, 256, GEMM_SMEM>>>(bl1, 3);

    // ---- classifier ----
    classifier_kernel<<<NN / 32, 256, CLS_SMEM>>>(W1, b1, W2, b2, out);
}